// round 7
// baseline (speedup 1.0000x reference)
#include <cuda_runtime.h>
#include <cuda_bf16.h>
#include <math.h>
#include <stdint.h>

#define B_   128
#define T_   64
#define D_   300
#define KPX  320
#define H_   512
#define G4_  2048

#define TM 64
#define TN 128
#define KC 32
#define PAD 40
// 3-stage smem: per stage Ahi(5120) Alo(5120) Bhi(10240) Blo(10240) = 30720 B
#define STA_HI(s) ((uint32_t)(s) * 30720u)
#define STA_LO(s) (STA_HI(s) + 5120u)
#define STB_HI(s) (STA_HI(s) + 10240u)
#define STB_LO(s) (STA_HI(s) + 20480u)
static constexpr int SMEM_MM = 3 * 30720;   // 92160

__device__ __forceinline__ uint32_t smem_u32(const void* p) {
    uint32_t a;
    asm("{ .reg .u64 t; cvta.to.shared.u64 t, %1; cvt.u32.u64 %0, t; }" : "=r"(a) : "l"(p));
    return a;
}
#define CP_ASYNC16(dst, src) \
    asm volatile("cp.async.cg.shared.global [%0], [%1], 16;" :: "r"(dst), "l"(src))
#define CP_COMMIT() asm volatile("cp.async.commit_group;" ::: "memory")
#define CP_WAIT0()  asm volatile("cp.async.wait_group 0;" ::: "memory")
#define CP_WAIT1()  asm volatile("cp.async.wait_group 1;" ::: "memory")
#define LDSM4(r0, r1, r2, r3, addr) \
    asm volatile("ldmatrix.sync.aligned.m8n8.x4.shared.b16 {%0,%1,%2,%3}, [%4];" \
                 : "=r"(r0), "=r"(r1), "=r"(r2), "=r"(r3) : "r"(addr))
#define MMA16816(c, a, b0, b1) \
    asm volatile("mma.sync.aligned.m16n8k16.row.col.f32.bf16.bf16.f32 " \
                 "{%0,%1,%2,%3}, {%4,%5,%6,%7}, {%8,%9}, {%0,%1,%2,%3};" \
                 : "+f"((c)[0]), "+f"((c)[1]), "+f"((c)[2]), "+f"((c)[3]) \
                 : "r"((a)[0]), "r"((a)[1]), "r"((a)[2]), "r"((a)[3]), \
                   "r"(b0), "r"(b1))

__device__ __forceinline__ float sigf(float x) { return __fdividef(1.f, 1.f + __expf(-x)); }
__device__ __forceinline__ float ftanh(float x) { return 1.f - __fdividef(2.f, __expf(2.f * x) + 1.f); }
__device__ __forceinline__ float tanha(float x) {
    float y; asm("tanh.approx.f32 %0, %1;" : "=f"(y) : "f"(x)); return y;
}

// ---------------- plane sizes (bf16 element counts) ----------------
static constexpr size_t P_E  = (size_t)B_ * T_ * KPX;     // one e term-plane
static constexpr size_t P_Y  = 4ull * B_ * T_ * H_;       // one Y term-plane
static constexpr size_t P_HB = 4ull * B_ * H_;            // one h term-plane
static constexpr size_t P_RB = 256ull * H_;               // one r term-plane

// ---------------- scratch layout (float units) ----------------
static constexpr size_t OFF_EB   = 0;                                    // bf16 [2 which][2 term][8192][320]
static constexpr size_t OFF_XG   = OFF_EB + (2ull * 2 * P_E) / 2;
static constexpr size_t OFF_Y    = OFF_XG + 4ull * B_ * T_ * G4_;        // fp32 Y
static constexpr size_t OFF_YB   = OFF_Y + 4ull * B_ * T_ * H_;          // bf16 [2 term][4][8192][512]
static constexpr size_t OFF_H    = OFF_YB + (2ull * P_Y) / 2;            // fp32 h ping-pong [2][4][128][512]
static constexpr size_t OFF_HB   = OFF_H + 2ull * 4 * B_ * H_;           // bf16 [2 pp][2 term][4][128][512]
static constexpr size_t OFF_C    = OFF_HB + (2ull * 2 * P_HB) / 2;       // fp32 c
static constexpr size_t OFF_WYY  = OFF_C + 4ull * B_ * H_;
static constexpr size_t OFF_HWY  = OFF_WYY + 2ull * B_ * T_ * H_;
static constexpr size_t OFF_UPT  = OFF_HWY + 2ull * B_ * T_ * H_;        // [4 ks][256][1024] fp32
static constexpr size_t OFF_RB   = OFF_UPT + 4ull * 256 * 1024;          // bf16 [2 term][256][512]
static constexpr size_t OFF_RL   = OFF_RB + (2ull * P_RB) / 2;
static constexpr size_t OFF_BP   = OFF_RL + 256ull * H_;
static constexpr size_t OFF_WXS  = OFF_BP + 2ull * G4_;
static constexpr size_t OFF_WHS  = OFF_WXS + (2ull * 2 * G4_ * KPX) / 2;
static constexpr size_t OFF_WYS  = OFF_WHS + (2ull * 2 * G4_ * H_) / 2;
static constexpr size_t OFF_WHA  = OFF_WYS + (2ull * H_ * H_) / 2;
static constexpr size_t OFF_WCS  = OFF_WHA + (2ull * H_ * H_) / 2;
static constexpr size_t OFF_SYNC = OFF_WCS + (2ull * 2 * H_ * H_) / 2;
static constexpr size_t TOTAL_F  = OFF_SYNC + 16;

__device__ __align__(256) float d_buf[TOTAL_F];

__device__ __forceinline__ void split_store(float v, __nv_bfloat16* hi, __nv_bfloat16* lo) {
    __nv_bfloat16 h = __float2bfloat16_rn(v);
    *hi = h;
    *lo = __float2bfloat16_rn(v - __bfloat162float(h));
}

// ---------------- grid barrier ----------------
__device__ __forceinline__ void gbar(unsigned* cnt, unsigned* rel,
                                     unsigned seq, unsigned ncta) {
    __syncthreads();
    if (threadIdx.x == 0) {
        unsigned old;
        asm volatile("fence.acq_rel.gpu;" ::: "memory");
        asm volatile("atom.relaxed.gpu.global.add.u32 %0, [%1], 1;"
                     : "=r"(old) : "l"(cnt) : "memory");
        if (old + 1u == ncta * seq) {
            asm volatile("st.release.gpu.global.u32 [%0], %1;"
                         :: "l"(rel), "r"(seq) : "memory");
        }
        unsigned v;
        do {
            asm volatile("ld.acquire.gpu.global.u32 %0, [%1];"
                         : "=r"(v) : "l"(rel) : "memory");
        } while (v < seq);
    }
    __syncthreads();
}

// ---------------- prep: weight splits + all zero-init ----------------
__global__ void k_prep(const float* __restrict__ W1, const float* __restrict__ W2,
                       const float* __restrict__ Wy, const float* __restrict__ Wh,
                       const float* __restrict__ Wr, const float* __restrict__ Wt,
                       const float* __restrict__ b1, const float* __restrict__ b2) {
    float* buf = d_buf;
    __nv_bfloat16* WxS = (__nv_bfloat16*)(buf + OFF_WXS);
    __nv_bfloat16* WhS = (__nv_bfloat16*)(buf + OFF_WHS);
    __nv_bfloat16* WyS = (__nv_bfloat16*)(buf + OFF_WYS);
    __nv_bfloat16* WhA = (__nv_bfloat16*)(buf + OFF_WHA);
    __nv_bfloat16* WcS = (__nv_bfloat16*)(buf + OFF_WCS);
    float* bP = buf + OFF_BP;

    const size_t R1 = 2ull * G4_ * KPX;
    const size_t R2 = 2ull * G4_ * H_;
    const size_t R3 = (size_t)H_ * H_;
    const size_t R4 = (size_t)H_ * H_;
    const size_t R5 = 2ull * H_ * H_;
    const size_t R6 = 2ull * G4_;
    const size_t R7 = OFF_WYY - OFF_H;          // h fp32 + h bf16 + c (contiguous)
    const size_t R8 = (2ull * P_RB) / 2;        // RB
    const size_t R9 = 16;                       // sync
    const size_t TOT = R1 + R2 + R3 + R4 + R5 + R6 + R7 + R8 + R9;
    size_t stride = (size_t)gridDim.x * blockDim.x;
    for (size_t id = (size_t)blockIdx.x * blockDim.x + threadIdx.x; id < TOT; id += stride) {
        size_t i = id;
        if (i < R1) {
            int w = (int)(i / ((size_t)G4_ * KPX));
            size_t rem = i % ((size_t)G4_ * KPX);
            int np = (int)(rem / KPX), k = (int)(rem % KPX);
            int col = (np & 3) * H_ + (np >> 2);
            const float* W = w ? W2 : W1;
            float v = (k < D_) ? W[(size_t)k * G4_ + col] : 0.f;
            size_t o = ((size_t)(w * 2) * G4_ + np) * KPX + k;
            split_store(v, WxS + o, WxS + o + (size_t)G4_ * KPX);
            continue;
        }
        i -= R1;
        if (i < R2) {
            int w = (int)(i / ((size_t)G4_ * H_));
            size_t rem = i % ((size_t)G4_ * H_);
            int np = (int)(rem / H_), k = (int)(rem % H_);
            int col = (np & 3) * H_ + (np >> 2);
            const float* W = w ? W2 : W1;
            float v = W[(size_t)(D_ + k) * G4_ + col];
            size_t o = ((size_t)(w * 2) * G4_ + np) * H_ + k;
            split_store(v, WhS + o, WhS + o + (size_t)G4_ * H_);
            continue;
        }
        i -= R2;
        if (i < R3) {
            int n = (int)(i / H_), k = (int)(i % H_);
            size_t o = (size_t)n * H_ + k;
            split_store(Wy[(size_t)k * H_ + n], WyS + o, WyS + o + (size_t)H_ * H_);
            continue;
        }
        i -= R3;
        if (i < R4) {
            int n = (int)(i / H_), k = (int)(i % H_);
            size_t o = (size_t)n * H_ + k;
            split_store(Wh[(size_t)k * H_ + n], WhA + o, WhA + o + (size_t)H_ * H_);
            continue;
        }
        i -= R4;
        if (i < R5) {
            int n = (int)(i / H_), k = (int)(i % H_);
            float v = (n < H_) ? Wr[(size_t)k * H_ + n] : Wt[(size_t)k * H_ + (n - H_)];
            size_t o = (size_t)n * H_ + k;
            split_store(v, WcS + o, WcS + o + 2ull * H_ * H_);
            continue;
        }
        i -= R5;
        if (i < R6) {
            int w = (int)(i / G4_), np = (int)(i % G4_);
            int col = (np & 3) * H_ + (np >> 2);
            bP[i] = (w ? b2 : b1)[col];
            continue;
        }
        i -= R6;
        if (i < R7) { (buf + OFF_H)[i] = 0.f; continue; }
        i -= R7;
        if (i < R8) { (buf + OFF_RB)[i] = 0.f; continue; }
        i -= R8;
        (buf + OFF_SYNC)[i] = 0.f;
    }
}

// ---------------- embedding gather -> bf16 hi/lo ----------------
__global__ void k_gather(const int* __restrict__ t1, const int* __restrict__ t2,
                         const float* __restrict__ emb) {
    __nv_bfloat16* eb = (__nv_bfloat16*)(d_buf + OFF_EB);
    size_t total = 2ull * B_ * T_ * KPX;
    size_t stride = (size_t)gridDim.x * blockDim.x;
    for (size_t i = (size_t)blockIdx.x * blockDim.x + threadIdx.x; i < total; i += stride) {
        int which = (int)(i / P_E);
        size_t rem = i % P_E;
        int bt = (int)(rem / KPX), k = (int)(rem % KPX);
        int tok = (which ? t2 : t1)[bt];
        float v = (k < D_) ? emb[(size_t)tok * D_ + k] : 0.f;
        __nv_bfloat16* p = eb + (size_t)which * 2 * P_E + rem;
        split_store(v, p, p + P_E);
    }
}

// ---------------------------------------------------------------------------
// Core K-loop: acc += A(bf16 hi/lo) x B(bf16 hi/lo), 64x128 tile, 128 threads,
// 3-stage cp.async pipeline, 3-term split MMA.
// ---------------------------------------------------------------------------
__device__ __forceinline__ void gemm_k3(
    const __nv_bfloat16* __restrict__ Ahg, const __nv_bfloat16* __restrict__ Alg,
    const __nv_bfloat16* __restrict__ Bhg, const __nv_bfloat16* __restrict__ Blg,
    int nch, uint32_t sb,
    uint32_t aSt, uint32_t bSt, uint32_t aLd, uint32_t bLd,
    int wid, float acc[4][4][4]) {
    auto issue = [&](int ch, int slot) {
        const __nv_bfloat16* bh = Bhg + ch * KC;
        const __nv_bfloat16* bl = Blg + ch * KC;
#pragma unroll
        for (int q = 0; q < 4; q++) {
            CP_ASYNC16(sb + STB_HI(slot) + bSt + q * 16, bh + q * 8);
            CP_ASYNC16(sb + STB_LO(slot) + bSt + q * 16, bl + q * 8);
        }
        const __nv_bfloat16* ah = Ahg + ch * KC;
        const __nv_bfloat16* al = Alg + ch * KC;
        CP_ASYNC16(sb + STA_HI(slot) + aSt,      ah);
        CP_ASYNC16(sb + STA_HI(slot) + aSt + 16, ah + 8);
        CP_ASYNC16(sb + STA_LO(slot) + aSt,      al);
        CP_ASYNC16(sb + STA_LO(slot) + aSt + 16, al + 8);
        CP_COMMIT();
    };
    issue(0, 0);
    if (nch > 1) issue(1, 1);
    for (int ch = 0; ch < nch; ch++) {
        if (ch + 1 < nch) { CP_WAIT1(); } else { CP_WAIT0(); }
        __syncthreads();
        if (ch + 2 < nch) issue(ch + 2, (ch + 2) % 3);
        int s = ch % 3;
#pragma unroll
        for (int h16 = 0; h16 < 2; h16++) {
            uint32_t kb = (uint32_t)h16 * 32;
            uint32_t bh[8], bl[8];
#pragma unroll
            for (int g = 0; g < 2; g++) {
                uint32_t rowb = (uint32_t)((wid * 32 + g * 16) * PAD) * 2;
                LDSM4(bh[g * 4 + 0], bh[g * 4 + 1], bh[g * 4 + 2], bh[g * 4 + 3],
                      sb + STB_HI(s) + bLd + rowb + kb);
                LDSM4(bl[g * 4 + 0], bl[g * 4 + 1], bl[g * 4 + 2], bl[g * 4 + 3],
                      sb + STB_LO(s) + bLd + rowb + kb);
            }
#pragma unroll
            for (int mt = 0; mt < 4; mt++) {
                uint32_t ah4[4], al4[4];
                uint32_t rowa = (uint32_t)(mt * 16 * PAD) * 2;
                LDSM4(ah4[0], ah4[1], ah4[2], ah4[3], sb + STA_HI(s) + aLd + rowa + kb);
                LDSM4(al4[0], al4[1], al4[2], al4[3], sb + STA_LO(s) + aLd + rowa + kb);
#pragma unroll
                for (int nt = 0; nt < 4; nt++) {
                    int bi = (nt >> 1) * 4 + (nt & 1) * 2;
                    MMA16816(acc[mt][nt], ah4, bh[bi], bh[bi + 1]);
                    MMA16816(acc[mt][nt], ah4, bl[bi], bl[bi + 1]);
                    MMA16816(acc[mt][nt], al4, bh[bi], bh[bi + 1]);
                }
            }
        }
    }
}

// ---------------- bulk GEMM ----------------
struct MZ {
    const __nv_bfloat16 *Ahi, *Alo, *Bhi, *Blo;
    float* C;
    const float* bias;
};
struct MP {
    MZ z[4];
    int Klen, lda, ldb, ldc;
};

__global__ void __launch_bounds__(128) mm_gemm(MP p) {
    extern __shared__ __align__(16) char smem_raw[];
    uint32_t sb = smem_u32(smem_raw);
    const MZ z = p.z[blockIdx.z];
    int tid = threadIdx.x, lane = tid & 31, wid = tid >> 5;
    int n0 = blockIdx.x * TN, m0 = blockIdx.y * TM;

    const __nv_bfloat16* Ahg = z.Ahi + (size_t)(m0 + (tid >> 1)) * p.lda + (tid & 1) * 16;
    const __nv_bfloat16* Alg = z.Alo + (size_t)(m0 + (tid >> 1)) * p.lda + (tid & 1) * 16;
    const __nv_bfloat16* Bhg = z.Bhi + (size_t)(n0 + tid) * p.ldb;
    const __nv_bfloat16* Blg = z.Blo + (size_t)(n0 + tid) * p.ldb;
    uint32_t aSt = (uint32_t)((tid >> 1) * PAD + (tid & 1) * 16) * 2;
    uint32_t bSt = (uint32_t)(tid * PAD) * 2;
    uint32_t aLd = (uint32_t)((lane & 15) * PAD + ((lane >> 4) << 3)) * 2;
    uint32_t bLd = (uint32_t)(((lane & 7) + ((lane & 16) >> 1)) * PAD + (lane & 8)) * 2;

    float acc[4][4][4] = {};
    gemm_k3(Ahg, Alg, Bhg, Blg, p.Klen / KC, sb, aSt, bSt, aLd, bLd, wid, acc);

#pragma unroll
    for (int mt = 0; mt < 4; mt++) {
        int r = m0 + mt * 16 + (lane >> 2);
#pragma unroll
        for (int nt = 0; nt < 4; nt++) {
            int c = n0 + wid * 32 + nt * 8 + (lane & 3) * 2;
            float b0 = 0.f, b1 = 0.f;
            if (z.bias) { b0 = z.bias[c]; b1 = z.bias[c + 1]; }
            *(float2*)(z.C + (size_t)r * p.ldc + c) =
                make_float2(acc[mt][nt][0] + b0, acc[mt][nt][1] + b1);
            *(float2*)(z.C + (size_t)(r + 8) * p.ldc + c) =
                make_float2(acc[mt][nt][2] + b0, acc[mt][nt][3] + b1);
        }
    }
}

// ---------------- persistent LSTM scan ----------------
__global__ void __launch_bounds__(128) k_lstm_persist(
    const int* __restrict__ s1, const int* __restrict__ s2) {
    extern __shared__ __align__(16) char smem_raw[];
    uint32_t sb = smem_u32(smem_raw);
    float* buf = d_buf;
    int tid = threadIdx.x, lane = tid & 31, wid = tid >> 5;
    int blk = blockIdx.x;
    int r  = blk >> 5;
    int mt_ = (blk >> 4) & 1;
    int nt_ = blk & 15;
    int n0 = nt_ * TN, m0 = mt_ * TM;
    int widx = (r == 0 || r == 2) ? 0 : 1;
    const int* sl = (r == 0 || r == 3) ? s1 : s2;

    const __nv_bfloat16* WhS = (const __nv_bfloat16*)(buf + OFF_WHS);
    const __nv_bfloat16* Bhg = WhS + (size_t)(widx * 2 + 0) * G4_ * H_ + (size_t)(n0 + tid) * H_;
    const __nv_bfloat16* Blg = WhS + (size_t)(widx * 2 + 1) * G4_ * H_ + (size_t)(n0 + tid) * H_;

    const float* Xg  = buf + OFF_XG + (size_t)r * B_ * T_ * G4_;
    float*       cst = buf + OFF_C + (size_t)r * B_ * H_;
    float*       Yst = buf + OFF_Y + (size_t)r * B_ * T_ * H_;
    __nv_bfloat16* YBb = (__nv_bfloat16*)(buf + OFF_YB) + (size_t)r * B_ * T_ * H_;
    float*       hB  = buf + OFF_H;
    __nv_bfloat16* HBb = (__nv_bfloat16*)(buf + OFF_HB);
    const size_t HBUF = 4ull * B_ * H_;

    unsigned* sync = (unsigned*)(buf + OFF_SYNC);

    uint32_t aSt = (uint32_t)((tid >> 1) * PAD + (tid & 1) * 16) * 2;
    uint32_t bSt = (uint32_t)(tid * PAD) * 2;
    uint32_t aLd = (uint32_t)((lane & 15) * PAD + ((lane >> 4) << 3)) * 2;
    uint32_t bLd = (uint32_t)(((lane & 7) + ((lane & 16) >> 1)) * PAD + (lane & 8)) * 2;

    for (int t = 0; t < T_; t++) {
        int ppi = t & 1, ppo = ppi ^ 1;
        const float* hin  = hB + (size_t)ppi * HBUF + (size_t)r * B_ * H_;
        float*       hout = hB + (size_t)ppo * HBUF + (size_t)r * B_ * H_;
        const __nv_bfloat16* Ah = HBb + (size_t)ppi * 2 * P_HB + (size_t)r * B_ * H_
                                  + (size_t)(m0 + (tid >> 1)) * H_ + (tid & 1) * 16;
        __nv_bfloat16* ho_hi = HBb + (size_t)ppo * 2 * P_HB + (size_t)r * B_ * H_;

        float acc[4][4][4] = {};
        gemm_k3(Ah, Ah + P_HB, Bhg, Blg, H_ / KC, sb, aSt, bSt, aLd, bLd, wid, acc);

#pragma unroll
        for (int mt = 0; mt < 4; mt++) {
            int b = m0 + mt * 16 + (lane >> 2);
#pragma unroll
            for (int nt = 0; nt < 4; nt++) {
                float fo0 = __shfl_xor_sync(0xffffffffu, acc[mt][nt][0], 1);
                float fo1 = __shfl_xor_sync(0xffffffffu, acc[mt][nt][1], 1);
                float fo2 = __shfl_xor_sync(0xffffffffu, acc[mt][nt][2], 1);
                float fo3 = __shfl_xor_sync(0xffffffffu, acc[mt][nt][3], 1);
                if (!(lane & 1)) {
#pragma unroll
                    for (int half = 0; half < 2; half++) {
                        int bb = b + half * 8;
                        float gi = half ? acc[mt][nt][2] : acc[mt][nt][0];
                        float gj = half ? acc[mt][nt][3] : acc[mt][nt][1];
                        float gf = half ? fo2 : fo0;
                        float go = half ? fo3 : fo1;
                        int c0 = n0 + wid * 32 + nt * 8 + (lane & 3) * 2;
                        int j = c0 >> 2;
                        float4 x = *(const float4*)(Xg + ((size_t)bb * T_ + t) * G4_ + c0);
                        gi += x.x; gj += x.y; gf += x.z; go += x.w;
                        size_t ci = (size_t)bb * H_ + j;
                        size_t yi = ((size_t)bb * T_ + t) * H_ + j;
                        float hv, yv;
                        if (t < sl[bb]) {
                            float cc = cst[ci];
                            float cn = cc * sigf(gf + 1.f) + sigf(gi) * ftanh(gj);
                            hv = ftanh(cn) * sigf(go);
                            cst[ci] = cn;
                            yv = hv;
                        } else {
                            hv = __ldcg(hin + ci);
                            yv = 0.f;
                        }
                        hout[ci] = hv;
                        split_store(hv, ho_hi + ci, ho_hi + P_HB + ci);
                        Yst[yi] = yv;
                        split_store(yv, YBb + yi, YBb + P_Y + yi);
                    }
                }
            }
        }
        gbar(sync + 0, sync + 1, (unsigned)(t + 1), 128u);
    }
}

// ---------------- persistent attention scan ----------------
__global__ void __launch_bounds__(128) k_att_persist(
    const float* __restrict__ wv,
    const int* __restrict__ s1, const int* __restrict__ s2) {
    extern __shared__ __align__(16) char smem_raw[];
    uint32_t sb = smem_u32(smem_raw);
    float* smf = (float*)smem_raw;
    float* buf = d_buf;
    int tid = threadIdx.x, lane = tid & 31, wid = tid >> 5;
    int blk = blockIdx.x;

    int ks  = blk & 3;
    int mt_ = (blk >> 2) & 3;
    int nt_ = blk >> 4;
    int m0 = mt_ * TM, n0 = nt_ * TN, kst = ks * 128;

    const __nv_bfloat16* WcS = (const __nv_bfloat16*)(buf + OFF_WCS);
    const __nv_bfloat16* Bhg = WcS + (size_t)(n0 + tid) * H_ + kst;
    const __nv_bfloat16* Blg = WcS + 2ull * H_ * H_ + (size_t)(n0 + tid) * H_ + kst;

    __nv_bfloat16* RBb = (__nv_bfloat16*)(buf + OFF_RB);
    float* uPt4 = buf + OFF_UPT;
    float* rL   = buf + OFF_RL;
    const float* WyY = buf + OFF_WYY;
    const float* HWy = buf + OFF_HWY;
    const float* Yb  = buf + OFF_Y;
    unsigned* sync = (unsigned*)(buf + OFF_SYNC);

    uint32_t aSt = (uint32_t)((tid >> 1) * PAD + (tid & 1) * 16) * 2;
    uint32_t bSt = (uint32_t)(tid * PAD) * 2;
    uint32_t aLd = (uint32_t)((lane & 15) * PAD + ((lane >> 4) << 3)) * 2;
    uint32_t bLd = (uint32_t)(((lane & 7) + ((lane & 16) >> 1)) * PAD + (lane & 8)) * 2;

    const __nv_bfloat16* Ah = RBb + (size_t)(m0 + (tid >> 1)) * H_ + kst + (tid & 1) * 16;

    float wvr[16];
#pragma unroll
    for (int k = 0; k < 16; k++) wvr[k] = __ldg(wv + lane + 32 * k);

    int pA = blk * 2, pB = blk * 2 + 1;
    int aA = pA >> 7, bA = pA & 127;
    int aB = pB >> 7, bB = pB & 127;
    int sl2A = aA ? s1[bA] : s2[bA];
    int sl2B = aB ? s1[bB] : s2[bB];
    int slmA = aA ? s2[bA] : s1[bA];
    int slmB = aB ? s2[bB] : s1[bB];

    for (int t = 0; t < T_; t++) {
        // ---- phase G ----
        {
            float acc[4][4][4] = {};
            gemm_k3(Ah, Ah + P_RB, Bhg, Blg, 4, sb, aSt, bSt, aLd, bLd, wid, acc);
            float* Cb = uPt4 + (size_t)ks * 256 * 1024;
#pragma unroll
            for (int mt = 0; mt < 4; mt++) {
                int r = m0 + mt * 16 + (lane >> 2);
#pragma unroll
                for (int nt = 0; nt < 4; nt++) {
                    int c = n0 + wid * 32 + nt * 8 + (lane & 3) * 2;
                    *(float2*)(Cb + (size_t)r * 1024 + c) =
                        make_float2(acc[mt][nt][0], acc[mt][nt][1]);
                    *(float2*)(Cb + (size_t)(r + 8) * 1024 + c) =
                        make_float2(acc[mt][nt][2], acc[mt][nt][3]);
                }
            }
        }
        gbar(sync + 2, sync + 3, (unsigned)(2 * t + 1), 128u);

        // ---- phase A ----
        for (int pi = 0; pi < 2; pi++) {
            int p    = pi ? pB : pA;
            int a    = pi ? aB : aA;
            int b    = pi ? bB : bA;
            int sl2  = pi ? sl2B : sl2A;
            int slm  = pi ? slmB : slmA;
            if (t >= sl2) continue;

            float* su  = smf;
            float* spt = smf + 512;
            float* sc  = smf + 1024;
            const float* hb = HWy + (size_t)a * B_ * T_ * H_ + ((size_t)b * T_ + t) * H_;
#pragma unroll
            for (int q = 0; q < 4; q++) {
                int h = tid + q * 128;
                float s0 = 0.f, s1v = 0.f;
#pragma unroll
                for (int k = 0; k < 4; k++) {
                    const float* up = uPt4 + ((size_t)k * 256 + p) * 1024;
                    s0  += __ldcg(up + h);
                    s1v += __ldcg(up + 512 + h);
                }
                su[h]  = s0 + __ldg(hb + h);
                spt[h] = s1v;
            }
            __syncthreads();
            const float* WyYb = WyY + (size_t)a * B_ * T_ * H_ + (size_t)b * T_ * H_;
#pragma unroll
            for (int q = 0; q < 16; q++) {
                int t2 = wid * 16 + q;
                if (t2 < slm) {
                    const float* row = WyYb + (size_t)t2 * H_;
                    float s = 0.f;
#pragma unroll
                    for (int k = 0; k < 16; k++) {
                        int hh = lane + 32 * k;
                        s += tanha(__ldg(row + hh) + su[hh]) * wvr[k];
                    }
                    for (int o = 16; o; o >>= 1) s += __shfl_xor_sync(0xffffffffu, s, o);
                    if (lane == 0) sc[t2] = s;
                } else if (lane == 0) {
                    sc[t2] = -10000.f;
                }
            }
            __syncthreads();
            if (wid == 0) {
                float v1 = sc[lane], v2 = sc[lane + 32];
                float m = fmaxf(v1, v2);
                for (int o = 16; o; o >>= 1) m = fmaxf(m, __shfl_xor_sync(0xffffffffu, m, o));
                float e1 = __expf(v1 - m), e2 = __expf(v2 - m);
                float s = e1 + e2;
                for (int o = 16; o; o >>= 1) s += __shfl_xor_sync(0xffffffffu, s, o);
                float inv = __fdividef(1.f, s);
                sc[lane] = e1 * inv;
                sc[lane + 32] = e2 * inv;
            }
            __syncthreads();
            const float* Yp = Yb + (size_t)(a ? 2 : 0) * B_ * T_ * H_ + (size_t)b * T_ * H_;
#pragma unroll
            for (int q = 0; q < 4; q++) {
                int h = tid + q * 128;
                float accv = 0.f;
                for (int t2 = 0; t2 < slm; t2++)
                    accv += sc[t2] * __ldg(Yp + (size_t)t2 * H_ + h);
                float rn = accv + ftanh(spt[h]);
                if (t == sl2 - 1) {
                    rL[(size_t)p * H_ + h] = rn;
                } else {
                    __nv_bfloat16* rp = RBb + (size_t)p * H_ + h;
                    split_store(rn, rp, rp + P_RB);
                }
            }
            __syncthreads();
        }
        gbar(sync + 2, sync + 3, (unsigned)(2 * t + 2), 128u);
    }
}

// ---------------- final projection ----------------
__global__ void __launch_bounds__(512) k_final(
    const float* __restrict__ rL, const float* __restrict__ hfin,
    const float* __restrict__ Wp, const float* __restrict__ Wx,
    const float* __restrict__ U, const float* __restrict__ bU,
    float* __restrict__ out) {
    int b = blockIdx.x;
    int tid = threadIdx.x;
    __shared__ float s_in[4][512];
    __shared__ float s_sum[512];
    __shared__ float red0[16], red1[16];
    s_in[0][tid] = rL[(size_t)b * H_ + tid];
    s_in[1][tid] = hfin[((size_t)1 * B_ + b) * H_ + tid];
    s_in[2][tid] = rL[((size_t)B_ + b) * H_ + tid];
    s_in[3][tid] = hfin[((size_t)3 * B_ + b) * H_ + tid];
    __syncthreads();
    float acc0 = 0.f, acc1 = 0.f;
    for (int k = 0; k < H_; k++) {
        float wp = Wp[(size_t)k * H_ + tid];
        float wx = Wx[(size_t)k * H_ + tid];
        acc0 += s_in[0][k] * wp + s_in[1][k] * wx;
        acc1 += s_in[2][k] * wp + s_in[3][k] * wx;
    }
    s_sum[tid] = ftanh(acc0) + ftanh(acc1);
    __syncthreads();
    float p0 = s_sum[tid] * U[(size_t)tid * 2 + 0];
    float p1 = s_sum[tid] * U[(size_t)tid * 2 + 1];
    for (int o = 16; o; o >>= 1) {
        p0 += __shfl_xor_sync(0xffffffffu, p0, o);
        p1 += __shfl_xor_sync(0xffffffffu, p1, o);
    }
    int wp_ = tid >> 5;
    if ((tid & 31) == 0) { red0[wp_] = p0; red1[wp_] = p1; }
    __syncthreads();
    if (tid < 16) {
        p0 = red0[tid]; p1 = red1[tid];
        for (int o = 8; o; o >>= 1) {
            p0 += __shfl_xor_sync(0x0000ffffu, p0, o);
            p1 += __shfl_xor_sync(0x0000ffffu, p1, o);
        }
        if (tid == 0) {
            out[b * 2 + 0] = p0 + bU[0];
            out[b * 2 + 1] = p1 + bU[1];
        }
    }
}

// ---------------- host ----------------
extern "C" void kernel_launch(void* const* d_in, const int* in_sizes, int n_in,
                              void* d_out, int out_size) {
    (void)in_sizes; (void)n_in; (void)out_size;
    const int*   tokens1 = (const int*)d_in[0];
    const int*   tokens2 = (const int*)d_in[1];
    const int*   seqlen1 = (const int*)d_in[2];
    const int*   seqlen2 = (const int*)d_in[3];
    const float* emb = (const float*)d_in[4];
    const float* W1  = (const float*)d_in[5];
    const float* b1  = (const float*)d_in[6];
    const float* W2  = (const float*)d_in[7];
    const float* b2  = (const float*)d_in[8];
    const float* Wy  = (const float*)d_in[9];
    const float* Wh  = (const float*)d_in[10];
    const float* Wr  = (const float*)d_in[11];
    const float* wv  = (const float*)d_in[12];
    const float* Wt  = (const float*)d_in[13];
    const float* Wp  = (const float*)d_in[14];
    const float* Wx  = (const float*)d_in[15];
    const float* U   = (const float*)d_in[16];
    const float* bU  = (const float*)d_in[17];
    float* out = (float*)d_out;

    cudaFuncSetAttribute(mm_gemm, cudaFuncAttributeMaxDynamicSharedMemorySize, SMEM_MM);
    cudaFuncSetAttribute(k_lstm_persist, cudaFuncAttributeMaxDynamicSharedMemorySize, SMEM_MM);
    cudaFuncSetAttribute(k_att_persist, cudaFuncAttributeMaxDynamicSharedMemorySize, SMEM_MM);

    float* buf = nullptr;
    cudaGetSymbolAddress((void**)&buf, d_buf);
    float* Xg   = buf + OFF_XG;
    float* hBuf = buf + OFF_H;
    float* WyY  = buf + OFF_WYY;
    float* HWy  = buf + OFF_HWY;
    float* rL   = buf + OFF_RL;
    float* bP   = buf + OFF_BP;
    __nv_bfloat16* EB  = (__nv_bfloat16*)(buf + OFF_EB);
    __nv_bfloat16* YB  = (__nv_bfloat16*)(buf + OFF_YB);
    __nv_bfloat16* WxS = (__nv_bfloat16*)(buf + OFF_WXS);
    __nv_bfloat16* WyS = (__nv_bfloat16*)(buf + OFF_WYS);
    __nv_bfloat16* WhA = (__nv_bfloat16*)(buf + OFF_WHA);

    // launch #1, #2
    k_prep<<<1024, 256>>>(W1, W2, Wy, Wh, Wr, Wt, b1, b2);
    k_gather<<<2048, 256>>>(tokens1, tokens2, emb);

    const int iidx[4] = {0, 1, 1, 0}, widx[4] = {0, 1, 0, 1};

    // launch #3: X-part GEMM (A = EB bf16 planes)
    {
        MP p = {};
        for (int r = 0; r < 4; r++) {
            p.z[r].Ahi  = EB + (size_t)iidx[r] * 2 * P_E;
            p.z[r].Alo  = EB + (size_t)iidx[r] * 2 * P_E + P_E;
            p.z[r].Bhi  = WxS + (size_t)(widx[r] * 2 + 0) * G4_ * KPX;
            p.z[r].Blo  = WxS + (size_t)(widx[r] * 2 + 1) * G4_ * KPX;
            p.z[r].C    = Xg + (size_t)r * B_ * T_ * G4_;
            p.z[r].bias = bP + (size_t)widx[r] * G4_;
        }
        p.Klen = KPX; p.lda = KPX; p.ldb = KPX; p.ldc = G4_;
        mm_gemm<<<dim3(G4_ / TN, (B_ * T_) / TM, 4), 128, SMEM_MM>>>(p);
    }

    // launch #4 (ncu target): persistent LSTM scan
    k_lstm_persist<<<128, 128, SMEM_MM>>>(seqlen1, seqlen2);

    // launch #5: WyY + HWy (A = YB bf16 planes)
    {
        MP p = {};
        const int runs[4] = {0, 2, 1, 3};
        for (int q = 0; q < 4; q++) {
            p.z[q].Ahi = YB + (size_t)runs[q] * B_ * T_ * H_;
            p.z[q].Alo = YB + P_Y + (size_t)runs[q] * B_ * T_ * H_;
            p.z[q].Bhi = (q < 2 ? WyS : WhA);
            p.z[q].Blo = (q < 2 ? WyS : WhA) + (size_t)H_ * H_;
            p.z[q].C   = (q < 2 ? WyY + (size_t)q * B_ * T_ * H_
                                : HWy + (size_t)(q - 2) * B_ * T_ * H_);
            p.z[q].bias = nullptr;
        }
        p.Klen = H_; p.lda = H_; p.ldb = H_; p.ldc = H_;
        mm_gemm<<<dim3(H_ / TN, (B_ * T_) / TM, 4), 128, SMEM_MM>>>(p);
    }

    // launch #6: persistent attention scan
    k_att_persist<<<128, 128, SMEM_MM>>>(wv, seqlen1, seqlen2);

    // launch #7
    k_final<<<B_, 512>>>(rL, hBuf, Wp, Wx, U, bU, out);
}

// round 8
// speedup vs baseline: 1.0147x; 1.0147x over previous
#include <cuda_runtime.h>
#include <cuda_bf16.h>
#include <math.h>
#include <stdint.h>

#define B_   128
#define T_   64
#define D_   300
#define KPX  320
#define H_   512
#define G4_  2048

#define TM 64
#define TN 128
#define KC 32
#define PAD 40
// per-group pipeline slab (same as R6): A 4x5120 + B 4x10240 = 61440 bytes
#define A_BASE(term,stage) ((uint32_t)(((term)*2+(stage))*5120))
#define B_BASE(term,stage) ((uint32_t)(20480u + ((term)*2+(stage))*10240u))
#define GSLAB 61440u
static constexpr int SMEM_MM   = 61440;    // bulk gemm: 128 thr, 1 group
static constexpr int SMEM_PST  = 122880;   // persistent: 256 thr, 2 groups

// epilogue reduction scratch index (floats), reuses pipeline smem
#define RED(w, mtl, nt, ln, q) (((((w)*2+(mtl))*4+(nt))*32+(ln))*4+(q))

__device__ __forceinline__ uint32_t smem_u32(const void* p) {
    uint32_t a;
    asm("{ .reg .u64 t; cvta.to.shared.u64 t, %1; cvt.u32.u64 %0, t; }" : "=r"(a) : "l"(p));
    return a;
}
#define CP_ASYNC16(dst, src) \
    asm volatile("cp.async.cg.shared.global [%0], [%1], 16;" :: "r"(dst), "l"(src))
#define CP_COMMIT() asm volatile("cp.async.commit_group;" ::: "memory")
#define CP_WAIT0()  asm volatile("cp.async.wait_group 0;" ::: "memory")
#define LDSM4(r0, r1, r2, r3, addr) \
    asm volatile("ldmatrix.sync.aligned.m8n8.x4.shared.b16 {%0,%1,%2,%3}, [%4];" \
                 : "=r"(r0), "=r"(r1), "=r"(r2), "=r"(r3) : "r"(addr))
#define MMA16816(c, a, b0, b1) \
    asm volatile("mma.sync.aligned.m16n8k16.row.col.f32.bf16.bf16.f32 " \
                 "{%0,%1,%2,%3}, {%4,%5,%6,%7}, {%8,%9}, {%0,%1,%2,%3};" \
                 : "+f"((c)[0]), "+f"((c)[1]), "+f"((c)[2]), "+f"((c)[3]) \
                 : "r"((a)[0]), "r"((a)[1]), "r"((a)[2]), "r"((a)[3]), \
                   "r"(b0), "r"(b1))

__device__ __forceinline__ float sigf(float x) { return __fdividef(1.f, 1.f + __expf(-x)); }
__device__ __forceinline__ float ftanh(float x) { return 1.f - __fdividef(2.f, __expf(2.f * x) + 1.f); }
__device__ __forceinline__ float tanha(float x) {
    float y; asm("tanh.approx.f32 %0, %1;" : "=f"(y) : "f"(x)); return y;
}

// ---------------- scratch layout (float units) — R6 layout ----------------
static constexpr size_t OFF_E    = 0;
static constexpr size_t OFF_XG   = OFF_E   + 2ull * B_ * T_ * KPX;
static constexpr size_t OFF_Y    = OFF_XG  + 4ull * B_ * T_ * G4_;
static constexpr size_t OFF_H    = OFF_Y   + 4ull * B_ * T_ * H_;
static constexpr size_t OFF_C    = OFF_H   + 2ull * 4 * B_ * H_;
static constexpr size_t OFF_WYY  = OFF_C   + 4ull * B_ * H_;
static constexpr size_t OFF_HWY  = OFF_WYY + 2ull * B_ * T_ * H_;
static constexpr size_t OFF_UPT  = OFF_HWY + 2ull * B_ * T_ * H_;
static constexpr size_t OFF_R    = OFF_UPT + 4ull * 256 * 1024;
static constexpr size_t OFF_RL   = OFF_R   + 256ull * H_;
static constexpr size_t OFF_BP   = OFF_RL  + 256ull * H_;
static constexpr size_t OFF_WXS  = OFF_BP  + 2ull * G4_;
static constexpr size_t OFF_WHS  = OFF_WXS + (2ull * 2 * G4_ * KPX) / 2;
static constexpr size_t OFF_WYS  = OFF_WHS + (2ull * 2 * G4_ * H_) / 2;
static constexpr size_t OFF_WHA  = OFF_WYS + (2ull * H_ * H_) / 2;
static constexpr size_t OFF_WCS  = OFF_WHA + (2ull * H_ * H_) / 2;
static constexpr size_t OFF_SYNC = OFF_WCS + (2ull * 2 * H_ * H_) / 2;
static constexpr size_t TOTAL_F  = OFF_SYNC + 16;

__device__ __align__(256) float d_buf[TOTAL_F];

__device__ __forceinline__ void split_store(float v, __nv_bfloat16* hi, __nv_bfloat16* lo) {
    __nv_bfloat16 h = __float2bfloat16_rn(v);
    *hi = h;
    *lo = __float2bfloat16_rn(v - __bfloat162float(h));
}

// ---------------- grid barrier ----------------
__device__ __forceinline__ void gbar(unsigned* cnt, unsigned* rel,
                                     unsigned seq, unsigned ncta) {
    __syncthreads();
    if (threadIdx.x == 0) {
        unsigned old;
        asm volatile("fence.acq_rel.gpu;" ::: "memory");
        asm volatile("atom.relaxed.gpu.global.add.u32 %0, [%1], 1;"
                     : "=r"(old) : "l"(cnt) : "memory");
        if (old + 1u == ncta * seq) {
            asm volatile("st.release.gpu.global.u32 [%0], %1;"
                         :: "l"(rel), "r"(seq) : "memory");
        }
        unsigned v;
        do {
            asm volatile("ld.acquire.gpu.global.u32 %0, [%1];"
                         : "=r"(v) : "l"(rel) : "memory");
        } while (v < seq);
    }
    __syncthreads();
}

// ---------------- prep: weight splits + all zero-init ----------------
__global__ void k_prep(const float* __restrict__ W1, const float* __restrict__ W2,
                       const float* __restrict__ Wy, const float* __restrict__ Wh,
                       const float* __restrict__ Wr, const float* __restrict__ Wt,
                       const float* __restrict__ b1, const float* __restrict__ b2) {
    float* buf = d_buf;
    __nv_bfloat16* WxS = (__nv_bfloat16*)(buf + OFF_WXS);
    __nv_bfloat16* WhS = (__nv_bfloat16*)(buf + OFF_WHS);
    __nv_bfloat16* WyS = (__nv_bfloat16*)(buf + OFF_WYS);
    __nv_bfloat16* WhA = (__nv_bfloat16*)(buf + OFF_WHA);
    __nv_bfloat16* WcS = (__nv_bfloat16*)(buf + OFF_WCS);
    float* bP = buf + OFF_BP;

    const size_t R1 = 2ull * G4_ * KPX;
    const size_t R2 = 2ull * G4_ * H_;
    const size_t R3 = (size_t)H_ * H_;
    const size_t R4 = (size_t)H_ * H_;
    const size_t R5 = 2ull * H_ * H_;
    const size_t R6 = 2ull * G4_;
    const size_t R7 = 12ull * B_ * H_;      // h ping-pong + c
    const size_t R8 = 256ull * H_;          // rbuf
    const size_t R9 = 16;                   // sync
    const size_t TOT = R1 + R2 + R3 + R4 + R5 + R6 + R7 + R8 + R9;
    size_t stride = (size_t)gridDim.x * blockDim.x;
    for (size_t id = (size_t)blockIdx.x * blockDim.x + threadIdx.x; id < TOT; id += stride) {
        size_t i = id;
        if (i < R1) {
            int w = (int)(i / ((size_t)G4_ * KPX));
            size_t rem = i % ((size_t)G4_ * KPX);
            int np = (int)(rem / KPX), k = (int)(rem % KPX);
            int col = (np & 3) * H_ + (np >> 2);
            const float* W = w ? W2 : W1;
            float v = (k < D_) ? W[(size_t)k * G4_ + col] : 0.f;
            size_t o = ((size_t)(w * 2) * G4_ + np) * KPX + k;
            split_store(v, WxS + o, WxS + o + (size_t)G4_ * KPX);
            continue;
        }
        i -= R1;
        if (i < R2) {
            int w = (int)(i / ((size_t)G4_ * H_));
            size_t rem = i % ((size_t)G4_ * H_);
            int np = (int)(rem / H_), k = (int)(rem % H_);
            int col = (np & 3) * H_ + (np >> 2);
            const float* W = w ? W2 : W1;
            float v = W[(size_t)(D_ + k) * G4_ + col];
            size_t o = ((size_t)(w * 2) * G4_ + np) * H_ + k;
            split_store(v, WhS + o, WhS + o + (size_t)G4_ * H_);
            continue;
        }
        i -= R2;
        if (i < R3) {
            int n = (int)(i / H_), k = (int)(i % H_);
            size_t o = (size_t)n * H_ + k;
            split_store(Wy[(size_t)k * H_ + n], WyS + o, WyS + o + (size_t)H_ * H_);
            continue;
        }
        i -= R3;
        if (i < R4) {
            int n = (int)(i / H_), k = (int)(i % H_);
            size_t o = (size_t)n * H_ + k;
            split_store(Wh[(size_t)k * H_ + n], WhA + o, WhA + o + (size_t)H_ * H_);
            continue;
        }
        i -= R4;
        if (i < R5) {
            int n = (int)(i / H_), k = (int)(i % H_);
            float v = (n < H_) ? Wr[(size_t)k * H_ + n] : Wt[(size_t)k * H_ + (n - H_)];
            size_t o = (size_t)n * H_ + k;
            split_store(v, WcS + o, WcS + o + 2ull * H_ * H_);
            continue;
        }
        i -= R5;
        if (i < R6) {
            int w = (int)(i / G4_), np = (int)(i % G4_);
            int col = (np & 3) * H_ + (np >> 2);
            bP[i] = (w ? b2 : b1)[col];
            continue;
        }
        i -= R6;
        if (i < R7) { (buf + OFF_H)[i] = 0.f; continue; }
        i -= R7;
        if (i < R8) { (buf + OFF_R)[i] = 0.f; continue; }
        i -= R8;
        (buf + OFF_SYNC)[i] = 0.f;
    }
}

__global__ void k_gather(float* __restrict__ e, const int* __restrict__ t1,
                         const int* __restrict__ t2, const float* __restrict__ emb) {
    size_t total = 2ull * B_ * T_ * KPX;
    size_t stride = (size_t)gridDim.x * blockDim.x;
    for (size_t i = (size_t)blockIdx.x * blockDim.x + threadIdx.x; i < total; i += stride) {
        int which = (int)(i / ((size_t)B_ * T_ * KPX));
        size_t rem = i % ((size_t)B_ * T_ * KPX);
        int bt = (int)(rem / KPX), k = (int)(rem % KPX);
        int tok = (which ? t2 : t1)[bt];
        e[i] = (k < D_) ? emb[(size_t)tok * D_ + k] : 0.f;
    }
}

// ---------------------------------------------------------------------------
// Core K-loop for ONE warp-group (128 threads): acc += A(fp32) x B(bf16 hi/lo)
// over `nch` chunks starting at the given pointers. Double-buffered as in R6.
// __syncthreads inside is executed by ALL warps (both groups run same nch).
// ---------------------------------------------------------------------------
__device__ __forceinline__ void gemm_k(
    const float* __restrict__ Ag, const __nv_bfloat16* __restrict__ Bhg,
    const __nv_bfloat16* __restrict__ Blg, int nch,
    char* smem_raw, uint32_t sb, uint32_t gofs,
    uint32_t aSt, uint32_t bSt, uint32_t aLd, uint32_t bLd,
    int wg, float acc[4][4][4]) {
    float fA[16];
    {
#pragma unroll
        for (int q = 0; q < 4; q++) {
            CP_ASYNC16(sb + gofs + B_BASE(0, 0) + bSt + q * 16, Bhg + q * 8);
            CP_ASYNC16(sb + gofs + B_BASE(1, 0) + bSt + q * 16, Blg + q * 8);
        }
        CP_COMMIT();
        const float4* s4 = (const float4*)Ag;
#pragma unroll
        for (int q = 0; q < 4; q++) {
            float4 v = __ldcg(s4 + q);
            fA[4 * q] = v.x; fA[4 * q + 1] = v.y; fA[4 * q + 2] = v.z; fA[4 * q + 3] = v.w;
        }
        ushort hi[16], lo[16];
#pragma unroll
        for (int q = 0; q < 16; q++) {
            __nv_bfloat16 hb = __float2bfloat16_rn(fA[q]);
            __nv_bfloat16 lb = __float2bfloat16_rn(fA[q] - __bfloat162float(hb));
            hi[q] = *(ushort*)&hb; lo[q] = *(ushort*)&lb;
        }
        *(uint4*)(smem_raw + gofs + A_BASE(0, 0) + aSt)      = *(uint4*)(hi);
        *(uint4*)(smem_raw + gofs + A_BASE(0, 0) + aSt + 16) = *(uint4*)(hi + 8);
        *(uint4*)(smem_raw + gofs + A_BASE(1, 0) + aSt)      = *(uint4*)(lo);
        *(uint4*)(smem_raw + gofs + A_BASE(1, 0) + aSt + 16) = *(uint4*)(lo + 8);
        CP_WAIT0();
        __syncthreads();
    }
    for (int ch = 0; ch < nch; ch++) {
        int s = ch & 1, ns = s ^ 1;
        bool more = (ch + 1) < nch;
        if (more) {
            const __nv_bfloat16* bh2 = Bhg + (ch + 1) * KC;
            const __nv_bfloat16* bl2 = Blg + (ch + 1) * KC;
#pragma unroll
            for (int q = 0; q < 4; q++) {
                CP_ASYNC16(sb + gofs + B_BASE(0, ns) + bSt + q * 16, bh2 + q * 8);
                CP_ASYNC16(sb + gofs + B_BASE(1, ns) + bSt + q * 16, bl2 + q * 8);
            }
            CP_COMMIT();
            const float4* s4 = (const float4*)(Ag + (ch + 1) * KC);
#pragma unroll
            for (int q = 0; q < 4; q++) {
                float4 v = __ldcg(s4 + q);
                fA[4 * q] = v.x; fA[4 * q + 1] = v.y; fA[4 * q + 2] = v.z; fA[4 * q + 3] = v.w;
            }
        }
#pragma unroll
        for (int h16 = 0; h16 < 2; h16++) {
            uint32_t kb = (uint32_t)h16 * 32;
            uint32_t bh[8], bl[8];
#pragma unroll
            for (int g2 = 0; g2 < 2; g2++) {
                uint32_t rowb = (uint32_t)((wg * 32 + g2 * 16) * PAD) * 2;
                LDSM4(bh[g2 * 4 + 0], bh[g2 * 4 + 1], bh[g2 * 4 + 2], bh[g2 * 4 + 3],
                      sb + gofs + B_BASE(0, s) + bLd + rowb + kb);
                LDSM4(bl[g2 * 4 + 0], bl[g2 * 4 + 1], bl[g2 * 4 + 2], bl[g2 * 4 + 3],
                      sb + gofs + B_BASE(1, s) + bLd + rowb + kb);
            }
#pragma unroll
            for (int mt = 0; mt < 4; mt++) {
                uint32_t ah[4], al[4];
                uint32_t rowa = (uint32_t)(mt * 16 * PAD) * 2;
                LDSM4(ah[0], ah[1], ah[2], ah[3], sb + gofs + A_BASE(0, s) + aLd + rowa + kb);
                LDSM4(al[0], al[1], al[2], al[3], sb + gofs + A_BASE(1, s) + aLd + rowa + kb);
#pragma unroll
                for (int nt = 0; nt < 4; nt++) {
                    int bi = (nt >> 1) * 4 + (nt & 1) * 2;
                    MMA16816(acc[mt][nt], ah, bh[bi], bh[bi + 1]);
                    MMA16816(acc[mt][nt], ah, bl[bi], bl[bi + 1]);
                    MMA16816(acc[mt][nt], al, bh[bi], bh[bi + 1]);
                }
            }
        }
        if (more) {
            ushort hi[16], lo[16];
#pragma unroll
            for (int q = 0; q < 16; q++) {
                __nv_bfloat16 hb = __float2bfloat16_rn(fA[q]);
                __nv_bfloat16 lb = __float2bfloat16_rn(fA[q] - __bfloat162float(hb));
                hi[q] = *(ushort*)&hb; lo[q] = *(ushort*)&lb;
            }
            *(uint4*)(smem_raw + gofs + A_BASE(0, ns) + aSt)      = *(uint4*)(hi);
            *(uint4*)(smem_raw + gofs + A_BASE(0, ns) + aSt + 16) = *(uint4*)(hi + 8);
            *(uint4*)(smem_raw + gofs + A_BASE(1, ns) + aSt)      = *(uint4*)(lo);
            *(uint4*)(smem_raw + gofs + A_BASE(1, ns) + aSt + 16) = *(uint4*)(lo + 8);
            CP_WAIT0();
        }
        __syncthreads();
    }
}

// split-K partial exchange: warp w stores the 2 mts its partner (w^4) handles,
// then adds partner's partials into its own 2 handled mts.
__device__ __forceinline__ void splitk_reduce(float* red, int wid, int lane, int g,
                                              float acc[4][4][4]) {
#pragma unroll
    for (int mtl = 0; mtl < 2; mtl++) {
        int mts = g ? mtl : (2 + mtl);   // store what partner handles
#pragma unroll
        for (int nt = 0; nt < 4; nt++)
#pragma unroll
            for (int q = 0; q < 4; q++)
                red[RED(wid, mtl, nt, lane, q)] = acc[mts][nt][q];
    }
    __syncthreads();
    int pw = wid ^ 4;
#pragma unroll
    for (int mtl = 0; mtl < 2; mtl++) {
        int mtm = g ? (2 + mtl) : mtl;   // handled mts
#pragma unroll
        for (int nt = 0; nt < 4; nt++)
#pragma unroll
            for (int q = 0; q < 4; q++)
                acc[mtm][nt][q] += red[RED(pw, mtl, nt, lane, q)];
    }
}

// ---------------- bulk GEMM (128 thr, unchanged from R6) ----------------
struct MZ {
    const float*         A;
    const __nv_bfloat16* Bhi;
    const __nv_bfloat16* Blo;
    float*               C;
    const float*         bias;
};
struct MP {
    MZ z[4];
    int Klen, lda, ldb, ldc;
};

__global__ void __launch_bounds__(128) mm_gemm(MP p) {
    extern __shared__ __align__(16) char smem_raw[];
    uint32_t sb = smem_u32(smem_raw);
    const MZ z = p.z[blockIdx.z];
    int tid = threadIdx.x, lane = tid & 31, wid = tid >> 5;
    int n0 = blockIdx.x * TN, m0 = blockIdx.y * TM;

    const float*         Ag  = z.A   + (size_t)(m0 + (tid >> 1)) * p.lda + (tid & 1) * 16;
    const __nv_bfloat16* Bhg = z.Bhi + (size_t)(n0 + tid) * p.ldb;
    const __nv_bfloat16* Blg = z.Blo + (size_t)(n0 + tid) * p.ldb;
    uint32_t aSt = (uint32_t)((tid >> 1) * PAD + (tid & 1) * 16) * 2;
    uint32_t bSt = (uint32_t)(tid * PAD) * 2;
    uint32_t aLd = (uint32_t)((lane & 15) * PAD + ((lane >> 4) << 3)) * 2;
    uint32_t bLd = (uint32_t)(((lane & 7) + ((lane & 16) >> 1)) * PAD + (lane & 8)) * 2;

    float acc[4][4][4] = {};
    gemm_k(Ag, Bhg, Blg, p.Klen / KC, smem_raw, sb, 0, aSt, bSt, aLd, bLd, wid, acc);

#pragma unroll
    for (int mt = 0; mt < 4; mt++) {
        int r = m0 + mt * 16 + (lane >> 2);
#pragma unroll
        for (int nt = 0; nt < 4; nt++) {
            int c = n0 + wid * 32 + nt * 8 + (lane & 3) * 2;
            float b0 = 0.f, b1 = 0.f;
            if (z.bias) { b0 = z.bias[c]; b1 = z.bias[c + 1]; }
            *(float2*)(z.C + (size_t)r * p.ldc + c) =
                make_float2(acc[mt][nt][0] + b0, acc[mt][nt][1] + b1);
            *(float2*)(z.C + (size_t)(r + 8) * p.ldc + c) =
                make_float2(acc[mt][nt][2] + b0, acc[mt][nt][3] + b1);
        }
    }
}

// ---------------- persistent LSTM scan (256 thr, split-K x2) ----------------
__global__ void __launch_bounds__(256) k_lstm_persist(
    const int* __restrict__ s1, const int* __restrict__ s2) {
    extern __shared__ __align__(16) char smem_raw[];
    uint32_t sb = smem_u32(smem_raw);
    float* red = (float*)smem_raw;
    float* buf = d_buf;
    int tid = threadIdx.x, lane = tid & 31, wid = tid >> 5;
    int g = tid >> 7, tg = tid & 127, wg = wid & 3;
    uint32_t gofs = (uint32_t)g * GSLAB;
    int blk = blockIdx.x;
    int r  = blk >> 5;
    int mt_ = (blk >> 4) & 1;
    int nt_ = blk & 15;
    int n0 = nt_ * TN, m0 = mt_ * TM;
    int widx = (r == 0 || r == 2) ? 0 : 1;
    const int* sl = (r == 0 || r == 3) ? s1 : s2;
    const int KH = H_ / 2;   // per-group K half

    const __nv_bfloat16* WhS = (const __nv_bfloat16*)(buf + OFF_WHS);
    const __nv_bfloat16* Bhg = WhS + (size_t)(widx * 2 + 0) * G4_ * H_
                               + (size_t)(n0 + tg) * H_ + g * KH;
    const __nv_bfloat16* Blg = WhS + (size_t)(widx * 2 + 1) * G4_ * H_
                               + (size_t)(n0 + tg) * H_ + g * KH;

    const float* Xg  = buf + OFF_XG + (size_t)r * B_ * T_ * G4_;
    float*       cst = buf + OFF_C + (size_t)r * B_ * H_;
    float*       Yst = buf + OFF_Y + (size_t)r * B_ * T_ * H_;
    float*       hB  = buf + OFF_H;
    const size_t HBUF = 4ull * B_ * H_;

    unsigned* sync = (unsigned*)(buf + OFF_SYNC);

    uint32_t aSt = (uint32_t)((tg >> 1) * PAD + (tg & 1) * 16) * 2;
    uint32_t bSt = (uint32_t)(tg * PAD) * 2;
    uint32_t aLd = (uint32_t)((lane & 15) * PAD + ((lane >> 4) << 3)) * 2;
    uint32_t bLd = (uint32_t)(((lane & 7) + ((lane & 16) >> 1)) * PAD + (lane & 8)) * 2;

    for (int t = 0; t < T_; t++) {
        const float* hin  = hB + (size_t)(t & 1) * HBUF + (size_t)r * B_ * H_;
        float*       hout = hB + (size_t)((t + 1) & 1) * HBUF + (size_t)r * B_ * H_;
        const float* Ag = hin + (size_t)(m0 + (tg >> 1)) * H_ + g * KH + (tg & 1) * 16;

        float acc[4][4][4] = {};
        gemm_k(Ag, Bhg, Blg, KH / KC, smem_raw, sb, gofs, aSt, bSt, aLd, bLd, wg, acc);
        splitk_reduce(red, wid, lane, g, acc);

        // epilogue: each warp handles 2 mts (group0: 0-1, group1: 2-3)
#pragma unroll
        for (int mtl = 0; mtl < 2; mtl++) {
            int mt = g ? (2 + mtl) : mtl;
            int b = m0 + mt * 16 + (lane >> 2);
#pragma unroll
            for (int nt = 0; nt < 4; nt++) {
                float fo0 = __shfl_xor_sync(0xffffffffu, acc[mt][nt][0], 1);
                float fo1 = __shfl_xor_sync(0xffffffffu, acc[mt][nt][1], 1);
                float fo2 = __shfl_xor_sync(0xffffffffu, acc[mt][nt][2], 1);
                float fo3 = __shfl_xor_sync(0xffffffffu, acc[mt][nt][3], 1);
                if (!(lane & 1)) {
#pragma unroll
                    for (int half = 0; half < 2; half++) {
                        int bb = b + half * 8;
                        float gi = half ? acc[mt][nt][2] : acc[mt][nt][0];
                        float gj = half ? acc[mt][nt][3] : acc[mt][nt][1];
                        float gf = half ? fo2 : fo0;
                        float go = half ? fo3 : fo1;
                        int c0 = n0 + wg * 32 + nt * 8 + (lane & 3) * 2;
                        int j = c0 >> 2;
                        float4 x = *(const float4*)(Xg + ((size_t)bb * T_ + t) * G4_ + c0);
                        gi += x.x; gj += x.y; gf += x.z; go += x.w;
                        size_t ci = (size_t)bb * H_ + j;
                        float yv = 0.f;
                        if (t < sl[bb]) {
                            float cc = cst[ci];
                            float cn = cc * sigf(gf + 1.f) + sigf(gi) * ftanh(gj);
                            float hn = ftanh(cn) * sigf(go);
                            cst[ci] = cn;
                            hout[ci] = hn;
                            yv = hn;
                        } else {
                            hout[ci] = __ldcg(hin + ci);
                        }
                        Yst[((size_t)bb * T_ + t) * H_ + j] = yv;
                    }
                }
            }
        }
        gbar(sync + 0, sync + 1, (unsigned)(t + 1), 128u);
    }
}

// ---------------- persistent attention scan (256 thr, split-K x2) ----------
__global__ void __launch_bounds__(256) k_att_persist(
    const float* __restrict__ wv,
    const int* __restrict__ s1, const int* __restrict__ s2) {
    extern __shared__ __align__(16) char smem_raw[];
    uint32_t sb = smem_u32(smem_raw);
    float* red = (float*)smem_raw;
    float* smf = (float*)smem_raw;
    float* buf = d_buf;
    int tid = threadIdx.x, lane = tid & 31, wid = tid >> 5;
    int g = tid >> 7, tg = tid & 127, wg = wid & 3;
    uint32_t gofs = (uint32_t)g * GSLAB;
    int blk = blockIdx.x;

    int ks  = blk & 3;
    int mt_ = (blk >> 2) & 3;
    int nt_ = blk >> 4;
    int m0 = mt_ * TM, n0 = nt_ * TN, kst = ks * 128;
    const int KH = 64;   // per-group half of the 128-wide k-slice

    const __nv_bfloat16* WcS = (const __nv_bfloat16*)(buf + OFF_WCS);
    const __nv_bfloat16* Bhg = WcS + (size_t)(n0 + tg) * H_ + kst + g * KH;
    const __nv_bfloat16* Blg = WcS + 2ull * H_ * H_ + (size_t)(n0 + tg) * H_ + kst + g * KH;

    float* rbuf = buf + OFF_R;
    float* uPt4 = buf + OFF_UPT;
    float* rL   = buf + OFF_RL;
    const float* WyY = buf + OFF_WYY;
    const float* HWy = buf + OFF_HWY;
    const float* Yb  = buf + OFF_Y;
    unsigned* sync = (unsigned*)(buf + OFF_SYNC);

    uint32_t aSt = (uint32_t)((tg >> 1) * PAD + (tg & 1) * 16) * 2;
    uint32_t bSt = (uint32_t)(tg * PAD) * 2;
    uint32_t aLd = (uint32_t)((lane & 15) * PAD + ((lane >> 4) << 3)) * 2;
    uint32_t bLd = (uint32_t)(((lane & 7) + ((lane & 16) >> 1)) * PAD + (lane & 8)) * 2;

    const float* Ag = rbuf + (size_t)(m0 + (tg >> 1)) * H_ + kst + g * KH + (tg & 1) * 16;

    float wvr[16];
#pragma unroll
    for (int k = 0; k < 16; k++) wvr[k] = __ldg(wv + lane + 32 * k);

    int pA = blk * 2, pB = blk * 2 + 1;
    int aA = pA >> 7, bA = pA & 127;
    int aB = pB >> 7, bB = pB & 127;
    int sl2A = aA ? s1[bA] : s2[bA];
    int sl2B = aB ? s1[bB] : s2[bB];
    int slmA = aA ? s2[bA] : s1[bA];
    int slmB = aB ? s2[bB] : s1[bB];

    for (int t = 0; t < T_; t++) {
        // ---- phase G: uPt4[ks] = rbuf(kslice) @ Wc ----
        {
            float acc[4][4][4] = {};
            gemm_k(Ag, Bhg, Blg, KH / KC, smem_raw, sb, gofs, aSt, bSt, aLd, bLd, wg, acc);
            splitk_reduce(red, wid, lane, g, acc);
            float* Cb = uPt4 + (size_t)ks * 256 * 1024;
#pragma unroll
            for (int mtl = 0; mtl < 2; mtl++) {
                int mt = g ? (2 + mtl) : mtl;
                int rr = m0 + mt * 16 + (lane >> 2);
#pragma unroll
                for (int nt = 0; nt < 4; nt++) {
                    int c = n0 + wg * 32 + nt * 8 + (lane & 3) * 2;
                    *(float2*)(Cb + (size_t)rr * 1024 + c) =
                        make_float2(acc[mt][nt][0], acc[mt][nt][1]);
                    *(float2*)(Cb + (size_t)(rr + 8) * 1024 + c) =
                        make_float2(acc[mt][nt][2], acc[mt][nt][3]);
                }
            }
        }
        gbar(sync + 2, sync + 3, (unsigned)(2 * t + 1), 128u);

        // ---- phase A: two (a,b) pairs with exact skipping, 8 warps ----
        for (int pi = 0; pi < 2; pi++) {
            int p    = pi ? pB : pA;
            int a    = pi ? aB : aA;
            int b    = pi ? bB : bA;
            int sl2  = pi ? sl2B : sl2A;
            int slm  = pi ? slmB : slmA;
            if (t >= sl2) continue;

            float* su  = smf;
            float* spt = smf + 512;
            float* sc  = smf + 1024;
            const float* hb = HWy + (size_t)a * B_ * T_ * H_ + ((size_t)b * T_ + t) * H_;
#pragma unroll
            for (int q = 0; q < 2; q++) {
                int h = tid + q * 256;
                float s0 = 0.f, s1v = 0.f;
#pragma unroll
                for (int k = 0; k < 4; k++) {
                    const float* up = uPt4 + ((size_t)k * 256 + p) * 1024;
                    s0  += __ldcg(up + h);
                    s1v += __ldcg(up + 512 + h);
                }
                su[h]  = s0 + __ldg(hb + h);
                spt[h] = s1v;
            }
            __syncthreads();
            const float* WyYb = WyY + (size_t)a * B_ * T_ * H_ + (size_t)b * T_ * H_;
#pragma unroll
            for (int q = 0; q < 8; q++) {
                int t2 = wid * 8 + q;
                if (t2 < slm) {
                    const float* row = WyYb + (size_t)t2 * H_;
                    float s = 0.f;
#pragma unroll
                    for (int k = 0; k < 16; k++) {
                        int hh = lane + 32 * k;
                        s += tanha(__ldg(row + hh) + su[hh]) * wvr[k];
                    }
                    for (int o = 16; o; o >>= 1) s += __shfl_xor_sync(0xffffffffu, s, o);
                    if (lane == 0) sc[t2] = s;
                } else if (lane == 0) {
                    sc[t2] = -10000.f;
                }
            }
            __syncthreads();
            if (wid == 0) {
                float v1 = sc[lane], v2 = sc[lane + 32];
                float m = fmaxf(v1, v2);
                for (int o = 16; o; o >>= 1) m = fmaxf(m, __shfl_xor_sync(0xffffffffu, m, o));
                float e1 = __expf(v1 - m), e2 = __expf(v2 - m);
                float s = e1 + e2;
                for (int o = 16; o; o >>= 1) s += __shfl_xor_sync(0xffffffffu, s, o);
                float inv = __fdividef(1.f, s);
                sc[lane] = e1 * inv;
                sc[lane + 32] = e2 * inv;
            }
            __syncthreads();
            const float* Yp = Yb + (size_t)(a ? 2 : 0) * B_ * T_ * H_ + (size_t)b * T_ * H_;
#pragma unroll
            for (int q = 0; q < 2; q++) {
                int h = tid + q * 256;
                float accv = 0.f;
                for (int t2 = 0; t2 < slm; t2++)
                    accv += sc[t2] * __ldg(Yp + (size_t)t2 * H_ + h);
                float rn = accv + ftanh(spt[h]);
                if (t == sl2 - 1) rL[(size_t)p * H_ + h] = rn;
                else              rbuf[(size_t)p * H_ + h] = rn;
            }
            __syncthreads();
        }
        gbar(sync + 2, sync + 3, (unsigned)(2 * t + 2), 128u);
    }
}

// ---------------- final projection ----------------
__global__ void __launch_bounds__(512) k_final(
    const float* __restrict__ rL, const float* __restrict__ hfin,
    const float* __restrict__ Wp, const float* __restrict__ Wx,
    const float* __restrict__ U, const float* __restrict__ bU,
    float* __restrict__ out) {
    int b = blockIdx.x;
    int tid = threadIdx.x;
    __shared__ float s_in[4][512];
    __shared__ float s_sum[512];
    __shared__ float red0[16], red1[16];
    s_in[0][tid] = rL[(size_t)b * H_ + tid];
    s_in[1][tid] = hfin[((size_t)1 * B_ + b) * H_ + tid];
    s_in[2][tid] = rL[((size_t)B_ + b) * H_ + tid];
    s_in[3][tid] = hfin[((size_t)3 * B_ + b) * H_ + tid];
    __syncthreads();
    float acc0 = 0.f, acc1 = 0.f;
    for (int k = 0; k < H_; k++) {
        float wp = Wp[(size_t)k * H_ + tid];
        float wx = Wx[(size_t)k * H_ + tid];
        acc0 += s_in[0][k] * wp + s_in[1][k] * wx;
        acc1 += s_in[2][k] * wp + s_in[3][k] * wx;
    }
    s_sum[tid] = ftanh(acc0) + ftanh(acc1);
    __syncthreads();
    float p0 = s_sum[tid] * U[(size_t)tid * 2 + 0];
    float p1 = s_sum[tid] * U[(size_t)tid * 2 + 1];
    for (int o = 16; o; o >>= 1) {
        p0 += __shfl_xor_sync(0xffffffffu, p0, o);
        p1 += __shfl_xor_sync(0xffffffffu, p1, o);
    }
    int wp_ = tid >> 5;
    if ((tid & 31) == 0) { red0[wp_] = p0; red1[wp_] = p1; }
    __syncthreads();
    if (tid < 16) {
        p0 = red0[tid]; p1 = red1[tid];
        for (int o = 8; o; o >>= 1) {
            p0 += __shfl_xor_sync(0x0000ffffu, p0, o);
            p1 += __shfl_xor_sync(0x0000ffffu, p1, o);
        }
        if (tid == 0) {
            out[b * 2 + 0] = p0 + bU[0];
            out[b * 2 + 1] = p1 + bU[1];
        }
    }
}

// ---------------- host ----------------
extern "C" void kernel_launch(void* const* d_in, const int* in_sizes, int n_in,
                              void* d_out, int out_size) {
    (void)in_sizes; (void)n_in; (void)out_size;
    const int*   tokens1 = (const int*)d_in[0];
    const int*   tokens2 = (const int*)d_in[1];
    const int*   seqlen1 = (const int*)d_in[2];
    const int*   seqlen2 = (const int*)d_in[3];
    const float* emb = (const float*)d_in[4];
    const float* W1  = (const float*)d_in[5];
    const float* b1  = (const float*)d_in[6];
    const float* W2  = (const float*)d_in[7];
    const float* b2  = (const float*)d_in[8];
    const float* Wy  = (const float*)d_in[9];
    const float* Wh  = (const float*)d_in[10];
    const float* Wr  = (const float*)d_in[11];
    const float* wv  = (const float*)d_in[12];
    const float* Wt  = (const float*)d_in[13];
    const float* Wp  = (const float*)d_in[14];
    const float* Wx  = (const float*)d_in[15];
    const float* U   = (const float*)d_in[16];
    const float* bU  = (const float*)d_in[17];
    float* out = (float*)d_out;

    cudaFuncSetAttribute(mm_gemm, cudaFuncAttributeMaxDynamicSharedMemorySize, SMEM_MM);
    cudaFuncSetAttribute(k_lstm_persist, cudaFuncAttributeMaxDynamicSharedMemorySize, SMEM_PST);
    cudaFuncSetAttribute(k_att_persist, cudaFuncAttributeMaxDynamicSharedMemorySize, SMEM_PST);

    float* buf = nullptr;
    cudaGetSymbolAddress((void**)&buf, d_buf);
    float* e    = buf + OFF_E;
    float* Xg   = buf + OFF_XG;
    float* Yb   = buf + OFF_Y;
    float* hBuf = buf + OFF_H;
    float* WyY  = buf + OFF_WYY;
    float* HWy  = buf + OFF_HWY;
    float* rL   = buf + OFF_RL;
    float* bP   = buf + OFF_BP;
    __nv_bfloat16* WxS = (__nv_bfloat16*)(buf + OFF_WXS);
    __nv_bfloat16* WyS = (__nv_bfloat16*)(buf + OFF_WYS);
    __nv_bfloat16* WhA = (__nv_bfloat16*)(buf + OFF_WHA);

    k_prep<<<1024, 256>>>(W1, W2, Wy, Wh, Wr, Wt, b1, b2);
    k_gather<<<2048, 256>>>(e, tokens1, tokens2, emb);

    const int iidx[4] = {0, 1, 1, 0}, widx[4] = {0, 1, 0, 1};

    // launch #3: X-part GEMM
    {
        MP p = {};
        for (int r = 0; r < 4; r++) {
            p.z[r].A    = e + (size_t)iidx[r] * B_ * T_ * KPX;
            p.z[r].Bhi  = WxS + (size_t)(widx[r] * 2 + 0) * G4_ * KPX;
            p.z[r].Blo  = WxS + (size_t)(widx[r] * 2 + 1) * G4_ * KPX;
            p.z[r].C    = Xg + (size_t)r * B_ * T_ * G4_;
            p.z[r].bias = bP + (size_t)widx[r] * G4_;
        }
        p.Klen = KPX; p.lda = KPX; p.ldb = KPX; p.ldc = G4_;
        mm_gemm<<<dim3(G4_ / TN, (B_ * T_) / TM, 4), 128, SMEM_MM>>>(p);
    }

    // launch #4 (ncu target): persistent LSTM scan, 256 thr split-K
    k_lstm_persist<<<128, 256, SMEM_PST>>>(seqlen1, seqlen2);

    // launch #5: WyY + HWy
    {
        MP p = {};
        const int runs[4] = {0, 2, 1, 3};
        for (int q = 0; q < 4; q++) {
            p.z[q].A   = Yb + (size_t)runs[q] * B_ * T_ * H_;
            p.z[q].Bhi = (q < 2 ? WyS : WhA);
            p.z[q].Blo = (q < 2 ? WyS : WhA) + (size_t)H_ * H_;
            p.z[q].C   = (q < 2 ? WyY + (size_t)q * B_ * T_ * H_
                                : HWy + (size_t)(q - 2) * B_ * T_ * H_);
            p.z[q].bias = nullptr;
        }
        p.Klen = H_; p.lda = H_; p.ldb = H_; p.ldc = H_;
        mm_gemm<<<dim3(H_ / TN, (B_ * T_) / TM, 4), 128, SMEM_MM>>>(p);
    }

    // launch #6: persistent attention scan, 256 thr split-K
    k_att_persist<<<128, 256, SMEM_PST>>>(wv, seqlen1, seqlen2);

    k_final<<<B_, 512>>>(rL, hBuf, Wp, Wx, U, bU, out);
}

// round 9
// speedup vs baseline: 1.0519x; 1.0367x over previous
#include <cuda_runtime.h>
#include <cuda_bf16.h>
#include <math.h>
#include <stdint.h>

#define B_   128
#define T_   64
#define D_   300
#define KPX  320
#define H_   512
#define G4_  2048

// ---- bulk GEMM tile (R6 engine) ----
#define TM 64
#define TN 128
#define KC 32
#define PAD 40
#define A_BASE(term,stage) ((uint32_t)(((term)*2+(stage))*5120))
#define B_BASE(term,stage) ((uint32_t)(20480u + ((term)*2+(stage))*10240u))
static constexpr int SMEM_MM = 61440;

// ---- persistent LSTM smem ----  B slab 2x66560, A 3 stages x 20480
static constexpr int SMEM_LSTM = 133120 + 3 * 20480;   // 194560
// ---- persistent ATT smem ----   B slab 2x34816, A 3 stages x 10240
static constexpr int SMEM_ATT  = 69632 + 3 * 10240;    // 100352

__device__ __forceinline__ uint32_t smem_u32(const void* p) {
    uint32_t a;
    asm("{ .reg .u64 t; cvta.to.shared.u64 t, %1; cvt.u32.u64 %0, t; }" : "=r"(a) : "l"(p));
    return a;
}
#define CP_ASYNC16(dst, src) \
    asm volatile("cp.async.cg.shared.global [%0], [%1], 16;" :: "r"(dst), "l"(src))
#define CP_COMMIT() asm volatile("cp.async.commit_group;" ::: "memory")
#define CP_WAIT0()  asm volatile("cp.async.wait_group 0;" ::: "memory")
#define CP_WAIT1()  asm volatile("cp.async.wait_group 1;" ::: "memory")
#define LDSM4(r0, r1, r2, r3, addr) \
    asm volatile("ldmatrix.sync.aligned.m8n8.x4.shared.b16 {%0,%1,%2,%3}, [%4];" \
                 : "=r"(r0), "=r"(r1), "=r"(r2), "=r"(r3) : "r"(addr))
#define MMA16816(c, a, b0, b1) \
    asm volatile("mma.sync.aligned.m16n8k16.row.col.f32.bf16.bf16.f32 " \
                 "{%0,%1,%2,%3}, {%4,%5,%6,%7}, {%8,%9}, {%0,%1,%2,%3};" \
                 : "+f"((c)[0]), "+f"((c)[1]), "+f"((c)[2]), "+f"((c)[3]) \
                 : "r"((a)[0]), "r"((a)[1]), "r"((a)[2]), "r"((a)[3]), \
                   "r"(b0), "r"(b1))

__device__ __forceinline__ float sigf(float x) { return __fdividef(1.f, 1.f + __expf(-x)); }
__device__ __forceinline__ float ftanh(float x) { return 1.f - __fdividef(2.f, __expf(2.f * x) + 1.f); }
__device__ __forceinline__ float tanha(float x) {
    float y; asm("tanh.approx.f32 %0, %1;" : "=f"(y) : "f"(x)); return y;
}

// bf16 plane sizes (element counts)
static constexpr size_t P_HB = 4ull * B_ * H_;    // h term-plane
static constexpr size_t P_RB = 256ull * H_;       // r term-plane

// ---------------- scratch layout (float units) ----------------
static constexpr size_t OFF_E    = 0;
static constexpr size_t OFF_XG   = OFF_E   + 2ull * B_ * T_ * KPX;
static constexpr size_t OFF_Y    = OFF_XG  + 4ull * B_ * T_ * G4_;
static constexpr size_t OFF_H    = OFF_Y   + 4ull * B_ * T_ * H_;          // fp32 h ping-pong
static constexpr size_t OFF_HB   = OFF_H   + 2ull * 4 * B_ * H_;           // bf16 [2pp][2term][P_HB]
static constexpr size_t OFF_C    = OFF_HB  + (2ull * 2 * P_HB) / 2;
static constexpr size_t OFF_WYY  = OFF_C   + 4ull * B_ * H_;
static constexpr size_t OFF_HWY  = OFF_WYY + 2ull * B_ * T_ * H_;
static constexpr size_t OFF_UPT  = OFF_HWY + 2ull * B_ * T_ * H_;          // [4ks][256][1024]
static constexpr size_t OFF_RB   = OFF_UPT + 4ull * 256 * 1024;            // bf16 [2term][P_RB]
static constexpr size_t OFF_RL   = OFF_RB  + (2ull * P_RB) / 2;
static constexpr size_t OFF_BP   = OFF_RL  + 256ull * H_;
static constexpr size_t OFF_WXS  = OFF_BP  + 2ull * G4_;
static constexpr size_t OFF_WHS  = OFF_WXS + (2ull * 2 * G4_ * KPX) / 2;
static constexpr size_t OFF_WYS  = OFF_WHS + (2ull * 2 * G4_ * H_) / 2;
static constexpr size_t OFF_WHA  = OFF_WYS + (2ull * H_ * H_) / 2;
static constexpr size_t OFF_WCS  = OFF_WHA + (2ull * H_ * H_) / 2;
static constexpr size_t OFF_SYNC = OFF_WCS + (2ull * 2 * H_ * H_) / 2;
static constexpr size_t TOTAL_F  = OFF_SYNC + 16;

__device__ __align__(256) float d_buf[TOTAL_F];

__device__ __forceinline__ void split_store(float v, __nv_bfloat16* hi, __nv_bfloat16* lo) {
    __nv_bfloat16 h = __float2bfloat16_rn(v);
    *hi = h;
    *lo = __float2bfloat16_rn(v - __bfloat162float(h));
}

// ---------------- grid barrier ----------------
__device__ __forceinline__ void gbar(unsigned* cnt, unsigned* rel,
                                     unsigned seq, unsigned ncta) {
    __syncthreads();
    if (threadIdx.x == 0) {
        unsigned old;
        asm volatile("fence.acq_rel.gpu;" ::: "memory");
        asm volatile("atom.relaxed.gpu.global.add.u32 %0, [%1], 1;"
                     : "=r"(old) : "l"(cnt) : "memory");
        if (old + 1u == ncta * seq) {
            asm volatile("st.release.gpu.global.u32 [%0], %1;"
                         :: "l"(rel), "r"(seq) : "memory");
        }
        unsigned v;
        do {
            asm volatile("ld.acquire.gpu.global.u32 %0, [%1];"
                         : "=r"(v) : "l"(rel) : "memory");
        } while (v < seq);
    }
    __syncthreads();
}

// ---------------- prep: weight splits + all zero-init ----------------
__global__ void k_prep(const float* __restrict__ W1, const float* __restrict__ W2,
                       const float* __restrict__ Wy, const float* __restrict__ Wh,
                       const float* __restrict__ Wr, const float* __restrict__ Wt,
                       const float* __restrict__ b1, const float* __restrict__ b2) {
    float* buf = d_buf;
    __nv_bfloat16* WxS = (__nv_bfloat16*)(buf + OFF_WXS);
    __nv_bfloat16* WhS = (__nv_bfloat16*)(buf + OFF_WHS);
    __nv_bfloat16* WyS = (__nv_bfloat16*)(buf + OFF_WYS);
    __nv_bfloat16* WhA = (__nv_bfloat16*)(buf + OFF_WHA);
    __nv_bfloat16* WcS = (__nv_bfloat16*)(buf + OFF_WCS);
    float* bP = buf + OFF_BP;

    const size_t R1 = 2ull * G4_ * KPX;
    const size_t R2 = 2ull * G4_ * H_;
    const size_t R3 = (size_t)H_ * H_;
    const size_t R4 = (size_t)H_ * H_;
    const size_t R5 = 2ull * H_ * H_;
    const size_t R6 = 2ull * G4_;
    const size_t R7 = OFF_WYY - OFF_H;      // fp32 h + bf16 h planes + c
    const size_t R8 = OFF_RL - OFF_RB;      // bf16 r planes
    const size_t R9 = 16;
    const size_t TOT = R1 + R2 + R3 + R4 + R5 + R6 + R7 + R8 + R9;
    size_t stride = (size_t)gridDim.x * blockDim.x;
    for (size_t id = (size_t)blockIdx.x * blockDim.x + threadIdx.x; id < TOT; id += stride) {
        size_t i = id;
        if (i < R1) {
            int w = (int)(i / ((size_t)G4_ * KPX));
            size_t rem = i % ((size_t)G4_ * KPX);
            int np = (int)(rem / KPX), k = (int)(rem % KPX);
            int col = (np & 3) * H_ + (np >> 2);
            const float* W = w ? W2 : W1;
            float v = (k < D_) ? W[(size_t)k * G4_ + col] : 0.f;
            size_t o = ((size_t)(w * 2) * G4_ + np) * KPX + k;
            split_store(v, WxS + o, WxS + o + (size_t)G4_ * KPX);
            continue;
        }
        i -= R1;
        if (i < R2) {
            int w = (int)(i / ((size_t)G4_ * H_));
            size_t rem = i % ((size_t)G4_ * H_);
            int np = (int)(rem / H_), k = (int)(rem % H_);
            int col = (np & 3) * H_ + (np >> 2);
            const float* W = w ? W2 : W1;
            float v = W[(size_t)(D_ + k) * G4_ + col];
            size_t o = ((size_t)(w * 2) * G4_ + np) * H_ + k;
            split_store(v, WhS + o, WhS + o + (size_t)G4_ * H_);
            continue;
        }
        i -= R2;
        if (i < R3) {
            int n = (int)(i / H_), k = (int)(i % H_);
            size_t o = (size_t)n * H_ + k;
            split_store(Wy[(size_t)k * H_ + n], WyS + o, WyS + o + (size_t)H_ * H_);
            continue;
        }
        i -= R3;
        if (i < R4) {
            int n = (int)(i / H_), k = (int)(i % H_);
            size_t o = (size_t)n * H_ + k;
            split_store(Wh[(size_t)k * H_ + n], WhA + o, WhA + o + (size_t)H_ * H_);
            continue;
        }
        i -= R4;
        if (i < R5) {
            int n = (int)(i / H_), k = (int)(i % H_);
            float v = (n < H_) ? Wr[(size_t)k * H_ + n] : Wt[(size_t)k * H_ + (n - H_)];
            size_t o = (size_t)n * H_ + k;
            split_store(v, WcS + o, WcS + o + 2ull * H_ * H_);
            continue;
        }
        i -= R5;
        if (i < R6) {
            int w = (int)(i / G4_), np = (int)(i % G4_);
            int col = (np & 3) * H_ + (np >> 2);
            bP[i] = (w ? b2 : b1)[col];
            continue;
        }
        i -= R6;
        if (i < R7) { (buf + OFF_H)[i] = 0.f; continue; }
        i -= R7;
        if (i < R8) { (buf + OFF_RB)[i] = 0.f; continue; }
        i -= R8;
        (buf + OFF_SYNC)[i] = 0.f;
    }
}

__global__ void k_gather(float* __restrict__ e, const int* __restrict__ t1,
                         const int* __restrict__ t2, const float* __restrict__ emb) {
    size_t total = 2ull * B_ * T_ * KPX;
    size_t stride = (size_t)gridDim.x * blockDim.x;
    for (size_t i = (size_t)blockIdx.x * blockDim.x + threadIdx.x; i < total; i += stride) {
        int which = (int)(i / ((size_t)B_ * T_ * KPX));
        size_t rem = i % ((size_t)B_ * T_ * KPX);
        int bt = (int)(rem / KPX), k = (int)(rem % KPX);
        int tok = (which ? t2 : t1)[bt];
        e[i] = (k < D_) ? emb[(size_t)tok * D_ + k] : 0.f;
    }
}

// ---------------------------------------------------------------------------
// R6 bulk GEMM engine (fp32 A, in-kernel split, double-buffered)
// ---------------------------------------------------------------------------
__device__ __forceinline__ void gemm_k(
    const float* __restrict__ Ag, const __nv_bfloat16* __restrict__ Bhg,
    const __nv_bfloat16* __restrict__ Blg, int nch,
    char* smem_raw, uint32_t sb,
    uint32_t aSt, uint32_t bSt, uint32_t aLd, uint32_t bLd,
    int wid, float acc[4][4][4]) {
    float fA[16];
    {
#pragma unroll
        for (int q = 0; q < 4; q++) {
            CP_ASYNC16(sb + B_BASE(0, 0) + bSt + q * 16, Bhg + q * 8);
            CP_ASYNC16(sb + B_BASE(1, 0) + bSt + q * 16, Blg + q * 8);
        }
        CP_COMMIT();
        const float4* s4 = (const float4*)Ag;
#pragma unroll
        for (int q = 0; q < 4; q++) {
            float4 v = __ldcg(s4 + q);
            fA[4 * q] = v.x; fA[4 * q + 1] = v.y; fA[4 * q + 2] = v.z; fA[4 * q + 3] = v.w;
        }
        ushort hi[16], lo[16];
#pragma unroll
        for (int q = 0; q < 16; q++) {
            __nv_bfloat16 hb = __float2bfloat16_rn(fA[q]);
            __nv_bfloat16 lb = __float2bfloat16_rn(fA[q] - __bfloat162float(hb));
            hi[q] = *(ushort*)&hb; lo[q] = *(ushort*)&lb;
        }
        *(uint4*)(smem_raw + A_BASE(0, 0) + aSt)      = *(uint4*)(hi);
        *(uint4*)(smem_raw + A_BASE(0, 0) + aSt + 16) = *(uint4*)(hi + 8);
        *(uint4*)(smem_raw + A_BASE(1, 0) + aSt)      = *(uint4*)(lo);
        *(uint4*)(smem_raw + A_BASE(1, 0) + aSt + 16) = *(uint4*)(lo + 8);
        CP_WAIT0();
        __syncthreads();
    }
    for (int ch = 0; ch < nch; ch++) {
        int s = ch & 1, ns = s ^ 1;
        bool more = (ch + 1) < nch;
        if (more) {
            const __nv_bfloat16* bh2 = Bhg + (ch + 1) * KC;
            const __nv_bfloat16* bl2 = Blg + (ch + 1) * KC;
#pragma unroll
            for (int q = 0; q < 4; q++) {
                CP_ASYNC16(sb + B_BASE(0, ns) + bSt + q * 16, bh2 + q * 8);
                CP_ASYNC16(sb + B_BASE(1, ns) + bSt + q * 16, bl2 + q * 8);
            }
            CP_COMMIT();
            const float4* s4 = (const float4*)(Ag + (ch + 1) * KC);
#pragma unroll
            for (int q = 0; q < 4; q++) {
                float4 v = __ldcg(s4 + q);
                fA[4 * q] = v.x; fA[4 * q + 1] = v.y; fA[4 * q + 2] = v.z; fA[4 * q + 3] = v.w;
            }
        }
#pragma unroll
        for (int h16 = 0; h16 < 2; h16++) {
            uint32_t kb = (uint32_t)h16 * 32;
            uint32_t bh[8], bl[8];
#pragma unroll
            for (int g2 = 0; g2 < 2; g2++) {
                uint32_t rowb = (uint32_t)((wid * 32 + g2 * 16) * PAD) * 2;
                LDSM4(bh[g2 * 4 + 0], bh[g2 * 4 + 1], bh[g2 * 4 + 2], bh[g2 * 4 + 3],
                      sb + B_BASE(0, s) + bLd + rowb + kb);
                LDSM4(bl[g2 * 4 + 0], bl[g2 * 4 + 1], bl[g2 * 4 + 2], bl[g2 * 4 + 3],
                      sb + B_BASE(1, s) + bLd + rowb + kb);
            }
#pragma unroll
            for (int mt = 0; mt < 4; mt++) {
                uint32_t ah[4], al[4];
                uint32_t rowa = (uint32_t)(mt * 16 * PAD) * 2;
                LDSM4(ah[0], ah[1], ah[2], ah[3], sb + A_BASE(0, s) + aLd + rowa + kb);
                LDSM4(al[0], al[1], al[2], al[3], sb + A_BASE(1, s) + aLd + rowa + kb);
#pragma unroll
                for (int nt = 0; nt < 4; nt++) {
                    int bi = (nt >> 1) * 4 + (nt & 1) * 2;
                    MMA16816(acc[mt][nt], ah, bh[bi], bh[bi + 1]);
                    MMA16816(acc[mt][nt], ah, bl[bi], bl[bi + 1]);
                    MMA16816(acc[mt][nt], al, bh[bi], bh[bi + 1]);
                }
            }
        }
        if (more) {
            ushort hi[16], lo[16];
#pragma unroll
            for (int q = 0; q < 16; q++) {
                __nv_bfloat16 hb = __float2bfloat16_rn(fA[q]);
                __nv_bfloat16 lb = __float2bfloat16_rn(fA[q] - __bfloat162float(hb));
                hi[q] = *(ushort*)&hb; lo[q] = *(ushort*)&lb;
            }
            *(uint4*)(smem_raw + A_BASE(0, ns) + aSt)      = *(uint4*)(hi);
            *(uint4*)(smem_raw + A_BASE(0, ns) + aSt + 16) = *(uint4*)(hi + 8);
            *(uint4*)(smem_raw + A_BASE(1, ns) + aSt)      = *(uint4*)(lo);
            *(uint4*)(smem_raw + A_BASE(1, ns) + aSt + 16) = *(uint4*)(lo + 8);
            CP_WAIT0();
        }
        __syncthreads();
    }
}

struct MZ {
    const float*         A;
    const __nv_bfloat16* Bhi;
    const __nv_bfloat16* Blo;
    float*               C;
    const float*         bias;
};
struct MP {
    MZ z[4];
    int Klen, lda, ldb, ldc;
};

__global__ void __launch_bounds__(128) mm_gemm(MP p) {
    extern __shared__ __align__(16) char smem_raw[];
    uint32_t sb = smem_u32(smem_raw);
    const MZ z = p.z[blockIdx.z];
    int tid = threadIdx.x, lane = tid & 31, wid = tid >> 5;
    int n0 = blockIdx.x * TN, m0 = blockIdx.y * TM;

    const float*         Ag  = z.A   + (size_t)(m0 + (tid >> 1)) * p.lda + (tid & 1) * 16;
    const __nv_bfloat16* Bhg = z.Bhi + (size_t)(n0 + tid) * p.ldb;
    const __nv_bfloat16* Blg = z.Blo + (size_t)(n0 + tid) * p.ldb;
    uint32_t aSt = (uint32_t)((tid >> 1) * PAD + (tid & 1) * 16) * 2;
    uint32_t bSt = (uint32_t)(tid * PAD) * 2;
    uint32_t aLd = (uint32_t)((lane & 15) * PAD + ((lane >> 4) << 3)) * 2;
    uint32_t bLd = (uint32_t)(((lane & 7) + ((lane & 16) >> 1)) * PAD + (lane & 8)) * 2;

    float acc[4][4][4] = {};
    gemm_k(Ag, Bhg, Blg, p.Klen / KC, smem_raw, sb, aSt, bSt, aLd, bLd, wid, acc);

#pragma unroll
    for (int mt = 0; mt < 4; mt++) {
        int r = m0 + mt * 16 + (lane >> 2);
#pragma unroll
        for (int nt = 0; nt < 4; nt++) {
            int c = n0 + wid * 32 + nt * 8 + (lane & 3) * 2;
            float b0 = 0.f, b1 = 0.f;
            if (z.bias) { b0 = z.bias[c]; b1 = z.bias[c + 1]; }
            *(float2*)(z.C + (size_t)r * p.ldc + c) =
                make_float2(acc[mt][nt][0] + b0, acc[mt][nt][1] + b1);
            *(float2*)(z.C + (size_t)(r + 8) * p.ldc + c) =
                make_float2(acc[mt][nt][2] + b0, acc[mt][nt][3] + b1);
        }
    }
}

// ---------------------------------------------------------------------------
// Persistent LSTM scan: TM=128(batch) x TN=64, Wh slab resident in smem.
// 128 CTAs = 4 runs x 32 n-tiles. 128 threads.
// smem: [term0 B 66560][term1 B 66560][A stages 3 x 20480]
// ---------------------------------------------------------------------------
__global__ void __launch_bounds__(128) k_lstm_persist(
    const int* __restrict__ s1, const int* __restrict__ s2) {
    extern __shared__ __align__(16) char smem[];
    uint32_t sb = smem_u32(smem);
    float* buf = d_buf;
    int tid = threadIdx.x, lane = tid & 31, wg = tid >> 5;
    int blk = blockIdx.x;
    int r = blk >> 5, nt_ = blk & 31;
    int n0 = nt_ * 64;
    int widx = (r == 0 || r == 2) ? 0 : 1;
    const int* sl = (r == 0 || r == 3) ? s1 : s2;

    // ---- one-time B slab preload: 64 rows x 512 K x 2 terms ----
    {
        const __nv_bfloat16* WhS = (const __nv_bfloat16*)(buf + OFF_WHS);
        int n = tid >> 1, half = tid & 1;
#pragma unroll
        for (int tau = 0; tau < 2; tau++) {
            const __nv_bfloat16* src = WhS + (size_t)(widx * 2 + tau) * G4_ * H_
                                       + (size_t)(n0 + n) * H_ + half * 256;
            uint32_t dst = sb + (uint32_t)tau * 66560u + (uint32_t)n * 1040u + (uint32_t)half * 512u;
#pragma unroll
            for (int q = 0; q < 32; q++) CP_ASYNC16(dst + q * 16, src + q * 8);
        }
        CP_COMMIT(); CP_WAIT0(); __syncthreads();
    }

    const float* Xg  = buf + OFF_XG + (size_t)r * B_ * T_ * G4_;
    float*       cst = buf + OFF_C + (size_t)r * B_ * H_;
    float*       Yst = buf + OFF_Y + (size_t)r * B_ * T_ * H_;
    float*       hB  = buf + OFF_H;
    __nv_bfloat16* HBb = (__nv_bfloat16*)(buf + OFF_HB);
    unsigned* sync = (unsigned*)(buf + OFF_SYNC);
    const size_t HBUF = 4ull * B_ * H_;

    uint32_t aLd   = (uint32_t)((lane & 15) * 40 + ((lane >> 4) << 3)) * 2;
    uint32_t bBase = (uint32_t)(wg * 16) * 1040u
                   + (uint32_t)(((lane & 7) + ((lane & 16) >> 1)) * 520 + (lane & 8)) * 2;

    for (int t = 0; t < T_; t++) {
        int ppi = t & 1, ppo = ppi ^ 1;
        const float* hin  = hB + (size_t)ppi * HBUF + (size_t)r * B_ * H_;
        float*       hout = hB + (size_t)ppo * HBUF + (size_t)r * B_ * H_;
        const __nv_bfloat16* Ain = HBb + (size_t)ppi * 2 * P_HB + (size_t)r * B_ * H_;
        __nv_bfloat16*       ho  = HBb + (size_t)ppo * 2 * P_HB + (size_t)r * B_ * H_;

        auto issueA = [&](int ch, int slot) {
#pragma unroll
            for (int tau = 0; tau < 2; tau++) {
                const __nv_bfloat16* src = Ain + (size_t)tau * P_HB + (size_t)tid * H_ + ch * 32;
                uint32_t dst = sb + 133120u + (uint32_t)slot * 20480u
                             + (uint32_t)tau * 10240u + (uint32_t)tid * 80u;
                CP_ASYNC16(dst,      src);
                CP_ASYNC16(dst + 16, src + 8);
                CP_ASYNC16(dst + 32, src + 16);
                CP_ASYNC16(dst + 48, src + 24);
            }
            CP_COMMIT();
        };
        issueA(0, 0); issueA(1, 1);

        float acc[8][2][4] = {};
        for (int ch = 0; ch < 16; ch++) {
            if (ch == 15) { CP_WAIT0(); } else { CP_WAIT1(); }
            __syncthreads();
            if (ch + 2 < 16) issueA(ch + 2, (ch + 2) % 3);
            uint32_t abase = sb + 133120u + (uint32_t)(ch % 3) * 20480u;
#pragma unroll
            for (int h16 = 0; h16 < 2; h16++) {
                uint32_t kb = (uint32_t)(ch * 32 + h16 * 16) * 2;
                uint32_t bA[4], bB[4];
                LDSM4(bA[0], bA[1], bA[2], bA[3], sb + bBase + kb);
                LDSM4(bB[0], bB[1], bB[2], bB[3], sb + 66560u + bBase + kb);
#pragma unroll
                for (int mt = 0; mt < 8; mt++) {
                    uint32_t ah[4], al[4];
                    uint32_t rowa = (uint32_t)(mt * 16 * 80);
                    LDSM4(ah[0], ah[1], ah[2], ah[3], abase + aLd + rowa + h16 * 32);
                    LDSM4(al[0], al[1], al[2], al[3], abase + 10240u + aLd + rowa + h16 * 32);
                    MMA16816(acc[mt][0], ah, bA[0], bA[1]);
                    MMA16816(acc[mt][0], ah, bB[0], bB[1]);
                    MMA16816(acc[mt][0], al, bA[0], bA[1]);
                    MMA16816(acc[mt][1], ah, bA[2], bA[3]);
                    MMA16816(acc[mt][1], ah, bB[2], bB[3]);
                    MMA16816(acc[mt][1], al, bA[2], bA[3]);
                }
            }
        }

        // fused cell epilogue (permuted gate cols n' = 4j+g)
#pragma unroll
        for (int mt = 0; mt < 8; mt++) {
            int b = mt * 16 + (lane >> 2);
#pragma unroll
            for (int nt = 0; nt < 2; nt++) {
                float fo0 = __shfl_xor_sync(0xffffffffu, acc[mt][nt][0], 1);
                float fo1 = __shfl_xor_sync(0xffffffffu, acc[mt][nt][1], 1);
                float fo2 = __shfl_xor_sync(0xffffffffu, acc[mt][nt][2], 1);
                float fo3 = __shfl_xor_sync(0xffffffffu, acc[mt][nt][3], 1);
                if (!(lane & 1)) {
#pragma unroll
                    for (int half = 0; half < 2; half++) {
                        int bb = b + half * 8;
                        float gi = half ? acc[mt][nt][2] : acc[mt][nt][0];
                        float gj = half ? acc[mt][nt][3] : acc[mt][nt][1];
                        float gf = half ? fo2 : fo0;
                        float go = half ? fo3 : fo1;
                        int c0 = n0 + wg * 16 + nt * 8 + (lane & 3) * 2;
                        int j = c0 >> 2;
                        float4 x = *(const float4*)(Xg + ((size_t)bb * T_ + t) * G4_ + c0);
                        gi += x.x; gj += x.y; gf += x.z; go += x.w;
                        size_t ci = (size_t)bb * H_ + j;
                        float hv, yv;
                        if (t < sl[bb]) {
                            float cc = cst[ci];
                            float cn = cc * sigf(gf + 1.f) + sigf(gi) * ftanh(gj);
                            hv = ftanh(cn) * sigf(go);
                            cst[ci] = cn;
                            yv = hv;
                        } else {
                            hv = __ldcg(hin + ci);
                            yv = 0.f;
                        }
                        hout[ci] = hv;
                        split_store(hv, ho + ci, ho + P_HB + ci);
                        Yst[((size_t)bb * T_ + t) * H_ + j] = yv;
                    }
                }
            }
        }
        gbar(sync + 0, sync + 1, (unsigned)(t + 1), 128u);
    }
}

// ---------------------------------------------------------------------------
// Persistent attention scan: Wc slab resident (TN=128, K-slice 128), 128 thr.
// smem: [term0 B 34816][term1 B 34816][A stages 3 x 10240 | phase-A arrays]
// ---------------------------------------------------------------------------
__global__ void __launch_bounds__(128) k_att_persist(
    const float* __restrict__ wv,
    const int* __restrict__ s1, const int* __restrict__ s2) {
    extern __shared__ __align__(16) char smem[];
    uint32_t sb = smem_u32(smem);
    float* smf = (float*)(smem + 69632);
    float* buf = d_buf;
    int tid = threadIdx.x, lane = tid & 31, wg = tid >> 5;
    int blk = blockIdx.x;

    int ks  = blk & 3;
    int mt_ = (blk >> 2) & 3;
    int nt_ = blk >> 4;
    int m0 = mt_ * 64, n0 = nt_ * 128, kst = ks * 128;

    // ---- one-time B slab preload: 128 rows x 128 K x 2 terms ----
    {
        const __nv_bfloat16* WcS = (const __nv_bfloat16*)(buf + OFF_WCS);
#pragma unroll
        for (int tau = 0; tau < 2; tau++) {
            const __nv_bfloat16* src = WcS + (size_t)tau * 2 * H_ * H_
                                       + (size_t)(n0 + tid) * H_ + kst;
            uint32_t dst = sb + (uint32_t)tau * 34816u + (uint32_t)tid * 272u;
#pragma unroll
            for (int q = 0; q < 16; q++) CP_ASYNC16(dst + q * 16, src + q * 8);
        }
        CP_COMMIT(); CP_WAIT0(); __syncthreads();
    }

    __nv_bfloat16* RBb = (__nv_bfloat16*)(buf + OFF_RB);
    float* uPt4 = buf + OFF_UPT;
    float* rL   = buf + OFF_RL;
    const float* WyY = buf + OFF_WYY;
    const float* HWy = buf + OFF_HWY;
    const float* Yb  = buf + OFF_Y;
    unsigned* sync = (unsigned*)(buf + OFF_SYNC);

    uint32_t aLd   = (uint32_t)((lane & 15) * 40 + ((lane >> 4) << 3)) * 2;
    uint32_t bLd   = (uint32_t)(((lane & 7) + ((lane & 16) >> 1)) * 136 + (lane & 8)) * 2;

    float wvr[16];
#pragma unroll
    for (int k = 0; k < 16; k++) wvr[k] = __ldg(wv + lane + 32 * k);

    int pA = blk * 2, pB = blk * 2 + 1;
    int aA = pA >> 7, bA = pA & 127;
    int aB = pB >> 7, bB = pB & 127;
    int sl2A = aA ? s1[bA] : s2[bA];
    int sl2B = aB ? s1[bB] : s2[bB];
    int slmA = aA ? s2[bA] : s1[bA];
    int slmB = aB ? s2[bB] : s1[bB];

    for (int t = 0; t < T_; t++) {
        // ---- phase G: uPt4[ks] = r(kslice) @ Wc (B resident) ----
        {
            auto issueA = [&](int ch, int slot) {
                int row = tid >> 1, tau = tid & 1;
                const __nv_bfloat16* src = RBb + (size_t)tau * P_RB
                                           + (size_t)(m0 + row) * H_ + kst + ch * 32;
                uint32_t dst = sb + 69632u + (uint32_t)slot * 10240u
                             + (uint32_t)tau * 5120u + (uint32_t)row * 80u;
                CP_ASYNC16(dst,      src);
                CP_ASYNC16(dst + 16, src + 8);
                CP_ASYNC16(dst + 32, src + 16);
                CP_ASYNC16(dst + 48, src + 24);
                CP_COMMIT();
            };
            issueA(0, 0); issueA(1, 1);
            float acc[4][4][4] = {};
            for (int ch = 0; ch < 4; ch++) {
                if (ch == 3) { CP_WAIT0(); } else { CP_WAIT1(); }
                __syncthreads();
                if (ch + 2 < 4) issueA(ch + 2, (ch + 2) % 3);
                uint32_t abase = sb + 69632u + (uint32_t)(ch % 3) * 10240u;
#pragma unroll
                for (int h16 = 0; h16 < 2; h16++) {
                    uint32_t kb = (uint32_t)(ch * 32 + h16 * 16) * 2;
                    uint32_t bh[8], bl[8];
#pragma unroll
                    for (int g2 = 0; g2 < 2; g2++) {
                        uint32_t rowb = (uint32_t)((wg * 32 + g2 * 16) * 136) * 2;
                        LDSM4(bh[g2 * 4 + 0], bh[g2 * 4 + 1], bh[g2 * 4 + 2], bh[g2 * 4 + 3],
                              sb + bLd + rowb + kb);
                        LDSM4(bl[g2 * 4 + 0], bl[g2 * 4 + 1], bl[g2 * 4 + 2], bl[g2 * 4 + 3],
                              sb + 34816u + bLd + rowb + kb);
                    }
#pragma unroll
                    for (int mt = 0; mt < 4; mt++) {
                        uint32_t ah[4], al[4];
                        uint32_t rowa = (uint32_t)(mt * 16 * 80);
                        LDSM4(ah[0], ah[1], ah[2], ah[3], abase + aLd + rowa + h16 * 32);
                        LDSM4(al[0], al[1], al[2], al[3], abase + 5120u + aLd + rowa + h16 * 32);
#pragma unroll
                        for (int nt = 0; nt < 4; nt++) {
                            int bi = (nt >> 1) * 4 + (nt & 1) * 2;
                            MMA16816(acc[mt][nt], ah, bh[bi], bh[bi + 1]);
                            MMA16816(acc[mt][nt], ah, bl[bi], bl[bi + 1]);
                            MMA16816(acc[mt][nt], al, bh[bi], bh[bi + 1]);
                        }
                    }
                }
            }
            float* Cb = uPt4 + (size_t)ks * 256 * 1024;
#pragma unroll
            for (int mt = 0; mt < 4; mt++) {
                int rr = m0 + mt * 16 + (lane >> 2);
#pragma unroll
                for (int nt = 0; nt < 4; nt++) {
                    int c = n0 + wg * 32 + nt * 8 + (lane & 3) * 2;
                    *(float2*)(Cb + (size_t)rr * 1024 + c) =
                        make_float2(acc[mt][nt][0], acc[mt][nt][1]);
                    *(float2*)(Cb + (size_t)(rr + 8) * 1024 + c) =
                        make_float2(acc[mt][nt][2], acc[mt][nt][3]);
                }
            }
        }
        gbar(sync + 2, sync + 3, (unsigned)(2 * t + 1), 128u);

        // ---- phase A: two (a,b) pairs with exact skipping ----
        for (int pi = 0; pi < 2; pi++) {
            int p    = pi ? pB : pA;
            int a    = pi ? aB : aA;
            int b    = pi ? bB : bA;
            int sl2  = pi ? sl2B : sl2A;
            int slm  = pi ? slmB : slmA;
            if (t >= sl2) continue;

            float* su  = smf;
            float* spt = smf + 512;
            float* sc  = smf + 1024;
            const float* hb = HWy + (size_t)a * B_ * T_ * H_ + ((size_t)b * T_ + t) * H_;
#pragma unroll
            for (int q = 0; q < 4; q++) {
                int h = tid + q * 128;
                float s0 = 0.f, s1v = 0.f;
#pragma unroll
                for (int k = 0; k < 4; k++) {
                    const float* up = uPt4 + ((size_t)k * 256 + p) * 1024;
                    s0  += __ldcg(up + h);
                    s1v += __ldcg(up + 512 + h);
                }
                su[h]  = s0 + __ldg(hb + h);
                spt[h] = s1v;
            }
            __syncthreads();
            const float* WyYb = WyY + (size_t)a * B_ * T_ * H_ + (size_t)b * T_ * H_;
#pragma unroll
            for (int q = 0; q < 16; q++) {
                int t2 = wg * 16 + q;
                if (t2 < slm) {
                    const float* row = WyYb + (size_t)t2 * H_;
                    float s = 0.f;
#pragma unroll
                    for (int k = 0; k < 16; k++) {
                        int hh = lane + 32 * k;
                        s += tanha(__ldg(row + hh) + su[hh]) * wvr[k];
                    }
                    for (int o = 16; o; o >>= 1) s += __shfl_xor_sync(0xffffffffu, s, o);
                    if (lane == 0) sc[t2] = s;
                } else if (lane == 0) {
                    sc[t2] = -10000.f;
                }
            }
            __syncthreads();
            if (wg == 0) {
                float v1 = sc[lane], v2 = sc[lane + 32];
                float m = fmaxf(v1, v2);
                for (int o = 16; o; o >>= 1) m = fmaxf(m, __shfl_xor_sync(0xffffffffu, m, o));
                float e1 = __expf(v1 - m), e2 = __expf(v2 - m);
                float s = e1 + e2;
                for (int o = 16; o; o >>= 1) s += __shfl_xor_sync(0xffffffffu, s, o);
                float inv = __fdividef(1.f, s);
                sc[lane] = e1 * inv;
                sc[lane + 32] = e2 * inv;
            }
            __syncthreads();
            const float* Yp = Yb + (size_t)(a ? 2 : 0) * B_ * T_ * H_ + (size_t)b * T_ * H_;
#pragma unroll
            for (int q = 0; q < 4; q++) {
                int h = tid + q * 128;
                float accv = 0.f;
                for (int t2 = 0; t2 < slm; t2++)
                    accv += sc[t2] * __ldg(Yp + (size_t)t2 * H_ + h);
                float rn = accv + ftanh(spt[h]);
                if (t == sl2 - 1) {
                    rL[(size_t)p * H_ + h] = rn;
                } else {
                    split_store(rn, RBb + (size_t)p * H_ + h, RBb + P_RB + (size_t)p * H_ + h);
                }
            }
            __syncthreads();
        }
        gbar(sync + 2, sync + 3, (unsigned)(2 * t + 2), 128u);
    }
}

// ---------------- final projection ----------------
__global__ void __launch_bounds__(512) k_final(
    const float* __restrict__ rL, const float* __restrict__ hfin,
    const float* __restrict__ Wp, const float* __restrict__ Wx,
    const float* __restrict__ U, const float* __restrict__ bU,
    float* __restrict__ out) {
    int b = blockIdx.x;
    int tid = threadIdx.x;
    __shared__ float s_in[4][512];
    __shared__ float s_sum[512];
    __shared__ float red0[16], red1[16];
    s_in[0][tid] = rL[(size_t)b * H_ + tid];
    s_in[1][tid] = hfin[((size_t)1 * B_ + b) * H_ + tid];
    s_in[2][tid] = rL[((size_t)B_ + b) * H_ + tid];
    s_in[3][tid] = hfin[((size_t)3 * B_ + b) * H_ + tid];
    __syncthreads();
    float acc0 = 0.f, acc1 = 0.f;
    for (int k = 0; k < H_; k++) {
        float wp = Wp[(size_t)k * H_ + tid];
        float wx = Wx[(size_t)k * H_ + tid];
        acc0 += s_in[0][k] * wp + s_in[1][k] * wx;
        acc1 += s_in[2][k] * wp + s_in[3][k] * wx;
    }
    s_sum[tid] = ftanh(acc0) + ftanh(acc1);
    __syncthreads();
    float p0 = s_sum[tid] * U[(size_t)tid * 2 + 0];
    float p1 = s_sum[tid] * U[(size_t)tid * 2 + 1];
    for (int o = 16; o; o >>= 1) {
        p0 += __shfl_xor_sync(0xffffffffu, p0, o);
        p1 += __shfl_xor_sync(0xffffffffu, p1, o);
    }
    int wp_ = tid >> 5;
    if ((tid & 31) == 0) { red0[wp_] = p0; red1[wp_] = p1; }
    __syncthreads();
    if (tid < 16) {
        p0 = red0[tid]; p1 = red1[tid];
        for (int o = 8; o; o >>= 1) {
            p0 += __shfl_xor_sync(0x0000ffffu, p0, o);
            p1 += __shfl_xor_sync(0x0000ffffu, p1, o);
        }
        if (tid == 0) {
            out[b * 2 + 0] = p0 + bU[0];
            out[b * 2 + 1] = p1 + bU[1];
        }
    }
}

// ---------------- host ----------------
extern "C" void kernel_launch(void* const* d_in, const int* in_sizes, int n_in,
                              void* d_out, int out_size) {
    (void)in_sizes; (void)n_in; (void)out_size;
    const int*   tokens1 = (const int*)d_in[0];
    const int*   tokens2 = (const int*)d_in[1];
    const int*   seqlen1 = (const int*)d_in[2];
    const int*   seqlen2 = (const int*)d_in[3];
    const float* emb = (const float*)d_in[4];
    const float* W1  = (const float*)d_in[5];
    const float* b1  = (const float*)d_in[6];
    const float* W2  = (const float*)d_in[7];
    const float* b2  = (const float*)d_in[8];
    const float* Wy  = (const float*)d_in[9];
    const float* Wh  = (const float*)d_in[10];
    const float* Wr  = (const float*)d_in[11];
    const float* wv  = (const float*)d_in[12];
    const float* Wt  = (const float*)d_in[13];
    const float* Wp  = (const float*)d_in[14];
    const float* Wx  = (const float*)d_in[15];
    const float* U   = (const float*)d_in[16];
    const float* bU  = (const float*)d_in[17];
    float* out = (float*)d_out;

    cudaFuncSetAttribute(mm_gemm, cudaFuncAttributeMaxDynamicSharedMemorySize, SMEM_MM);
    cudaFuncSetAttribute(k_lstm_persist, cudaFuncAttributeMaxDynamicSharedMemorySize, SMEM_LSTM);
    cudaFuncSetAttribute(k_att_persist, cudaFuncAttributeMaxDynamicSharedMemorySize, SMEM_ATT);

    float* buf = nullptr;
    cudaGetSymbolAddress((void**)&buf, d_buf);
    float* e    = buf + OFF_E;
    float* Xg   = buf + OFF_XG;
    float* Yb   = buf + OFF_Y;
    float* hBuf = buf + OFF_H;
    float* WyY  = buf + OFF_WYY;
    float* HWy  = buf + OFF_HWY;
    float* rL   = buf + OFF_RL;
    float* bP   = buf + OFF_BP;
    __nv_bfloat16* WxS = (__nv_bfloat16*)(buf + OFF_WXS);
    __nv_bfloat16* WyS = (__nv_bfloat16*)(buf + OFF_WYS);
    __nv_bfloat16* WhA = (__nv_bfloat16*)(buf + OFF_WHA);

    k_prep<<<1024, 256>>>(W1, W2, Wy, Wh, Wr, Wt, b1, b2);
    k_gather<<<2048, 256>>>(e, tokens1, tokens2, emb);

    const int iidx[4] = {0, 1, 1, 0}, widx[4] = {0, 1, 0, 1};

    // launch #3: X-part GEMM
    {
        MP p = {};
        for (int r = 0; r < 4; r++) {
            p.z[r].A    = e + (size_t)iidx[r] * B_ * T_ * KPX;
            p.z[r].Bhi  = WxS + (size_t)(widx[r] * 2 + 0) * G4_ * KPX;
            p.z[r].Blo  = WxS + (size_t)(widx[r] * 2 + 1) * G4_ * KPX;
            p.z[r].C    = Xg + (size_t)r * B_ * T_ * G4_;
            p.z[r].bias = bP + (size_t)widx[r] * G4_;
        }
        p.Klen = KPX; p.lda = KPX; p.ldb = KPX; p.ldc = G4_;
        mm_gemm<<<dim3(G4_ / TN, (B_ * T_) / TM, 4), 128, SMEM_MM>>>(p);
    }

    // launch #4 (ncu target): persistent LSTM scan (weights resident)
    k_lstm_persist<<<128, 128, SMEM_LSTM>>>(seqlen1, seqlen2);

    // launch #5: WyY + HWy
    {
        MP p = {};
        const int runs[4] = {0, 2, 1, 3};
        for (int q = 0; q < 4; q++) {
            p.z[q].A   = Yb + (size_t)runs[q] * B_ * T_ * H_;
            p.z[q].Bhi = (q < 2 ? WyS : WhA);
            p.z[q].Blo = (q < 2 ? WyS : WhA) + (size_t)H_ * H_;
            p.z[q].C   = (q < 2 ? WyY + (size_t)q * B_ * T_ * H_
                                : HWy + (size_t)(q - 2) * B_ * T_ * H_);
            p.z[q].bias = nullptr;
        }
        p.Klen = H_; p.lda = H_; p.ldb = H_; p.ldc = H_;
        mm_gemm<<<dim3(H_ / TN, (B_ * T_) / TM, 4), 128, SMEM_MM>>>(p);
    }

    // launch #6: persistent attention scan (weights resident)
    k_att_persist<<<128, 128, SMEM_ATT>>>(wv, seqlen1, seqlen2);

    k_final<<<B_, 512>>>(rL, hBuf, Wp, Wx, U, bU, out);
}

// round 10
// speedup vs baseline: 1.2542x; 1.1923x over previous
#include <cuda_runtime.h>
#include <cuda_bf16.h>
#include <math.h>
#include <stdint.h>

#define B_   128
#define T_   64
#define D_   300
#define KPX  320
#define H_   512
#define G4_  2048

// ---- bulk GEMM tile ----
#define TM 64
#define TN 128
#define KC 32
#define PAD 40
#define A_BASE(term,stage) ((uint32_t)(((term)*2+(stage))*5120))
#define B_BASE(term,stage) ((uint32_t)(20480u + ((term)*2+(stage))*10240u))
static constexpr int SMEM_MM   = 61440;
static constexpr int SMEM_LSTM = 133120 + 3 * 20480;   // 194560
static constexpr int SMEM_ATT  = 69632 + 3 * 10240;    // 100352

__device__ __forceinline__ uint32_t smem_u32(const void* p) {
    uint32_t a;
    asm("{ .reg .u64 t; cvta.to.shared.u64 t, %1; cvt.u32.u64 %0, t; }" : "=r"(a) : "l"(p));
    return a;
}
#define CP_ASYNC16(dst, src) \
    asm volatile("cp.async.cg.shared.global [%0], [%1], 16;" :: "r"(dst), "l"(src))
#define CP_COMMIT() asm volatile("cp.async.commit_group;" ::: "memory")
#define CP_WAIT0()  asm volatile("cp.async.wait_group 0;" ::: "memory")
#define CP_WAIT1()  asm volatile("cp.async.wait_group 1;" ::: "memory")
#define LDSM4(r0, r1, r2, r3, addr) \
    asm volatile("ldmatrix.sync.aligned.m8n8.x4.shared.b16 {%0,%1,%2,%3}, [%4];" \
                 : "=r"(r0), "=r"(r1), "=r"(r2), "=r"(r3) : "r"(addr))
#define MMA16816(c, a, b0, b1) \
    asm volatile("mma.sync.aligned.m16n8k16.row.col.f32.bf16.bf16.f32 " \
                 "{%0,%1,%2,%3}, {%4,%5,%6,%7}, {%8,%9}, {%0,%1,%2,%3};" \
                 : "+f"((c)[0]), "+f"((c)[1]), "+f"((c)[2]), "+f"((c)[3]) \
                 : "r"((a)[0]), "r"((a)[1]), "r"((a)[2]), "r"((a)[3]), \
                   "r"(b0), "r"(b1))

__device__ __forceinline__ float sigf(float x) { return __fdividef(1.f, 1.f + __expf(-x)); }
__device__ __forceinline__ float ftanh(float x) { return 1.f - __fdividef(2.f, __expf(2.f * x) + 1.f); }
__device__ __forceinline__ float tanha(float x) {
    float y; asm("tanh.approx.f32 %0, %1;" : "=f"(y) : "f"(x)); return y;
}

static constexpr size_t P_HB = 4ull * B_ * H_;
static constexpr size_t P_RB = 256ull * H_;

// ---------------- scratch layout (float units) ----------------
static constexpr size_t OFF_E    = 0;
static constexpr size_t OFF_XG   = OFF_E   + 2ull * B_ * T_ * KPX;
static constexpr size_t OFF_Y    = OFF_XG  + 4ull * B_ * T_ * G4_;
static constexpr size_t OFF_H    = OFF_Y   + 4ull * B_ * T_ * H_;
static constexpr size_t OFF_HB   = OFF_H   + 2ull * 4 * B_ * H_;
static constexpr size_t OFF_C    = OFF_HB  + (2ull * 2 * P_HB) / 2;
static constexpr size_t OFF_WYY  = OFF_C   + 4ull * B_ * H_;
static constexpr size_t OFF_HWY  = OFF_WYY + 2ull * B_ * T_ * H_;
static constexpr size_t OFF_UPT  = OFF_HWY + 2ull * B_ * T_ * H_;
static constexpr size_t OFF_RB   = OFF_UPT + 4ull * 256 * 1024;
static constexpr size_t OFF_RL   = OFF_RB  + (2ull * P_RB) / 2;
static constexpr size_t OFF_BP   = OFF_RL  + 256ull * H_;
static constexpr size_t OFF_WXS  = OFF_BP  + 2ull * G4_;
static constexpr size_t OFF_WHS  = OFF_WXS + (2ull * 2 * G4_ * KPX) / 2;
static constexpr size_t OFF_WYS  = OFF_WHS + (2ull * 2 * G4_ * H_) / 2;
static constexpr size_t OFF_WHA  = OFF_WYS + (2ull * H_ * H_) / 2;
static constexpr size_t OFF_WCS  = OFF_WHA + (2ull * H_ * H_) / 2;
static constexpr size_t OFF_META = OFF_WCS + (2ull * 2 * H_ * H_) / 2;
// meta (int units within meta block):
#define M_PERM0 0
#define M_PERM1 128
#define M_IPOS0 256
#define M_IPOS1 384
#define M_SLS0  512
#define M_SLS1  640
#define M_MCNT0 768
#define M_MCNT1 832
#define M_PERM2 896
#define M_MCNT2 1152
#define M_ROWL0 1216
#define M_ROWL1 9408
#define M_NACT  17600
#define M_SYNC  17608
static constexpr size_t META_N  = 17640;
static constexpr size_t TOTAL_F = OFF_META + META_N;

__device__ __align__(256) float d_buf[TOTAL_F];

__device__ __forceinline__ void split_store(float v, __nv_bfloat16* hi, __nv_bfloat16* lo) {
    __nv_bfloat16 h = __float2bfloat16_rn(v);
    *hi = h;
    *lo = __float2bfloat16_rn(v - __bfloat162float(h));
}

// ---------------- grid barrier ----------------
__device__ __forceinline__ void gbar(unsigned* cnt, unsigned* rel,
                                     unsigned seq, unsigned ncta) {
    __syncthreads();
    if (threadIdx.x == 0) {
        unsigned old;
        asm volatile("fence.acq_rel.gpu;" ::: "memory");
        asm volatile("atom.relaxed.gpu.global.add.u32 %0, [%1], 1;"
                     : "=r"(old) : "l"(cnt) : "memory");
        if (old + 1u == ncta * seq) {
            asm volatile("st.release.gpu.global.u32 [%0], %1;"
                         :: "l"(rel), "r"(seq) : "memory");
        }
        unsigned v;
        do {
            asm volatile("ld.acquire.gpu.global.u32 %0, [%1];"
                         : "=r"(v) : "l"(rel) : "memory");
        } while (v < seq);
    }
    __syncthreads();
}

// ---------------- prep: weight splits + zero-init (incl. Y) ----------------
__global__ void k_prep(const float* __restrict__ W1, const float* __restrict__ W2,
                       const float* __restrict__ Wy, const float* __restrict__ Wh,
                       const float* __restrict__ Wr, const float* __restrict__ Wt,
                       const float* __restrict__ b1, const float* __restrict__ b2) {
    float* buf = d_buf;
    __nv_bfloat16* WxS = (__nv_bfloat16*)(buf + OFF_WXS);
    __nv_bfloat16* WhS = (__nv_bfloat16*)(buf + OFF_WHS);
    __nv_bfloat16* WyS = (__nv_bfloat16*)(buf + OFF_WYS);
    __nv_bfloat16* WhA = (__nv_bfloat16*)(buf + OFF_WHA);
    __nv_bfloat16* WcS = (__nv_bfloat16*)(buf + OFF_WCS);
    float* bP = buf + OFF_BP;

    const size_t R1 = 2ull * G4_ * KPX;
    const size_t R2 = 2ull * G4_ * H_;
    const size_t R3 = (size_t)H_ * H_;
    const size_t R4 = (size_t)H_ * H_;
    const size_t R5 = 2ull * H_ * H_;
    const size_t R6 = 2ull * G4_;
    const size_t R7 = OFF_WYY - OFF_H;          // h fp32 + h bf16 planes + c
    const size_t R8 = OFF_RL - OFF_RB;          // r bf16 planes
    const size_t R9 = 4ull * B_ * T_ * H_;      // zero Y
    const size_t R10 = 16;                      // sync words
    const size_t TOT = R1 + R2 + R3 + R4 + R5 + R6 + R7 + R8 + R9 + R10;
    size_t stride = (size_t)gridDim.x * blockDim.x;
    for (size_t id = (size_t)blockIdx.x * blockDim.x + threadIdx.x; id < TOT; id += stride) {
        size_t i = id;
        if (i < R1) {
            int w = (int)(i / ((size_t)G4_ * KPX));
            size_t rem = i % ((size_t)G4_ * KPX);
            int np = (int)(rem / KPX), k = (int)(rem % KPX);
            int col = (np & 3) * H_ + (np >> 2);
            const float* W = w ? W2 : W1;
            float v = (k < D_) ? W[(size_t)k * G4_ + col] : 0.f;
            size_t o = ((size_t)(w * 2) * G4_ + np) * KPX + k;
            split_store(v, WxS + o, WxS + o + (size_t)G4_ * KPX);
            continue;
        }
        i -= R1;
        if (i < R2) {
            int w = (int)(i / ((size_t)G4_ * H_));
            size_t rem = i % ((size_t)G4_ * H_);
            int np = (int)(rem / H_), k = (int)(rem % H_);
            int col = (np & 3) * H_ + (np >> 2);
            const float* W = w ? W2 : W1;
            float v = W[(size_t)(D_ + k) * G4_ + col];
            size_t o = ((size_t)(w * 2) * G4_ + np) * H_ + k;
            split_store(v, WhS + o, WhS + o + (size_t)G4_ * H_);
            continue;
        }
        i -= R2;
        if (i < R3) {
            int n = (int)(i / H_), k = (int)(i % H_);
            size_t o = (size_t)n * H_ + k;
            split_store(Wy[(size_t)k * H_ + n], WyS + o, WyS + o + (size_t)H_ * H_);
            continue;
        }
        i -= R3;
        if (i < R4) {
            int n = (int)(i / H_), k = (int)(i % H_);
            size_t o = (size_t)n * H_ + k;
            split_store(Wh[(size_t)k * H_ + n], WhA + o, WhA + o + (size_t)H_ * H_);
            continue;
        }
        i -= R4;
        if (i < R5) {
            int n = (int)(i / H_), k = (int)(i % H_);
            float v = (n < H_) ? Wr[(size_t)k * H_ + n] : Wt[(size_t)k * H_ + (n - H_)];
            size_t o = (size_t)n * H_ + k;
            split_store(v, WcS + o, WcS + o + 2ull * H_ * H_);
            continue;
        }
        i -= R5;
        if (i < R6) {
            int w = (int)(i / G4_), np = (int)(i % G4_);
            int col = (np & 3) * H_ + (np >> 2);
            bP[i] = (w ? b2 : b1)[col];
            continue;
        }
        i -= R6;
        if (i < R7) { (buf + OFF_H)[i] = 0.f; continue; }
        i -= R7;
        if (i < R8) { (buf + OFF_RB)[i] = 0.f; continue; }
        i -= R8;
        if (i < R9) { (buf + OFF_Y)[i] = 0.f; continue; }
        i -= R9;
        ((int*)(buf + OFF_META))[M_SYNC + i] = 0;
    }
}

// ---------------- sort + row lists ----------------
__global__ void __launch_bounds__(256) k_sort(const int* __restrict__ s1,
                                              const int* __restrict__ s2) {
    int* meta = (int*)(d_buf + OFF_META);
    int tid = threadIdx.x;
    __shared__ int sl[2][128];
    __shared__ int sl2s[256];
    __shared__ int cntA[256];
    __shared__ int totA;
    if (tid < 128) { sl[0][tid] = s1[tid]; sl[1][tid] = s2[tid]; }
    __syncthreads();
    // per-class rank sort (desc, stable)
    {
        int c = tid >> 7, i = tid & 127;
        int v = sl[c][i], r = 0;
        for (int j = 0; j < 128; j++) {
            int u = sl[c][j];
            if (u > v || (u == v && j < i)) r++;
        }
        meta[(c ? M_PERM1 : M_PERM0) + r] = i;
        meta[(c ? M_IPOS1 : M_IPOS0) + i] = r;
        meta[(c ? M_SLS1  : M_SLS0)  + r] = v;
    }
    if (tid < 128) {
        int c = tid >> 6, t = tid & 63;
        int cnt = 0;
        for (int i = 0; i < 128; i++) cnt += (sl[c][i] > t);
        meta[(c ? M_MCNT1 : M_MCNT0) + t] = cnt;
    }
    // pair sort (desc by sl2)
    {
        int a = tid >> 7, b = tid & 127;
        sl2s[tid] = a ? sl[0][b] : sl[1][b];
    }
    __syncthreads();
    {
        int v = sl2s[tid], r = 0;
        for (int j = 0; j < 256; j++) {
            int u = sl2s[j];
            if (u > v || (u == v && j < tid)) r++;
        }
        meta[M_PERM2 + r] = tid;
    }
    if (tid < 64) {
        int cnt = 0;
        for (int j = 0; j < 256; j++) cnt += (sl2s[j] > tid);
        meta[M_MCNT2 + tid] = cnt;
    }
    // row lists per class: actives (in row order) then deads
    for (int c = 0; c < 2; c++) {
        int base = c ? M_ROWL1 : M_ROWL0;
        int myA = 0;
        for (int k = 0; k < 32; k++) {
            int row = tid * 32 + k;
            myA += ((row & 63) < sl[c][row >> 6]);
        }
        __syncthreads();
        cntA[tid] = myA;
        __syncthreads();
        if (tid == 0) {
            int s = 0;
            for (int i = 0; i < 256; i++) { int v = cntA[i]; cntA[i] = s; s += v; }
            totA = s;
            meta[M_NACT + c] = s;
        }
        __syncthreads();
        int pa = cntA[tid];
        int pd = totA + (tid * 32 - pa);
        for (int k = 0; k < 32; k++) {
            int row = tid * 32 + k;
            if ((row & 63) < sl[c][row >> 6]) meta[base + pa++] = row;
            else                              meta[base + pd++] = row;
        }
        __syncthreads();
    }
}

__global__ void k_gather(float* __restrict__ e, const int* __restrict__ t1,
                         const int* __restrict__ t2, const float* __restrict__ emb) {
    size_t total = 2ull * B_ * T_ * KPX;
    size_t stride = (size_t)gridDim.x * blockDim.x;
    for (size_t i = (size_t)blockIdx.x * blockDim.x + threadIdx.x; i < total; i += stride) {
        int which = (int)(i / ((size_t)B_ * T_ * KPX));
        size_t rem = i % ((size_t)B_ * T_ * KPX);
        int bt = (int)(rem / KPX), k = (int)(rem % KPX);
        int tok = (which ? t2 : t1)[bt];
        e[i] = (k < D_) ? emb[(size_t)tok * D_ + k] : 0.f;
    }
}

// ---------------------------------------------------------------------------
// bulk GEMM engine (fp32 A, in-kernel split, double buffered)
// ---------------------------------------------------------------------------
__device__ __forceinline__ void gemm_k(
    const float* __restrict__ Ag, const __nv_bfloat16* __restrict__ Bhg,
    const __nv_bfloat16* __restrict__ Blg, int nch,
    char* smem_raw, uint32_t sb,
    uint32_t aSt, uint32_t bSt, uint32_t aLd, uint32_t bLd,
    int wid, float acc[4][4][4]) {
    float fA[16];
    {
#pragma unroll
        for (int q = 0; q < 4; q++) {
            CP_ASYNC16(sb + B_BASE(0, 0) + bSt + q * 16, Bhg + q * 8);
            CP_ASYNC16(sb + B_BASE(1, 0) + bSt + q * 16, Blg + q * 8);
        }
        CP_COMMIT();
        const float4* s4 = (const float4*)Ag;
#pragma unroll
        for (int q = 0; q < 4; q++) {
            float4 v = __ldcg(s4 + q);
            fA[4 * q] = v.x; fA[4 * q + 1] = v.y; fA[4 * q + 2] = v.z; fA[4 * q + 3] = v.w;
        }
        ushort hi[16], lo[16];
#pragma unroll
        for (int q = 0; q < 16; q++) {
            __nv_bfloat16 hb = __float2bfloat16_rn(fA[q]);
            __nv_bfloat16 lb = __float2bfloat16_rn(fA[q] - __bfloat162float(hb));
            hi[q] = *(ushort*)&hb; lo[q] = *(ushort*)&lb;
        }
        *(uint4*)(smem_raw + A_BASE(0, 0) + aSt)      = *(uint4*)(hi);
        *(uint4*)(smem_raw + A_BASE(0, 0) + aSt + 16) = *(uint4*)(hi + 8);
        *(uint4*)(smem_raw + A_BASE(1, 0) + aSt)      = *(uint4*)(lo);
        *(uint4*)(smem_raw + A_BASE(1, 0) + aSt + 16) = *(uint4*)(lo + 8);
        CP_WAIT0();
        __syncthreads();
    }
    for (int ch = 0; ch < nch; ch++) {
        int s = ch & 1, ns = s ^ 1;
        bool more = (ch + 1) < nch;
        if (more) {
            const __nv_bfloat16* bh2 = Bhg + (ch + 1) * KC;
            const __nv_bfloat16* bl2 = Blg + (ch + 1) * KC;
#pragma unroll
            for (int q = 0; q < 4; q++) {
                CP_ASYNC16(sb + B_BASE(0, ns) + bSt + q * 16, bh2 + q * 8);
                CP_ASYNC16(sb + B_BASE(1, ns) + bSt + q * 16, bl2 + q * 8);
            }
            CP_COMMIT();
            const float4* s4 = (const float4*)(Ag + (ch + 1) * KC);
#pragma unroll
            for (int q = 0; q < 4; q++) {
                float4 v = __ldcg(s4 + q);
                fA[4 * q] = v.x; fA[4 * q + 1] = v.y; fA[4 * q + 2] = v.z; fA[4 * q + 3] = v.w;
            }
        }
#pragma unroll
        for (int h16 = 0; h16 < 2; h16++) {
            uint32_t kb = (uint32_t)h16 * 32;
            uint32_t bh[8], bl[8];
#pragma unroll
            for (int g2 = 0; g2 < 2; g2++) {
                uint32_t rowb = (uint32_t)((wid * 32 + g2 * 16) * PAD) * 2;
                LDSM4(bh[g2 * 4 + 0], bh[g2 * 4 + 1], bh[g2 * 4 + 2], bh[g2 * 4 + 3],
                      sb + B_BASE(0, s) + bLd + rowb + kb);
                LDSM4(bl[g2 * 4 + 0], bl[g2 * 4 + 1], bl[g2 * 4 + 2], bl[g2 * 4 + 3],
                      sb + B_BASE(1, s) + bLd + rowb + kb);
            }
#pragma unroll
            for (int mt = 0; mt < 4; mt++) {
                uint32_t ah[4], al[4];
                uint32_t rowa = (uint32_t)(mt * 16 * PAD) * 2;
                LDSM4(ah[0], ah[1], ah[2], ah[3], sb + A_BASE(0, s) + aLd + rowa + kb);
                LDSM4(al[0], al[1], al[2], al[3], sb + A_BASE(1, s) + aLd + rowa + kb);
#pragma unroll
                for (int nt = 0; nt < 4; nt++) {
                    int bi = (nt >> 1) * 4 + (nt & 1) * 2;
                    MMA16816(acc[mt][nt], ah, bh[bi], bh[bi + 1]);
                    MMA16816(acc[mt][nt], ah, bl[bi], bl[bi + 1]);
                    MMA16816(acc[mt][nt], al, bh[bi], bh[bi + 1]);
                }
            }
        }
        if (more) {
            ushort hi[16], lo[16];
#pragma unroll
            for (int q = 0; q < 16; q++) {
                __nv_bfloat16 hb = __float2bfloat16_rn(fA[q]);
                __nv_bfloat16 lb = __float2bfloat16_rn(fA[q] - __bfloat162float(hb));
                hi[q] = *(ushort*)&hb; lo[q] = *(ushort*)&lb;
            }
            *(uint4*)(smem_raw + A_BASE(0, ns) + aSt)      = *(uint4*)(hi);
            *(uint4*)(smem_raw + A_BASE(0, ns) + aSt + 16) = *(uint4*)(hi + 8);
            *(uint4*)(smem_raw + A_BASE(1, ns) + aSt)      = *(uint4*)(lo);
            *(uint4*)(smem_raw + A_BASE(1, ns) + aSt + 16) = *(uint4*)(lo + 8);
            CP_WAIT0();
        }
        __syncthreads();
    }
}

struct MZ {
    const float*         A;
    const __nv_bfloat16* Bhi;
    const __nv_bfloat16* Blo;
    float*               C;
    const float*         bias;
    const int*           rows;    // optional row indirection (A and C rows)
    const int*           nactp;   // optional active row count
};
struct MP {
    MZ z[4];
    int Klen, lda, ldb, ldc;
};

__global__ void __launch_bounds__(128) mm_gemm(MP p) {
    extern __shared__ __align__(16) char smem_raw[];
    uint32_t sb = smem_u32(smem_raw);
    const MZ z = p.z[blockIdx.z];
    int tid = threadIdx.x, lane = tid & 31, wid = tid >> 5;
    int n0 = blockIdx.x * TN, m0 = blockIdx.y * TM;

    if (z.rows && m0 >= __ldg(z.nactp)) return;

    int arow = z.rows ? __ldg(z.rows + m0 + (tid >> 1)) : (m0 + (tid >> 1));
    const float*         Ag  = z.A   + (size_t)arow * p.lda + (tid & 1) * 16;
    const __nv_bfloat16* Bhg = z.Bhi + (size_t)(n0 + tid) * p.ldb;
    const __nv_bfloat16* Blg = z.Blo + (size_t)(n0 + tid) * p.ldb;
    uint32_t aSt = (uint32_t)((tid >> 1) * PAD + (tid & 1) * 16) * 2;
    uint32_t bSt = (uint32_t)(tid * PAD) * 2;
    uint32_t aLd = (uint32_t)((lane & 15) * PAD + ((lane >> 4) << 3)) * 2;
    uint32_t bLd = (uint32_t)(((lane & 7) + ((lane & 16) >> 1)) * PAD + (lane & 8)) * 2;

    float acc[4][4][4] = {};
    gemm_k(Ag, Bhg, Blg, p.Klen / KC, smem_raw, sb, aSt, bSt, aLd, bLd, wid, acc);

#pragma unroll
    for (int mt = 0; mt < 4; mt++) {
        int r = m0 + mt * 16 + (lane >> 2);
        int r0 = z.rows ? __ldg(z.rows + r) : r;
        int r1 = z.rows ? __ldg(z.rows + r + 8) : (r + 8);
#pragma unroll
        for (int nt = 0; nt < 4; nt++) {
            int c = n0 + wid * 32 + nt * 8 + (lane & 3) * 2;
            float b0 = 0.f, b1 = 0.f;
            if (z.bias) { b0 = z.bias[c]; b1 = z.bias[c + 1]; }
            *(float2*)(z.C + (size_t)r0 * p.ldc + c) =
                make_float2(acc[mt][nt][0] + b0, acc[mt][nt][1] + b1);
            *(float2*)(z.C + (size_t)r1 * p.ldc + c) =
                make_float2(acc[mt][nt][2] + b0, acc[mt][nt][3] + b1);
        }
    }
}

// ---------------------------------------------------------------------------
// Persistent LSTM scan: TM=128(sorted batch) x TN=64, Wh resident, mt-skip.
// ---------------------------------------------------------------------------
__global__ void __launch_bounds__(128) k_lstm_persist() {
    extern __shared__ __align__(16) char smem[];
    uint32_t sb = smem_u32(smem);
    float* buf = d_buf;
    int* meta = (int*)(buf + OFF_META);
    int tid = threadIdx.x, lane = tid & 31, wg = tid >> 5;
    int blk = blockIdx.x;
    int r = blk >> 5, nt_ = blk & 31;
    int n0 = nt_ * 64;
    int widx = (r == 0 || r == 2) ? 0 : 1;
    int cls  = (r == 0 || r == 3) ? 0 : 1;
    const int* permc = meta + (cls ? M_PERM1 : M_PERM0);
    const int* slsrt = meta + (cls ? M_SLS1  : M_SLS0);
    const int* mcnt  = meta + (cls ? M_MCNT1 : M_MCNT0);

    // one-time resident Wh slab: 64 rows x 512 K x {hi,lo}
    {
        const __nv_bfloat16* WhS = (const __nv_bfloat16*)(buf + OFF_WHS);
        int n = tid >> 1, half = tid & 1;
#pragma unroll
        for (int tau = 0; tau < 2; tau++) {
            const __nv_bfloat16* src = WhS + (size_t)(widx * 2 + tau) * G4_ * H_
                                       + (size_t)(n0 + n) * H_ + half * 256;
            uint32_t dst = sb + (uint32_t)tau * 66560u + (uint32_t)n * 1040u + (uint32_t)half * 512u;
#pragma unroll
            for (int q = 0; q < 32; q++) CP_ASYNC16(dst + q * 16, src + q * 8);
        }
        CP_COMMIT(); CP_WAIT0(); __syncthreads();
    }

    const float* Xg  = buf + OFF_XG + (size_t)r * B_ * T_ * G4_;
    float*       cst = buf + OFF_C + (size_t)r * B_ * H_;
    float*       Yst = buf + OFF_Y + (size_t)r * B_ * T_ * H_;
    float*       hB  = buf + OFF_H;
    __nv_bfloat16* HBb = (__nv_bfloat16*)(buf + OFF_HB);
    unsigned* sync = (unsigned*)(meta + M_SYNC);
    const size_t HBUF = 4ull * B_ * H_;

    uint32_t aLd   = (uint32_t)((lane & 15) * 40 + ((lane >> 4) << 3)) * 2;
    uint32_t bBase = (uint32_t)(wg * 16) * 1040u
                   + (uint32_t)(((lane & 7) + ((lane & 16) >> 1)) * 520 + (lane & 8)) * 2;

    for (int t = 0; t < T_; t++) {
        int mcur  = __ldg(mcnt + t);
        int mtmax = (mcur + 15) >> 4;
        int ppi = t & 1, ppo = ppi ^ 1;
        const float* hin  = hB + (size_t)ppi * HBUF + (size_t)r * B_ * H_;
        float*       hout = hB + (size_t)ppo * HBUF + (size_t)r * B_ * H_;
        const __nv_bfloat16* Ain = HBb + (size_t)ppi * 2 * P_HB + (size_t)r * B_ * H_;
        __nv_bfloat16*       ho  = HBb + (size_t)ppo * 2 * P_HB + (size_t)r * B_ * H_;

        float acc[8][2][4] = {};
        if (mtmax > 0) {
            int nrows = mtmax << 4;
            auto issueA = [&](int ch, int slot) {
                if (tid < nrows) {
#pragma unroll
                    for (int tau = 0; tau < 2; tau++) {
                        const __nv_bfloat16* src = Ain + (size_t)tau * P_HB + (size_t)tid * H_ + ch * 32;
                        uint32_t dst = sb + 133120u + (uint32_t)slot * 20480u
                                     + (uint32_t)tau * 10240u + (uint32_t)tid * 80u;
                        CP_ASYNC16(dst,      src);
                        CP_ASYNC16(dst + 16, src + 8);
                        CP_ASYNC16(dst + 32, src + 16);
                        CP_ASYNC16(dst + 48, src + 24);
                    }
                }
                CP_COMMIT();
            };
            issueA(0, 0); issueA(1, 1);
            for (int ch = 0; ch < 16; ch++) {
                if (ch == 15) { CP_WAIT0(); } else { CP_WAIT1(); }
                __syncthreads();
                if (ch + 2 < 16) issueA(ch + 2, (ch + 2) % 3);
                uint32_t abase = sb + 133120u + (uint32_t)(ch % 3) * 20480u;
#pragma unroll
                for (int h16 = 0; h16 < 2; h16++) {
                    uint32_t kb = (uint32_t)(ch * 32 + h16 * 16) * 2;
                    uint32_t bA[4], bB[4];
                    LDSM4(bA[0], bA[1], bA[2], bA[3], sb + bBase + kb);
                    LDSM4(bB[0], bB[1], bB[2], bB[3], sb + 66560u + bBase + kb);
#pragma unroll
                    for (int mt = 0; mt < 8; mt++) {
                        if (mt < mtmax) {
                            uint32_t ah[4], al[4];
                            uint32_t rowa = (uint32_t)(mt * 16 * 80);
                            LDSM4(ah[0], ah[1], ah[2], ah[3], abase + aLd + rowa + h16 * 32);
                            LDSM4(al[0], al[1], al[2], al[3], abase + 10240u + aLd + rowa + h16 * 32);
                            MMA16816(acc[mt][0], ah, bA[0], bA[1]);
                            MMA16816(acc[mt][0], ah, bB[0], bB[1]);
                            MMA16816(acc[mt][0], al, bA[0], bA[1]);
                            MMA16816(acc[mt][1], ah, bA[2], bA[3]);
                            MMA16816(acc[mt][1], ah, bB[2], bB[3]);
                            MMA16816(acc[mt][1], al, bA[2], bA[3]);
                        }
                    }
                }
            }
        }

        // epilogue: active frags -> fused cell; frozen frags -> copy
#pragma unroll
        for (int mt = 0; mt < 8; mt++) {
            if (mt < mtmax) {
                int b = mt * 16 + (lane >> 2);
#pragma unroll
                for (int nt = 0; nt < 2; nt++) {
                    float fo0 = __shfl_xor_sync(0xffffffffu, acc[mt][nt][0], 1);
                    float fo1 = __shfl_xor_sync(0xffffffffu, acc[mt][nt][1], 1);
                    float fo2 = __shfl_xor_sync(0xffffffffu, acc[mt][nt][2], 1);
                    float fo3 = __shfl_xor_sync(0xffffffffu, acc[mt][nt][3], 1);
                    if (!(lane & 1)) {
#pragma unroll
                        for (int half = 0; half < 2; half++) {
                            int bb = b + half * 8;          // sorted position
                            float gi = half ? acc[mt][nt][2] : acc[mt][nt][0];
                            float gj = half ? acc[mt][nt][3] : acc[mt][nt][1];
                            float gf = half ? fo2 : fo0;
                            float go = half ? fo3 : fo1;
                            int c0 = n0 + wg * 16 + nt * 8 + (lane & 3) * 2;
                            int j = c0 >> 2;
                            size_t ci = (size_t)bb * H_ + j;
                            int slv = __ldg(slsrt + bb);
                            float hv;
                            if (t < slv) {
                                int ob = __ldg(permc + bb);  // original batch
                                float4 x = *(const float4*)(Xg + ((size_t)ob * T_ + t) * G4_ + c0);
                                gi += x.x; gj += x.y; gf += x.z; go += x.w;
                                float cc = cst[ci];
                                float cn = cc * sigf(gf + 1.f) + sigf(gi) * ftanh(gj);
                                hv = ftanh(cn) * sigf(go);
                                cst[ci] = cn;
                                Yst[((size_t)ob * T_ + t) * H_ + j] = hv;
                            } else {
                                hv = __ldcg(hin + ci);
                            }
                            hout[ci] = hv;
                            split_store(hv, ho + ci, ho + P_HB + ci);
                        }
                    }
                }
            } else {
                // frozen copy: 16 rows x 16 j (this CTA's j-slice)
                int rr = mt * 16 + (tid >> 3);
                int jj = (n0 >> 2) + (tid & 7) * 2;
                size_t ci = (size_t)rr * H_ + jj;
#pragma unroll
                for (int q = 0; q < 2; q++) {
                    float hv = __ldcg(hin + ci + q);
                    hout[ci + q] = hv;
                    ho[ci + q]        = Ain[ci + q];
                    ho[P_HB + ci + q] = Ain[P_HB + ci + q];
                }
            }
        }
        gbar(sync + 0, sync + 1, (unsigned)(t + 1), 128u);
    }
}

// ---------------------------------------------------------------------------
// Persistent attention scan: Wc resident, sorted pairs, frag skipping.
// ---------------------------------------------------------------------------
__global__ void __launch_bounds__(128) k_att_persist(
    const float* __restrict__ wv,
    const int* __restrict__ s1, const int* __restrict__ s2) {
    extern __shared__ __align__(16) char smem[];
    uint32_t sb = smem_u32(smem);
    float* smf = (float*)(smem + 69632);
    float* buf = d_buf;
    int* meta = (int*)(buf + OFF_META);
    int tid = threadIdx.x, lane = tid & 31, wg = tid >> 5;
    int blk = blockIdx.x;

    int ks  = blk & 3;
    int mt_ = (blk >> 2) & 3;
    int nt_ = blk >> 4;
    int m0 = mt_ * 64, n0 = nt_ * 128, kst = ks * 128;

    // resident Wc slab
    {
        const __nv_bfloat16* WcS = (const __nv_bfloat16*)(buf + OFF_WCS);
#pragma unroll
        for (int tau = 0; tau < 2; tau++) {
            const __nv_bfloat16* src = WcS + (size_t)tau * 2 * H_ * H_
                                       + (size_t)(n0 + tid) * H_ + kst;
            uint32_t dst = sb + (uint32_t)tau * 34816u + (uint32_t)tid * 272u;
#pragma unroll
            for (int q = 0; q < 16; q++) CP_ASYNC16(dst + q * 16, src + q * 8);
        }
        CP_COMMIT(); CP_WAIT0(); __syncthreads();
    }

    __nv_bfloat16* RBb = (__nv_bfloat16*)(buf + OFF_RB);   // sorted pair order
    float* uPt4 = buf + OFF_UPT;                            // sorted pair rows
    float* rL   = buf + OFF_RL;                             // ORIGINAL pair index
    const float* WyY = buf + OFF_WYY;
    const float* HWy = buf + OFF_HWY;
    const float* Yb  = buf + OFF_Y;
    unsigned* sync = (unsigned*)(meta + M_SYNC);
    const int* mcnt2 = meta + M_MCNT2;

    uint32_t aLd = (uint32_t)((lane & 15) * 40 + ((lane >> 4) << 3)) * 2;
    uint32_t bLd = (uint32_t)(((lane & 7) + ((lane & 16) >> 1)) * 136 + (lane & 8)) * 2;

    float wvr[16];
#pragma unroll
    for (int k = 0; k < 16; k++) wvr[k] = __ldg(wv + lane + 32 * k);

    // this CTA's two (sorted) pairs
    int spA = blk * 2, spB = blk * 2 + 1;
    int pA = meta[M_PERM2 + spA], pB = meta[M_PERM2 + spB];
    int aA = pA >> 7, bA = pA & 127;
    int aB = pB >> 7, bB = pB & 127;
    int sl2A = aA ? s1[bA] : s2[bA];
    int sl2B = aB ? s1[bB] : s2[bB];
    int slmA = aA ? s2[bA] : s1[bA];
    int slmB = aB ? s2[bB] : s1[bB];

    for (int t = 0; t < T_; t++) {
        int mcur2 = __ldg(mcnt2 + t);
        int mtloc = 0;
        if (mcur2 > m0) { mtloc = (mcur2 - m0 + 15) >> 4; if (mtloc > 4) mtloc = 4; }

        if (mtloc > 0) {
            int nrows = mtloc << 4;
            auto issueA = [&](int ch, int slot) {
                int row = tid >> 1, tau = tid & 1;
                if (row < nrows) {
                    const __nv_bfloat16* src = RBb + (size_t)tau * P_RB
                                               + (size_t)(m0 + row) * H_ + kst + ch * 32;
                    uint32_t dst = sb + 69632u + (uint32_t)slot * 10240u
                                 + (uint32_t)tau * 5120u + (uint32_t)row * 80u;
                    CP_ASYNC16(dst,      src);
                    CP_ASYNC16(dst + 16, src + 8);
                    CP_ASYNC16(dst + 32, src + 16);
                    CP_ASYNC16(dst + 48, src + 24);
                }
                CP_COMMIT();
            };
            issueA(0, 0); issueA(1, 1);
            float acc[4][4][4] = {};
            for (int ch = 0; ch < 4; ch++) {
                if (ch == 3) { CP_WAIT0(); } else { CP_WAIT1(); }
                __syncthreads();
                if (ch + 2 < 4) issueA(ch + 2, (ch + 2) % 3);
                uint32_t abase = sb + 69632u + (uint32_t)(ch % 3) * 10240u;
#pragma unroll
                for (int h16 = 0; h16 < 2; h16++) {
                    uint32_t kb = (uint32_t)(ch * 32 + h16 * 16) * 2;
                    uint32_t bh[8], bl[8];
#pragma unroll
                    for (int g2 = 0; g2 < 2; g2++) {
                        uint32_t rowb = (uint32_t)((wg * 32 + g2 * 16) * 136) * 2;
                        LDSM4(bh[g2 * 4 + 0], bh[g2 * 4 + 1], bh[g2 * 4 + 2], bh[g2 * 4 + 3],
                              sb + bLd + rowb + kb);
                        LDSM4(bl[g2 * 4 + 0], bl[g2 * 4 + 1], bl[g2 * 4 + 2], bl[g2 * 4 + 3],
                              sb + 34816u + bLd + rowb + kb);
                    }
#pragma unroll
                    for (int mt = 0; mt < 4; mt++) {
                        if (mt < mtloc) {
                            uint32_t ah[4], al[4];
                            uint32_t rowa = (uint32_t)(mt * 16 * 80);
                            LDSM4(ah[0], ah[1], ah[2], ah[3], abase + aLd + rowa + h16 * 32);
                            LDSM4(al[0], al[1], al[2], al[3], abase + 5120u + aLd + rowa + h16 * 32);
#pragma unroll
                            for (int nt = 0; nt < 4; nt++) {
                                int bi = (nt >> 1) * 4 + (nt & 1) * 2;
                                MMA16816(acc[mt][nt], ah, bh[bi], bh[bi + 1]);
                                MMA16816(acc[mt][nt], ah, bl[bi], bl[bi + 1]);
                                MMA16816(acc[mt][nt], al, bh[bi], bh[bi + 1]);
                            }
                        }
                    }
                }
            }
            float* Cb = uPt4 + (size_t)ks * 256 * 1024;
#pragma unroll
            for (int mt = 0; mt < 4; mt++) {
                if (mt < mtloc) {
                    int rr = m0 + mt * 16 + (lane >> 2);
#pragma unroll
                    for (int nt = 0; nt < 4; nt++) {
                        int c = n0 + wg * 32 + nt * 8 + (lane & 3) * 2;
                        *(float2*)(Cb + (size_t)rr * 1024 + c) =
                            make_float2(acc[mt][nt][0], acc[mt][nt][1]);
                        *(float2*)(Cb + (size_t)(rr + 8) * 1024 + c) =
                            make_float2(acc[mt][nt][2], acc[mt][nt][3]);
                    }
                }
            }
        }
        gbar(sync + 2, sync + 3, (unsigned)(2 * t + 1), 128u);

        // phase A: two sorted pairs, exact skipping
        for (int pi = 0; pi < 2; pi++) {
            int sp   = pi ? spB : spA;
            int p    = pi ? pB : pA;
            int a    = pi ? aB : aA;
            int b    = pi ? bB : bA;
            int sl2  = pi ? sl2B : sl2A;
            int slm  = pi ? slmB : slmA;
            if (t >= sl2) continue;

            float* su  = smf;
            float* spt = smf + 512;
            float* sc  = smf + 1024;
            const float* hb = HWy + (size_t)a * B_ * T_ * H_ + ((size_t)b * T_ + t) * H_;
#pragma unroll
            for (int q = 0; q < 4; q++) {
                int h = tid + q * 128;
                float s0 = 0.f, s1v = 0.f;
#pragma unroll
                for (int k = 0; k < 4; k++) {
                    const float* up = uPt4 + ((size_t)k * 256 + sp) * 1024;
                    s0  += __ldcg(up + h);
                    s1v += __ldcg(up + 512 + h);
                }
                su[h]  = s0 + __ldg(hb + h);
                spt[h] = s1v;
            }
            __syncthreads();
            const float* WyYb = WyY + (size_t)a * B_ * T_ * H_ + (size_t)b * T_ * H_;
#pragma unroll
            for (int q = 0; q < 16; q++) {
                int t2 = wg * 16 + q;
                if (t2 < slm) {
                    const float* row = WyYb + (size_t)t2 * H_;
                    float s = 0.f;
#pragma unroll
                    for (int k = 0; k < 16; k++) {
                        int hh = lane + 32 * k;
                        s += tanha(__ldg(row + hh) + su[hh]) * wvr[k];
                    }
                    for (int o = 16; o; o >>= 1) s += __shfl_xor_sync(0xffffffffu, s, o);
                    if (lane == 0) sc[t2] = s;
                } else if (lane == 0) {
                    sc[t2] = -10000.f;
                }
            }
            __syncthreads();
            if (wg == 0) {
                float v1 = sc[lane], v2 = sc[lane + 32];
                float m = fmaxf(v1, v2);
                for (int o = 16; o; o >>= 1) m = fmaxf(m, __shfl_xor_sync(0xffffffffu, m, o));
                float e1 = __expf(v1 - m), e2 = __expf(v2 - m);
                float s = e1 + e2;
                for (int o = 16; o; o >>= 1) s += __shfl_xor_sync(0xffffffffu, s, o);
                float inv = __fdividef(1.f, s);
                sc[lane] = e1 * inv;
                sc[lane + 32] = e2 * inv;
            }
            __syncthreads();
            const float* Yp = Yb + (size_t)(a ? 2 : 0) * B_ * T_ * H_ + (size_t)b * T_ * H_;
#pragma unroll
            for (int q = 0; q < 4; q++) {
                int h = tid + q * 128;
                float accv = 0.f;
                for (int t2 = 0; t2 < slm; t2++)
                    accv += sc[t2] * __ldg(Yp + (size_t)t2 * H_ + h);
                float rn = accv + ftanh(spt[h]);
                if (t == sl2 - 1) {
                    rL[(size_t)p * H_ + h] = rn;
                } else {
                    split_store(rn, RBb + (size_t)sp * H_ + h, RBb + P_RB + (size_t)sp * H_ + h);
                }
            }
            __syncthreads();
        }
        gbar(sync + 2, sync + 3, (unsigned)(2 * t + 2), 128u);
    }
}

// ---------------- final projection (h rows are sorted) ----------------
__global__ void __launch_bounds__(512) k_final(
    const float* __restrict__ rL, const float* __restrict__ hfin,
    const float* __restrict__ Wp, const float* __restrict__ Wx,
    const float* __restrict__ U, const float* __restrict__ bU,
    float* __restrict__ out) {
    int b = blockIdx.x;
    int tid = threadIdx.x;
    const int* meta = (const int*)(d_buf + OFF_META);
    int ip1 = meta[M_IPOS1 + b];   // run1 class s2
    int ip0 = meta[M_IPOS0 + b];   // run3 class s1
    __shared__ float s_in[4][512];
    __shared__ float s_sum[512];
    __shared__ float red0[16], red1[16];
    s_in[0][tid] = rL[(size_t)b * H_ + tid];
    s_in[1][tid] = hfin[((size_t)1 * B_ + ip1) * H_ + tid];
    s_in[2][tid] = rL[((size_t)B_ + b) * H_ + tid];
    s_in[3][tid] = hfin[((size_t)3 * B_ + ip0) * H_ + tid];
    __syncthreads();
    float acc0 = 0.f, acc1 = 0.f;
    for (int k = 0; k < H_; k++) {
        float wp = Wp[(size_t)k * H_ + tid];
        float wx = Wx[(size_t)k * H_ + tid];
        acc0 += s_in[0][k] * wp + s_in[1][k] * wx;
        acc1 += s_in[2][k] * wp + s_in[3][k] * wx;
    }
    s_sum[tid] = ftanh(acc0) + ftanh(acc1);
    __syncthreads();
    float p0 = s_sum[tid] * U[(size_t)tid * 2 + 0];
    float p1 = s_sum[tid] * U[(size_t)tid * 2 + 1];
    for (int o = 16; o; o >>= 1) {
        p0 += __shfl_xor_sync(0xffffffffu, p0, o);
        p1 += __shfl_xor_sync(0xffffffffu, p1, o);
    }
    int wp_ = tid >> 5;
    if ((tid & 31) == 0) { red0[wp_] = p0; red1[wp_] = p1; }
    __syncthreads();
    if (tid < 16) {
        p0 = red0[tid]; p1 = red1[tid];
        for (int o = 8; o; o >>= 1) {
            p0 += __shfl_xor_sync(0x0000ffffu, p0, o);
            p1 += __shfl_xor_sync(0x0000ffffu, p1, o);
        }
        if (tid == 0) {
            out[b * 2 + 0] = p0 + bU[0];
            out[b * 2 + 1] = p1 + bU[1];
        }
    }
}

// ---------------- host ----------------
extern "C" void kernel_launch(void* const* d_in, const int* in_sizes, int n_in,
                              void* d_out, int out_size) {
    (void)in_sizes; (void)n_in; (void)out_size;
    const int*   tokens1 = (const int*)d_in[0];
    const int*   tokens2 = (const int*)d_in[1];
    const int*   seqlen1 = (const int*)d_in[2];
    const int*   seqlen2 = (const int*)d_in[3];
    const float* emb = (const float*)d_in[4];
    const float* W1  = (const float*)d_in[5];
    const float* b1  = (const float*)d_in[6];
    const float* W2  = (const float*)d_in[7];
    const float* b2  = (const float*)d_in[8];
    const float* Wy  = (const float*)d_in[9];
    const float* Wh  = (const float*)d_in[10];
    const float* Wr  = (const float*)d_in[11];
    const float* wv  = (const float*)d_in[12];
    const float* Wt  = (const float*)d_in[13];
    const float* Wp  = (const float*)d_in[14];
    const float* Wx  = (const float*)d_in[15];
    const float* U   = (const float*)d_in[16];
    const float* bU  = (const float*)d_in[17];
    float* out = (float*)d_out;

    cudaFuncSetAttribute(mm_gemm, cudaFuncAttributeMaxDynamicSharedMemorySize, SMEM_MM);
    cudaFuncSetAttribute(k_lstm_persist, cudaFuncAttributeMaxDynamicSharedMemorySize, SMEM_LSTM);
    cudaFuncSetAttribute(k_att_persist, cudaFuncAttributeMaxDynamicSharedMemorySize, SMEM_ATT);

    float* buf = nullptr;
    cudaGetSymbolAddress((void**)&buf, d_buf);
    float* e    = buf + OFF_E;
    float* Xg   = buf + OFF_XG;
    float* Yb   = buf + OFF_Y;
    float* hBuf = buf + OFF_H;
    float* WyY  = buf + OFF_WYY;
    float* HWy  = buf + OFF_HWY;
    float* rL   = buf + OFF_RL;
    float* bP   = buf + OFF_BP;
    int*   meta = (int*)(buf + OFF_META);
    __nv_bfloat16* WxS = (__nv_bfloat16*)(buf + OFF_WXS);
    __nv_bfloat16* WyS = (__nv_bfloat16*)(buf + OFF_WYS);
    __nv_bfloat16* WhA = (__nv_bfloat16*)(buf + OFF_WHA);

    k_prep<<<2048, 256>>>(W1, W2, Wy, Wh, Wr, Wt, b1, b2);
    k_sort<<<1, 256>>>(seqlen1, seqlen2);
    k_gather<<<2048, 256>>>(e, tokens1, tokens2, emb);

    const int iidx[4] = {0, 1, 1, 0}, widx[4] = {0, 1, 0, 1};
    const int xcls[4] = {0, 1, 1, 0};   // class per run

    // X GEMM: row-compacted
    {
        MP p = {};
        for (int r = 0; r < 4; r++) {
            p.z[r].A     = e + (size_t)iidx[r] * B_ * T_ * KPX;
            p.z[r].Bhi   = WxS + (size_t)(widx[r] * 2 + 0) * G4_ * KPX;
            p.z[r].Blo   = WxS + (size_t)(widx[r] * 2 + 1) * G4_ * KPX;
            p.z[r].C     = Xg + (size_t)r * B_ * T_ * G4_;
            p.z[r].bias  = bP + (size_t)widx[r] * G4_;
            p.z[r].rows  = meta + (xcls[r] ? M_ROWL1 : M_ROWL0);
            p.z[r].nactp = meta + M_NACT + xcls[r];
        }
        p.Klen = KPX; p.lda = KPX; p.ldb = KPX; p.ldc = G4_;
        mm_gemm<<<dim3(G4_ / TN, (B_ * T_) / TM, 4), 128, SMEM_MM>>>(p);
    }

    // persistent LSTM scan (sorted batches, frag skipping)
    k_lstm_persist<<<128, 128, SMEM_LSTM>>>();

    // WyY + HWy: row-compacted (same row lists)
    {
        MP p = {};
        const int runs[4] = {0, 2, 1, 3};
        const int qcls[4] = {0, 1, 1, 0};
        for (int q = 0; q < 4; q++) {
            p.z[q].A     = Yb + (size_t)runs[q] * B_ * T_ * H_;
            p.z[q].Bhi   = (q < 2 ? WyS : WhA);
            p.z[q].Blo   = (q < 2 ? WyS : WhA) + (size_t)H_ * H_;
            p.z[q].C     = (q < 2 ? WyY + (size_t)q * B_ * T_ * H_
                                  : HWy + (size_t)(q - 2) * B_ * T_ * H_);
            p.z[q].bias  = nullptr;
            p.z[q].rows  = meta + (qcls[q] ? M_ROWL1 : M_ROWL0);
            p.z[q].nactp = meta + M_NACT + qcls[q];
        }
        p.Klen = H_; p.lda = H_; p.ldb = H_; p.ldc = H_;
        mm_gemm<<<dim3(H_ / TN, (B_ * T_) / TM, 4), 128, SMEM_MM>>>(p);
    }

    // persistent attention scan (sorted pairs, frag skipping)
    k_att_persist<<<128, 128, SMEM_ATT>>>(wv, seqlen1, seqlen2);

    k_final<<<B_, 512>>>(rL, hBuf, Wp, Wx, U, bU, out);
}

// round 11
// speedup vs baseline: 1.7042x; 1.3588x over previous
#include <cuda_runtime.h>
#include <cuda_bf16.h>
#include <math.h>
#include <stdint.h>

#define B_   128
#define T_   64
#define D_   300
#define KPX  320
#define H_   512
#define G4_  2048

// ---- bulk GEMM tile ----
#define TM 64
#define TN 128
#define KC 32
#define PAD 40
#define A_BASE(term,stage) ((uint32_t)(((term)*2+(stage))*5120))
#define B_BASE(term,stage) ((uint32_t)(20480u + ((term)*2+(stage))*10240u))
static constexpr int SMEM_MM   = 61440;
static constexpr int SMEM_LSTM = 133120 + 3 * 20480;   // 194560
static constexpr int SMEM_ATT  = 69632 + 3 * 10240;    // 100352

__device__ __forceinline__ uint32_t smem_u32(const void* p) {
    uint32_t a;
    asm("{ .reg .u64 t; cvta.to.shared.u64 t, %1; cvt.u32.u64 %0, t; }" : "=r"(a) : "l"(p));
    return a;
}
#define CP_ASYNC16(dst, src) \
    asm volatile("cp.async.cg.shared.global [%0], [%1], 16;" :: "r"(dst), "l"(src))
#define CP_COMMIT() asm volatile("cp.async.commit_group;" ::: "memory")
#define CP_WAIT0()  asm volatile("cp.async.wait_group 0;" ::: "memory")
#define CP_WAIT1()  asm volatile("cp.async.wait_group 1;" ::: "memory")
#define LDSM4(r0, r1, r2, r3, addr) \
    asm volatile("ldmatrix.sync.aligned.m8n8.x4.shared.b16 {%0,%1,%2,%3}, [%4];" \
                 : "=r"(r0), "=r"(r1), "=r"(r2), "=r"(r3) : "r"(addr))
#define MMA16816(c, a, b0, b1) \
    asm volatile("mma.sync.aligned.m16n8k16.row.col.f32.bf16.bf16.f32 " \
                 "{%0,%1,%2,%3}, {%4,%5,%6,%7}, {%8,%9}, {%0,%1,%2,%3};" \
                 : "+f"((c)[0]), "+f"((c)[1]), "+f"((c)[2]), "+f"((c)[3]) \
                 : "r"((a)[0]), "r"((a)[1]), "r"((a)[2]), "r"((a)[3]), \
                   "r"(b0), "r"(b1))

__device__ __forceinline__ float sigf(float x) { return __fdividef(1.f, 1.f + __expf(-x)); }
__device__ __forceinline__ float ftanh(float x) { return 1.f - __fdividef(2.f, __expf(2.f * x) + 1.f); }
__device__ __forceinline__ float tanha(float x) {
    float y; asm("tanh.approx.f32 %0, %1;" : "=f"(y) : "f"(x)); return y;
}

static constexpr size_t P_HB = 4ull * B_ * H_;
static constexpr size_t P_RB = 256ull * H_;

// ---------------- scratch layout (float units) ----------------
static constexpr size_t OFF_E    = 0;
static constexpr size_t OFF_XG   = OFF_E   + 2ull * B_ * T_ * KPX;
static constexpr size_t OFF_Y    = OFF_XG  + 4ull * B_ * T_ * G4_;
static constexpr size_t OFF_H    = OFF_Y   + 4ull * B_ * T_ * H_;
static constexpr size_t OFF_HB   = OFF_H   + 2ull * 4 * B_ * H_;
static constexpr size_t OFF_C    = OFF_HB  + (2ull * 2 * P_HB) / 2;
static constexpr size_t OFF_WYY  = OFF_C   + 4ull * B_ * H_;
static constexpr size_t OFF_HWY  = OFF_WYY + 2ull * B_ * T_ * H_;
static constexpr size_t OFF_UPT  = OFF_HWY + 2ull * B_ * T_ * H_;
static constexpr size_t OFF_RB   = OFF_UPT + 4ull * 256 * 1024;
static constexpr size_t OFF_RL   = OFF_RB  + (2ull * P_RB) / 2;
static constexpr size_t OFF_BP   = OFF_RL  + 256ull * H_;
static constexpr size_t OFF_WXS  = OFF_BP  + 2ull * G4_;
static constexpr size_t OFF_WHS  = OFF_WXS + (2ull * 2 * G4_ * KPX) / 2;
static constexpr size_t OFF_WYS  = OFF_WHS + (2ull * 2 * G4_ * H_) / 2;
static constexpr size_t OFF_WHA  = OFF_WYS + (2ull * H_ * H_) / 2;
static constexpr size_t OFF_WCS  = OFF_WHA + (2ull * H_ * H_) / 2;
static constexpr size_t OFF_META = OFF_WCS + (2ull * 2 * H_ * H_) / 2;
#define M_PERM0 0
#define M_PERM1 128
#define M_IPOS0 256
#define M_IPOS1 384
#define M_SLS0  512
#define M_SLS1  640
#define M_MCNT0 768
#define M_MCNT1 832
#define M_PERM2 896
#define M_MCNT2 1152
#define M_ROWL0 1216
#define M_ROWL1 9408
#define M_NACT  17600
#define M_SYNC  17608
static constexpr size_t META_N  = 17640;
static constexpr size_t TOTAL_F = OFF_META + META_N;

__device__ __align__(256) float d_buf[TOTAL_F];

__device__ __forceinline__ void split_store(float v, __nv_bfloat16* hi, __nv_bfloat16* lo) {
    __nv_bfloat16 h = __float2bfloat16_rn(v);
    *hi = h;
    *lo = __float2bfloat16_rn(v - __bfloat162float(h));
}

// ---------------- grid barrier ----------------
__device__ __forceinline__ void gbar(unsigned* cnt, unsigned* rel,
                                     unsigned seq, unsigned ncta) {
    __syncthreads();
    if (threadIdx.x == 0) {
        unsigned old;
        asm volatile("fence.acq_rel.gpu;" ::: "memory");
        asm volatile("atom.relaxed.gpu.global.add.u32 %0, [%1], 1;"
                     : "=r"(old) : "l"(cnt) : "memory");
        if (old + 1u == ncta * seq) {
            asm volatile("st.release.gpu.global.u32 [%0], %1;"
                         :: "l"(rel), "r"(seq) : "memory");
        }
        unsigned v;
        do {
            asm volatile("ld.acquire.gpu.global.u32 %0, [%1];"
                         : "=r"(v) : "l"(rel) : "memory");
        } while (v < seq);
    }
    __syncthreads();
}

// ---------------- prep ----------------
__global__ void k_prep(const float* __restrict__ W1, const float* __restrict__ W2,
                       const float* __restrict__ Wy, const float* __restrict__ Wh,
                       const float* __restrict__ Wr, const float* __restrict__ Wt,
                       const float* __restrict__ b1, const float* __restrict__ b2) {
    float* buf = d_buf;
    __nv_bfloat16* WxS = (__nv_bfloat16*)(buf + OFF_WXS);
    __nv_bfloat16* WhS = (__nv_bfloat16*)(buf + OFF_WHS);
    __nv_bfloat16* WyS = (__nv_bfloat16*)(buf + OFF_WYS);
    __nv_bfloat16* WhA = (__nv_bfloat16*)(buf + OFF_WHA);
    __nv_bfloat16* WcS = (__nv_bfloat16*)(buf + OFF_WCS);
    float* bP = buf + OFF_BP;

    const size_t R1 = 2ull * G4_ * KPX;
    const size_t R2 = 2ull * G4_ * H_;
    const size_t R3 = (size_t)H_ * H_;
    const size_t R4 = (size_t)H_ * H_;
    const size_t R5 = 2ull * H_ * H_;
    const size_t R6 = 2ull * G4_;
    const size_t R7 = OFF_WYY - OFF_H;
    const size_t R8 = OFF_RL - OFF_RB;
    const size_t R9 = 4ull * B_ * T_ * H_;
    const size_t R10 = 16;
    const size_t TOT = R1 + R2 + R3 + R4 + R5 + R6 + R7 + R8 + R9 + R10;
    size_t stride = (size_t)gridDim.x * blockDim.x;
    for (size_t id = (size_t)blockIdx.x * blockDim.x + threadIdx.x; id < TOT; id += stride) {
        size_t i = id;
        if (i < R1) {
            int w = (int)(i / ((size_t)G4_ * KPX));
            size_t rem = i % ((size_t)G4_ * KPX);
            int np = (int)(rem / KPX), k = (int)(rem % KPX);
            int col = (np & 3) * H_ + (np >> 2);
            const float* W = w ? W2 : W1;
            float v = (k < D_) ? W[(size_t)k * G4_ + col] : 0.f;
            size_t o = ((size_t)(w * 2) * G4_ + np) * KPX + k;
            split_store(v, WxS + o, WxS + o + (size_t)G4_ * KPX);
            continue;
        }
        i -= R1;
        if (i < R2) {
            int w = (int)(i / ((size_t)G4_ * H_));
            size_t rem = i % ((size_t)G4_ * H_);
            int np = (int)(rem / H_), k = (int)(rem % H_);
            int col = (np & 3) * H_ + (np >> 2);
            const float* W = w ? W2 : W1;
            float v = W[(size_t)(D_ + k) * G4_ + col];
            size_t o = ((size_t)(w * 2) * G4_ + np) * H_ + k;
            split_store(v, WhS + o, WhS + o + (size_t)G4_ * H_);
            continue;
        }
        i -= R2;
        if (i < R3) {
            int n = (int)(i / H_), k = (int)(i % H_);
            size_t o = (size_t)n * H_ + k;
            split_store(Wy[(size_t)k * H_ + n], WyS + o, WyS + o + (size_t)H_ * H_);
            continue;
        }
        i -= R3;
        if (i < R4) {
            int n = (int)(i / H_), k = (int)(i % H_);
            size_t o = (size_t)n * H_ + k;
            split_store(Wh[(size_t)k * H_ + n], WhA + o, WhA + o + (size_t)H_ * H_);
            continue;
        }
        i -= R4;
        if (i < R5) {
            int n = (int)(i / H_), k = (int)(i % H_);
            float v = (n < H_) ? Wr[(size_t)k * H_ + n] : Wt[(size_t)k * H_ + (n - H_)];
            size_t o = (size_t)n * H_ + k;
            split_store(v, WcS + o, WcS + o + 2ull * H_ * H_);
            continue;
        }
        i -= R5;
        if (i < R6) {
            int w = (int)(i / G4_), np = (int)(i % G4_);
            int col = (np & 3) * H_ + (np >> 2);
            bP[i] = (w ? b2 : b1)[col];
            continue;
        }
        i -= R6;
        if (i < R7) { (buf + OFF_H)[i] = 0.f; continue; }
        i -= R7;
        if (i < R8) { (buf + OFF_RB)[i] = 0.f; continue; }
        i -= R8;
        if (i < R9) { (buf + OFF_Y)[i] = 0.f; continue; }
        i -= R9;
        ((int*)(buf + OFF_META))[M_SYNC + i] = 0;
    }
}

// ---------------- sort + row lists ----------------
__global__ void __launch_bounds__(256) k_sort(const int* __restrict__ s1,
                                              const int* __restrict__ s2) {
    int* meta = (int*)(d_buf + OFF_META);
    int tid = threadIdx.x;
    __shared__ int sl[2][128];
    __shared__ int sl2s[256];
    __shared__ int cntA[256];
    __shared__ int totA;
    if (tid < 128) { sl[0][tid] = s1[tid]; sl[1][tid] = s2[tid]; }
    __syncthreads();
    {
        int c = tid >> 7, i = tid & 127;
        int v = sl[c][i], r = 0;
        for (int j = 0; j < 128; j++) {
            int u = sl[c][j];
            if (u > v || (u == v && j < i)) r++;
        }
        meta[(c ? M_PERM1 : M_PERM0) + r] = i;
        meta[(c ? M_IPOS1 : M_IPOS0) + i] = r;
        meta[(c ? M_SLS1  : M_SLS0)  + r] = v;
    }
    if (tid < 128) {
        int c = tid >> 6, t = tid & 63;
        int cnt = 0;
        for (int i = 0; i < 128; i++) cnt += (sl[c][i] > t);
        meta[(c ? M_MCNT1 : M_MCNT0) + t] = cnt;
    }
    {
        int a = tid >> 7, b = tid & 127;
        sl2s[tid] = a ? sl[0][b] : sl[1][b];
    }
    __syncthreads();
    {
        int v = sl2s[tid], r = 0;
        for (int j = 0; j < 256; j++) {
            int u = sl2s[j];
            if (u > v || (u == v && j < tid)) r++;
        }
        meta[M_PERM2 + r] = tid;
    }
    if (tid < 64) {
        int cnt = 0;
        for (int j = 0; j < 256; j++) cnt += (sl2s[j] > tid);
        meta[M_MCNT2 + tid] = cnt;
    }
    for (int c = 0; c < 2; c++) {
        int base = c ? M_ROWL1 : M_ROWL0;
        int myA = 0;
        for (int k = 0; k < 32; k++) {
            int row = tid * 32 + k;
            myA += ((row & 63) < sl[c][row >> 6]);
        }
        __syncthreads();
        cntA[tid] = myA;
        __syncthreads();
        if (tid == 0) {
            int s = 0;
            for (int i = 0; i < 256; i++) { int v = cntA[i]; cntA[i] = s; s += v; }
            totA = s;
            meta[M_NACT + c] = s;
        }
        __syncthreads();
        int pa = cntA[tid];
        int pd = totA + (tid * 32 - pa);
        for (int k = 0; k < 32; k++) {
            int row = tid * 32 + k;
            if ((row & 63) < sl[c][row >> 6]) meta[base + pa++] = row;
            else                              meta[base + pd++] = row;
        }
        __syncthreads();
    }
}

__global__ void k_gather(float* __restrict__ e, const int* __restrict__ t1,
                         const int* __restrict__ t2, const float* __restrict__ emb) {
    size_t total = 2ull * B_ * T_ * KPX;
    size_t stride = (size_t)gridDim.x * blockDim.x;
    for (size_t i = (size_t)blockIdx.x * blockDim.x + threadIdx.x; i < total; i += stride) {
        int which = (int)(i / ((size_t)B_ * T_ * KPX));
        size_t rem = i % ((size_t)B_ * T_ * KPX);
        int bt = (int)(rem / KPX), k = (int)(rem % KPX);
        int tok = (which ? t2 : t1)[bt];
        e[i] = (k < D_) ? emb[(size_t)tok * D_ + k] : 0.f;
    }
}

// ---------------------------------------------------------------------------
// bulk GEMM engine (unchanged from R10)
// ---------------------------------------------------------------------------
__device__ __forceinline__ void gemm_k(
    const float* __restrict__ Ag, const __nv_bfloat16* __restrict__ Bhg,
    const __nv_bfloat16* __restrict__ Blg, int nch,
    char* smem_raw, uint32_t sb,
    uint32_t aSt, uint32_t bSt, uint32_t aLd, uint32_t bLd,
    int wid, float acc[4][4][4]) {
    float fA[16];
    {
#pragma unroll
        for (int q = 0; q < 4; q++) {
            CP_ASYNC16(sb + B_BASE(0, 0) + bSt + q * 16, Bhg + q * 8);
            CP_ASYNC16(sb + B_BASE(1, 0) + bSt + q * 16, Blg + q * 8);
        }
        CP_COMMIT();
        const float4* s4 = (const float4*)Ag;
#pragma unroll
        for (int q = 0; q < 4; q++) {
            float4 v = __ldcg(s4 + q);
            fA[4 * q] = v.x; fA[4 * q + 1] = v.y; fA[4 * q + 2] = v.z; fA[4 * q + 3] = v.w;
        }
        ushort hi[16], lo[16];
#pragma unroll
        for (int q = 0; q < 16; q++) {
            __nv_bfloat16 hb = __float2bfloat16_rn(fA[q]);
            __nv_bfloat16 lb = __float2bfloat16_rn(fA[q] - __bfloat162float(hb));
            hi[q] = *(ushort*)&hb; lo[q] = *(ushort*)&lb;
        }
        *(uint4*)(smem_raw + A_BASE(0, 0) + aSt)      = *(uint4*)(hi);
        *(uint4*)(smem_raw + A_BASE(0, 0) + aSt + 16) = *(uint4*)(hi + 8);
        *(uint4*)(smem_raw + A_BASE(1, 0) + aSt)      = *(uint4*)(lo);
        *(uint4*)(smem_raw + A_BASE(1, 0) + aSt + 16) = *(uint4*)(lo + 8);
        CP_WAIT0();
        __syncthreads();
    }
    for (int ch = 0; ch < nch; ch++) {
        int s = ch & 1, ns = s ^ 1;
        bool more = (ch + 1) < nch;
        if (more) {
            const __nv_bfloat16* bh2 = Bhg + (ch + 1) * KC;
            const __nv_bfloat16* bl2 = Blg + (ch + 1) * KC;
#pragma unroll
            for (int q = 0; q < 4; q++) {
                CP_ASYNC16(sb + B_BASE(0, ns) + bSt + q * 16, bh2 + q * 8);
                CP_ASYNC16(sb + B_BASE(1, ns) + bSt + q * 16, bl2 + q * 8);
            }
            CP_COMMIT();
            const float4* s4 = (const float4*)(Ag + (ch + 1) * KC);
#pragma unroll
            for (int q = 0; q < 4; q++) {
                float4 v = __ldcg(s4 + q);
                fA[4 * q] = v.x; fA[4 * q + 1] = v.y; fA[4 * q + 2] = v.z; fA[4 * q + 3] = v.w;
            }
        }
#pragma unroll
        for (int h16 = 0; h16 < 2; h16++) {
            uint32_t kb = (uint32_t)h16 * 32;
            uint32_t bh[8], bl[8];
#pragma unroll
            for (int g2 = 0; g2 < 2; g2++) {
                uint32_t rowb = (uint32_t)((wid * 32 + g2 * 16) * PAD) * 2;
                LDSM4(bh[g2 * 4 + 0], bh[g2 * 4 + 1], bh[g2 * 4 + 2], bh[g2 * 4 + 3],
                      sb + B_BASE(0, s) + bLd + rowb + kb);
                LDSM4(bl[g2 * 4 + 0], bl[g2 * 4 + 1], bl[g2 * 4 + 2], bl[g2 * 4 + 3],
                      sb + B_BASE(1, s) + bLd + rowb + kb);
            }
#pragma unroll
            for (int mt = 0; mt < 4; mt++) {
                uint32_t ah[4], al[4];
                uint32_t rowa = (uint32_t)(mt * 16 * PAD) * 2;
                LDSM4(ah[0], ah[1], ah[2], ah[3], sb + A_BASE(0, s) + aLd + rowa + kb);
                LDSM4(al[0], al[1], al[2], al[3], sb + A_BASE(1, s) + aLd + rowa + kb);
#pragma unroll
                for (int nt = 0; nt < 4; nt++) {
                    int bi = (nt >> 1) * 4 + (nt & 1) * 2;
                    MMA16816(acc[mt][nt], ah, bh[bi], bh[bi + 1]);
                    MMA16816(acc[mt][nt], ah, bl[bi], bl[bi + 1]);
                    MMA16816(acc[mt][nt], al, bh[bi], bh[bi + 1]);
                }
            }
        }
        if (more) {
            ushort hi[16], lo[16];
#pragma unroll
            for (int q = 0; q < 16; q++) {
                __nv_bfloat16 hb = __float2bfloat16_rn(fA[q]);
                __nv_bfloat16 lb = __float2bfloat16_rn(fA[q] - __bfloat162float(hb));
                hi[q] = *(ushort*)&hb; lo[q] = *(ushort*)&lb;
            }
            *(uint4*)(smem_raw + A_BASE(0, ns) + aSt)      = *(uint4*)(hi);
            *(uint4*)(smem_raw + A_BASE(0, ns) + aSt + 16) = *(uint4*)(hi + 8);
            *(uint4*)(smem_raw + A_BASE(1, ns) + aSt)      = *(uint4*)(lo);
            *(uint4*)(smem_raw + A_BASE(1, ns) + aSt + 16) = *(uint4*)(lo + 8);
            CP_WAIT0();
        }
        __syncthreads();
    }
}

struct MZ {
    const float*         A;
    const __nv_bfloat16* Bhi;
    const __nv_bfloat16* Blo;
    float*               C;
    const float*         bias;
    const int*           rows;
    const int*           nactp;
};
struct MP {
    MZ z[4];
    int Klen, lda, ldb, ldc;
};

__global__ void __launch_bounds__(128) mm_gemm(MP p) {
    extern __shared__ __align__(16) char smem_raw[];
    uint32_t sb = smem_u32(smem_raw);
    const MZ z = p.z[blockIdx.z];
    int tid = threadIdx.x, lane = tid & 31, wid = tid >> 5;
    int n0 = blockIdx.x * TN, m0 = blockIdx.y * TM;

    if (z.rows && m0 >= __ldg(z.nactp)) return;

    int arow = z.rows ? __ldg(z.rows + m0 + (tid >> 1)) : (m0 + (tid >> 1));
    const float*         Ag  = z.A   + (size_t)arow * p.lda + (tid & 1) * 16;
    const __nv_bfloat16* Bhg = z.Bhi + (size_t)(n0 + tid) * p.ldb;
    const __nv_bfloat16* Blg = z.Blo + (size_t)(n0 + tid) * p.ldb;
    uint32_t aSt = (uint32_t)((tid >> 1) * PAD + (tid & 1) * 16) * 2;
    uint32_t bSt = (uint32_t)(tid * PAD) * 2;
    uint32_t aLd = (uint32_t)((lane & 15) * PAD + ((lane >> 4) << 3)) * 2;
    uint32_t bLd = (uint32_t)(((lane & 7) + ((lane & 16) >> 1)) * PAD + (lane & 8)) * 2;

    float acc[4][4][4] = {};
    gemm_k(Ag, Bhg, Blg, p.Klen / KC, smem_raw, sb, aSt, bSt, aLd, bLd, wid, acc);

#pragma unroll
    for (int mt = 0; mt < 4; mt++) {
        int r = m0 + mt * 16 + (lane >> 2);
        int r0 = z.rows ? __ldg(z.rows + r) : r;
        int r1 = z.rows ? __ldg(z.rows + r + 8) : (r + 8);
#pragma unroll
        for (int nt = 0; nt < 4; nt++) {
            int c = n0 + wid * 32 + nt * 8 + (lane & 3) * 2;
            float b0 = 0.f, b1 = 0.f;
            if (z.bias) { b0 = z.bias[c]; b1 = z.bias[c + 1]; }
            *(float2*)(z.C + (size_t)r0 * p.ldc + c) =
                make_float2(acc[mt][nt][0] + b0, acc[mt][nt][1] + b1);
            *(float2*)(z.C + (size_t)r1 * p.ldc + c) =
                make_float2(acc[mt][nt][2] + b0, acc[mt][nt][3] + b1);
        }
    }
}

// ---------------------------------------------------------------------------
// Persistent LSTM scan: 256 threads / 8 warps. Warps split mt (interleaved),
// share one A/B smem pipeline. Wh resident. Sorted batches, frag skipping.
// ---------------------------------------------------------------------------
__global__ void __launch_bounds__(256) k_lstm_persist() {
    extern __shared__ __align__(16) char smem[];
    uint32_t sb = smem_u32(smem);
    float* buf = d_buf;
    int* meta = (int*)(buf + OFF_META);
    int tid = threadIdx.x, lane = tid & 31, wid = tid >> 5;
    int wg_n = wid & 3, wg_m = wid >> 2;
    int blk = blockIdx.x;
    int r = blk >> 5, nt_ = blk & 31;
    int n0 = nt_ * 64;
    int widx = (r == 0 || r == 2) ? 0 : 1;
    int cls  = (r == 0 || r == 3) ? 0 : 1;
    const int* permc = meta + (cls ? M_PERM1 : M_PERM0);
    const int* slsrt = meta + (cls ? M_SLS1  : M_SLS0);
    const int* mcnt  = meta + (cls ? M_MCNT1 : M_MCNT0);

    // resident Wh slab: 64 rows x 512 K x {hi,lo}
    {
        const __nv_bfloat16* WhS = (const __nv_bfloat16*)(buf + OFF_WHS);
        int tau = tid >> 7, q2 = tid & 127;
        int n = q2 >> 1, half = q2 & 1;
        const __nv_bfloat16* src = WhS + (size_t)(widx * 2 + tau) * G4_ * H_
                                   + (size_t)(n0 + n) * H_ + half * 256;
        uint32_t dst = sb + (uint32_t)tau * 66560u + (uint32_t)n * 1040u + (uint32_t)half * 512u;
#pragma unroll
        for (int q = 0; q < 32; q++) CP_ASYNC16(dst + q * 16, src + q * 8);
        CP_COMMIT(); CP_WAIT0(); __syncthreads();
    }

    const float* Xg  = buf + OFF_XG + (size_t)r * B_ * T_ * G4_;
    float*       cst = buf + OFF_C + (size_t)r * B_ * H_;
    float*       Yst = buf + OFF_Y + (size_t)r * B_ * T_ * H_;
    float*       hB  = buf + OFF_H;
    __nv_bfloat16* HBb = (__nv_bfloat16*)(buf + OFF_HB);
    unsigned* sync = (unsigned*)(meta + M_SYNC);
    const size_t HBUF = 4ull * B_ * H_;

    uint32_t aLd   = (uint32_t)((lane & 15) * 40 + ((lane >> 4) << 3)) * 2;
    uint32_t bBase = (uint32_t)(wg_n * 16) * 1040u
                   + (uint32_t)(((lane & 7) + ((lane & 16) >> 1)) * 520 + (lane & 8)) * 2;

    for (int t = 0; t < T_; t++) {
        int mcur  = __ldg(mcnt + t);
        int mtmax = (mcur + 15) >> 4;
        int ppi = t & 1, ppo = ppi ^ 1;
        const float* hin  = hB + (size_t)ppi * HBUF + (size_t)r * B_ * H_;
        float*       hout = hB + (size_t)ppo * HBUF + (size_t)r * B_ * H_;
        const __nv_bfloat16* Ain = HBb + (size_t)ppi * 2 * P_HB + (size_t)r * B_ * H_;
        __nv_bfloat16*       ho  = HBb + (size_t)ppo * 2 * P_HB + (size_t)r * B_ * H_;

        float acc[4][2][4] = {};   // k (mt=2k+wg_m) x nt x frag
        if (mtmax > 0) {
            int nrows = mtmax << 4;
            auto issueA = [&](int ch, int slot) {
                int tau = tid >> 7, row = tid & 127;
                if (row < nrows) {
                    const __nv_bfloat16* src = Ain + (size_t)tau * P_HB + (size_t)row * H_ + ch * 32;
                    uint32_t dst = sb + 133120u + (uint32_t)slot * 20480u
                                 + (uint32_t)tau * 10240u + (uint32_t)row * 80u;
                    CP_ASYNC16(dst,      src);
                    CP_ASYNC16(dst + 16, src + 8);
                    CP_ASYNC16(dst + 32, src + 16);
                    CP_ASYNC16(dst + 48, src + 24);
                }
                CP_COMMIT();
            };
            issueA(0, 0); issueA(1, 1);
            for (int ch = 0; ch < 16; ch++) {
                if (ch == 15) { CP_WAIT0(); } else { CP_WAIT1(); }
                __syncthreads();
                if (ch + 2 < 16) issueA(ch + 2, (ch + 2) % 3);
                uint32_t abase = sb + 133120u + (uint32_t)(ch % 3) * 20480u;
#pragma unroll
                for (int h16 = 0; h16 < 2; h16++) {
                    uint32_t kb = (uint32_t)(ch * 32 + h16 * 16) * 2;
                    uint32_t bA[4], bB[4];
                    LDSM4(bA[0], bA[1], bA[2], bA[3], sb + bBase + kb);
                    LDSM4(bB[0], bB[1], bB[2], bB[3], sb + 66560u + bBase + kb);
#pragma unroll
                    for (int k = 0; k < 4; k++) {
                        int mt = 2 * k + wg_m;
                        if (mt < mtmax) {
                            uint32_t ah[4], al[4];
                            uint32_t rowa = (uint32_t)(mt * 16 * 80);
                            LDSM4(ah[0], ah[1], ah[2], ah[3], abase + aLd + rowa + h16 * 32);
                            LDSM4(al[0], al[1], al[2], al[3], abase + 10240u + aLd + rowa + h16 * 32);
                            MMA16816(acc[k][0], ah, bA[0], bA[1]);
                            MMA16816(acc[k][0], ah, bB[0], bB[1]);
                            MMA16816(acc[k][0], al, bA[0], bA[1]);
                            MMA16816(acc[k][1], ah, bA[2], bA[3]);
                            MMA16816(acc[k][1], ah, bB[2], bB[3]);
                            MMA16816(acc[k][1], al, bA[2], bA[3]);
                        }
                    }
                }
            }
        }

        // epilogue: active mts owned by this warp
#pragma unroll
        for (int k = 0; k < 4; k++) {
            int mt = 2 * k + wg_m;
            if (mt < mtmax) {
                int b = mt * 16 + (lane >> 2);
#pragma unroll
                for (int nt = 0; nt < 2; nt++) {
                    float fo0 = __shfl_xor_sync(0xffffffffu, acc[k][nt][0], 1);
                    float fo1 = __shfl_xor_sync(0xffffffffu, acc[k][nt][1], 1);
                    float fo2 = __shfl_xor_sync(0xffffffffu, acc[k][nt][2], 1);
                    float fo3 = __shfl_xor_sync(0xffffffffu, acc[k][nt][3], 1);
                    if (!(lane & 1)) {
#pragma unroll
                        for (int half = 0; half < 2; half++) {
                            int bb = b + half * 8;
                            float gi = half ? acc[k][nt][2] : acc[k][nt][0];
                            float gj = half ? acc[k][nt][3] : acc[k][nt][1];
                            float gf = half ? fo2 : fo0;
                            float go = half ? fo3 : fo1;
                            int c0 = n0 + wg_n * 16 + nt * 8 + (lane & 3) * 2;
                            int j = c0 >> 2;
                            size_t ci = (size_t)bb * H_ + j;
                            int slv = __ldg(slsrt + bb);
                            float hv;
                            if (t < slv) {
                                int ob = __ldg(permc + bb);
                                float4 x = *(const float4*)(Xg + ((size_t)ob * T_ + t) * G4_ + c0);
                                gi += x.x; gj += x.y; gf += x.z; go += x.w;
                                float cc = cst[ci];
                                float cn = cc * sigf(gf + 1.f) + sigf(gi) * ftanh(gj);
                                hv = ftanh(cn) * sigf(go);
                                cst[ci] = cn;
                                Yst[((size_t)ob * T_ + t) * H_ + j] = hv;
                            } else {
                                hv = __ldcg(hin + ci);
                            }
                            hout[ci] = hv;
                            split_store(hv, ho + ci, ho + P_HB + ci);
                        }
                    }
                }
            }
        }
        // frozen copies: all 256 threads, 1 elem per thread per mt
        for (int mt = mtmax; mt < 8; mt++) {
            int rr = mt * 16 + (tid >> 4);
            int jj = (n0 >> 2) + (tid & 15);
            size_t ci = (size_t)rr * H_ + jj;
            float hv = __ldcg(hin + ci);
            hout[ci] = hv;
            ho[ci]        = Ain[ci];
            ho[P_HB + ci] = Ain[P_HB + ci];
        }
        gbar(sync + 0, sync + 1, (unsigned)(t + 1), 128u);
    }
}

// ---------------------------------------------------------------------------
// Persistent attention scan: 256 threads / 8 warps, Wc resident, sorted pairs.
// ---------------------------------------------------------------------------
__global__ void __launch_bounds__(256) k_att_persist(
    const float* __restrict__ wv,
    const int* __restrict__ s1, const int* __restrict__ s2) {
    extern __shared__ __align__(16) char smem[];
    uint32_t sb = smem_u32(smem);
    float* smf = (float*)(smem + 69632);
    float* buf = d_buf;
    int* meta = (int*)(buf + OFF_META);
    int tid = threadIdx.x, lane = tid & 31, wid = tid >> 5;
    int wg_n = wid & 3, wg_m = wid >> 2;
    int blk = blockIdx.x;

    int ks  = blk & 3;
    int mt_ = (blk >> 2) & 3;
    int nt_ = blk >> 4;
    int m0 = mt_ * 64, n0 = nt_ * 128, kst = ks * 128;

    // resident Wc slab: 128 rows x 128 K x {hi,lo}
    {
        const __nv_bfloat16* WcS = (const __nv_bfloat16*)(buf + OFF_WCS);
        int tau = tid >> 7, row = tid & 127;
        const __nv_bfloat16* src = WcS + (size_t)tau * 2 * H_ * H_
                                   + (size_t)(n0 + row) * H_ + kst;
        uint32_t dst = sb + (uint32_t)tau * 34816u + (uint32_t)row * 272u;
#pragma unroll
        for (int q = 0; q < 16; q++) CP_ASYNC16(dst + q * 16, src + q * 8);
        CP_COMMIT(); CP_WAIT0(); __syncthreads();
    }

    __nv_bfloat16* RBb = (__nv_bfloat16*)(buf + OFF_RB);
    float* uPt4 = buf + OFF_UPT;
    float* rL   = buf + OFF_RL;
    const float* WyY = buf + OFF_WYY;
    const float* HWy = buf + OFF_HWY;
    const float* Yb  = buf + OFF_Y;
    unsigned* sync = (unsigned*)(meta + M_SYNC);
    const int* mcnt2 = meta + M_MCNT2;

    uint32_t aLd = (uint32_t)((lane & 15) * 40 + ((lane >> 4) << 3)) * 2;
    uint32_t bLd = (uint32_t)(((lane & 7) + ((lane & 16) >> 1)) * 136 + (lane & 8)) * 2;

    float wvr[16];
#pragma unroll
    for (int k = 0; k < 16; k++) wvr[k] = __ldg(wv + lane + 32 * k);

    int spA = blk * 2, spB = blk * 2 + 1;
    int pA = meta[M_PERM2 + spA], pB = meta[M_PERM2 + spB];
    int aA = pA >> 7, bA = pA & 127;
    int aB = pB >> 7, bB = pB & 127;
    int sl2A = aA ? s1[bA] : s2[bA];
    int sl2B = aB ? s1[bB] : s2[bB];
    int slmA = aA ? s2[bA] : s1[bA];
    int slmB = aB ? s2[bB] : s1[bB];

    for (int t = 0; t < T_; t++) {
        int mcur2 = __ldg(mcnt2 + t);
        int mtloc = 0;
        if (mcur2 > m0) { mtloc = (mcur2 - m0 + 15) >> 4; if (mtloc > 4) mtloc = 4; }

        if (mtloc > 0) {
            int nrows = mtloc << 4;
            auto issueA = [&](int ch, int slot) {
                int row = tid >> 1, tau = tid & 1;
                if (tid < 128 && row < nrows) {
                    const __nv_bfloat16* src = RBb + (size_t)tau * P_RB
                                               + (size_t)(m0 + row) * H_ + kst + ch * 32;
                    uint32_t dst = sb + 69632u + (uint32_t)slot * 10240u
                                 + (uint32_t)tau * 5120u + (uint32_t)row * 80u;
                    CP_ASYNC16(dst,      src);
                    CP_ASYNC16(dst + 16, src + 8);
                    CP_ASYNC16(dst + 32, src + 16);
                    CP_ASYNC16(dst + 48, src + 24);
                }
                CP_COMMIT();
            };
            issueA(0, 0); issueA(1, 1);
            float acc[2][4][4] = {};
            for (int ch = 0; ch < 4; ch++) {
                if (ch == 3) { CP_WAIT0(); } else { CP_WAIT1(); }
                __syncthreads();
                if (ch + 2 < 4) issueA(ch + 2, (ch + 2) % 3);
                uint32_t abase = sb + 69632u + (uint32_t)(ch % 3) * 10240u;
#pragma unroll
                for (int h16 = 0; h16 < 2; h16++) {
                    uint32_t kb = (uint32_t)(ch * 32 + h16 * 16) * 2;
                    uint32_t bh[8], bl[8];
#pragma unroll
                    for (int g2 = 0; g2 < 2; g2++) {
                        uint32_t rowb = (uint32_t)((wg_n * 32 + g2 * 16) * 136) * 2;
                        LDSM4(bh[g2 * 4 + 0], bh[g2 * 4 + 1], bh[g2 * 4 + 2], bh[g2 * 4 + 3],
                              sb + bLd + rowb + kb);
                        LDSM4(bl[g2 * 4 + 0], bl[g2 * 4 + 1], bl[g2 * 4 + 2], bl[g2 * 4 + 3],
                              sb + 34816u + bLd + rowb + kb);
                    }
#pragma unroll
                    for (int k = 0; k < 2; k++) {
                        int mt = 2 * k + wg_m;
                        if (mt < mtloc) {
                            uint32_t ah[4], al[4];
                            uint32_t rowa = (uint32_t)(mt * 16 * 80);
                            LDSM4(ah[0], ah[1], ah[2], ah[3], abase + aLd + rowa + h16 * 32);
                            LDSM4(al[0], al[1], al[2], al[3], abase + 5120u + aLd + rowa + h16 * 32);
#pragma unroll
                            for (int nt = 0; nt < 4; nt++) {
                                int bi = (nt >> 1) * 4 + (nt & 1) * 2;
                                MMA16816(acc[k][nt], ah, bh[bi], bh[bi + 1]);
                                MMA16816(acc[k][nt], ah, bl[bi], bl[bi + 1]);
                                MMA16816(acc[k][nt], al, bh[bi], bh[bi + 1]);
                            }
                        }
                    }
                }
            }
            float* Cb = uPt4 + (size_t)ks * 256 * 1024;
#pragma unroll
            for (int k = 0; k < 2; k++) {
                int mt = 2 * k + wg_m;
                if (mt < mtloc) {
                    int rr = m0 + mt * 16 + (lane >> 2);
#pragma unroll
                    for (int nt = 0; nt < 4; nt++) {
                        int c = n0 + wg_n * 32 + nt * 8 + (lane & 3) * 2;
                        *(float2*)(Cb + (size_t)rr * 1024 + c) =
                            make_float2(acc[k][nt][0], acc[k][nt][1]);
                        *(float2*)(Cb + (size_t)(rr + 8) * 1024 + c) =
                            make_float2(acc[k][nt][2], acc[k][nt][3]);
                    }
                }
            }
        }
        gbar(sync + 2, sync + 3, (unsigned)(2 * t + 1), 128u);

        // phase A: two sorted pairs, exact skipping, 8 warps
        for (int pi = 0; pi < 2; pi++) {
            int sp   = pi ? spB : spA;
            int p    = pi ? pB : pA;
            int a    = pi ? aB : aA;
            int b    = pi ? bB : bA;
            int sl2  = pi ? sl2B : sl2A;
            int slm  = pi ? slmB : slmA;
            if (t >= sl2) continue;

            float* su  = smf;
            float* spt = smf + 512;
            float* sc  = smf + 1024;
            const float* hb = HWy + (size_t)a * B_ * T_ * H_ + ((size_t)b * T_ + t) * H_;
#pragma unroll
            for (int q = 0; q < 2; q++) {
                int h = tid + q * 256;
                float s0 = 0.f, s1v = 0.f;
#pragma unroll
                for (int k = 0; k < 4; k++) {
                    const float* up = uPt4 + ((size_t)k * 256 + sp) * 1024;
                    s0  += __ldcg(up + h);
                    s1v += __ldcg(up + 512 + h);
                }
                su[h]  = s0 + __ldg(hb + h);
                spt[h] = s1v;
            }
            __syncthreads();
            const float* WyYb = WyY + (size_t)a * B_ * T_ * H_ + (size_t)b * T_ * H_;
#pragma unroll
            for (int q = 0; q < 8; q++) {
                int t2 = wid * 8 + q;
                if (t2 < slm) {
                    const float* row = WyYb + (size_t)t2 * H_;
                    float s = 0.f;
#pragma unroll
                    for (int k = 0; k < 16; k++) {
                        int hh = lane + 32 * k;
                        s += tanha(__ldg(row + hh) + su[hh]) * wvr[k];
                    }
                    for (int o = 16; o; o >>= 1) s += __shfl_xor_sync(0xffffffffu, s, o);
                    if (lane == 0) sc[t2] = s;
                } else if (lane == 0) {
                    sc[t2] = -10000.f;
                }
            }
            __syncthreads();
            if (wid == 0) {
                float v1 = sc[lane], v2 = sc[lane + 32];
                float m = fmaxf(v1, v2);
                for (int o = 16; o; o >>= 1) m = fmaxf(m, __shfl_xor_sync(0xffffffffu, m, o));
                float e1 = __expf(v1 - m), e2 = __expf(v2 - m);
                float s = e1 + e2;
                for (int o = 16; o; o >>= 1) s += __shfl_xor_sync(0xffffffffu, s, o);
                float inv = __fdividef(1.f, s);
                sc[lane] = e1 * inv;
                sc[lane + 32] = e2 * inv;
            }
            __syncthreads();
            const float* Yp = Yb + (size_t)(a ? 2 : 0) * B_ * T_ * H_ + (size_t)b * T_ * H_;
#pragma unroll
            for (int q = 0; q < 2; q++) {
                int h = tid + q * 256;
                float accv = 0.f;
                for (int t2 = 0; t2 < slm; t2++)
                    accv += sc[t2] * __ldg(Yp + (size_t)t2 * H_ + h);
                float rn = accv + ftanh(spt[h]);
                if (t == sl2 - 1) {
                    rL[(size_t)p * H_ + h] = rn;
                } else {
                    split_store(rn, RBb + (size_t)sp * H_ + h, RBb + P_RB + (size_t)sp * H_ + h);
                }
            }
            __syncthreads();
        }
        gbar(sync + 2, sync + 3, (unsigned)(2 * t + 2), 128u);
    }
}

// ---------------- final projection ----------------
__global__ void __launch_bounds__(512) k_final(
    const float* __restrict__ rL, const float* __restrict__ hfin,
    const float* __restrict__ Wp, const float* __restrict__ Wx,
    const float* __restrict__ U, const float* __restrict__ bU,
    float* __restrict__ out) {
    int b = blockIdx.x;
    int tid = threadIdx.x;
    const int* meta = (const int*)(d_buf + OFF_META);
    int ip1 = meta[M_IPOS1 + b];
    int ip0 = meta[M_IPOS0 + b];
    __shared__ float s_in[4][512];
    __shared__ float s_sum[512];
    __shared__ float red0[16], red1[16];
    s_in[0][tid] = rL[(size_t)b * H_ + tid];
    s_in[1][tid] = hfin[((size_t)1 * B_ + ip1) * H_ + tid];
    s_in[2][tid] = rL[((size_t)B_ + b) * H_ + tid];
    s_in[3][tid] = hfin[((size_t)3 * B_ + ip0) * H_ + tid];
    __syncthreads();
    float acc0 = 0.f, acc1 = 0.f;
    for (int k = 0; k < H_; k++) {
        float wp = Wp[(size_t)k * H_ + tid];
        float wx = Wx[(size_t)k * H_ + tid];
        acc0 += s_in[0][k] * wp + s_in[1][k] * wx;
        acc1 += s_in[2][k] * wp + s_in[3][k] * wx;
    }
    s_sum[tid] = ftanh(acc0) + ftanh(acc1);
    __syncthreads();
    float p0 = s_sum[tid] * U[(size_t)tid * 2 + 0];
    float p1 = s_sum[tid] * U[(size_t)tid * 2 + 1];
    for (int o = 16; o; o >>= 1) {
        p0 += __shfl_xor_sync(0xffffffffu, p0, o);
        p1 += __shfl_xor_sync(0xffffffffu, p1, o);
    }
    int wp_ = tid >> 5;
    if ((tid & 31) == 0) { red0[wp_] = p0; red1[wp_] = p1; }
    __syncthreads();
    if (tid < 16) {
        p0 = red0[tid]; p1 = red1[tid];
        for (int o = 8; o; o >>= 1) {
            p0 += __shfl_xor_sync(0x0000ffffu, p0, o);
            p1 += __shfl_xor_sync(0x0000ffffu, p1, o);
        }
        if (tid == 0) {
            out[b * 2 + 0] = p0 + bU[0];
            out[b * 2 + 1] = p1 + bU[1];
        }
    }
}

// ---------------- host ----------------
extern "C" void kernel_launch(void* const* d_in, const int* in_sizes, int n_in,
                              void* d_out, int out_size) {
    (void)in_sizes; (void)n_in; (void)out_size;
    const int*   tokens1 = (const int*)d_in[0];
    const int*   tokens2 = (const int*)d_in[1];
    const int*   seqlen1 = (const int*)d_in[2];
    const int*   seqlen2 = (const int*)d_in[3];
    const float* emb = (const float*)d_in[4];
    const float* W1  = (const float*)d_in[5];
    const float* b1  = (const float*)d_in[6];
    const float* W2  = (const float*)d_in[7];
    const float* b2  = (const float*)d_in[8];
    const float* Wy  = (const float*)d_in[9];
    const float* Wh  = (const float*)d_in[10];
    const float* Wr  = (const float*)d_in[11];
    const float* wv  = (const float*)d_in[12];
    const float* Wt  = (const float*)d_in[13];
    const float* Wp  = (const float*)d_in[14];
    const float* Wx  = (const float*)d_in[15];
    const float* U   = (const float*)d_in[16];
    const float* bU  = (const float*)d_in[17];
    float* out = (float*)d_out;

    cudaFuncSetAttribute(mm_gemm, cudaFuncAttributeMaxDynamicSharedMemorySize, SMEM_MM);
    cudaFuncSetAttribute(k_lstm_persist, cudaFuncAttributeMaxDynamicSharedMemorySize, SMEM_LSTM);
    cudaFuncSetAttribute(k_att_persist, cudaFuncAttributeMaxDynamicSharedMemorySize, SMEM_ATT);

    float* buf = nullptr;
    cudaGetSymbolAddress((void**)&buf, d_buf);
    float* e    = buf + OFF_E;
    float* Xg   = buf + OFF_XG;
    float* Yb   = buf + OFF_Y;
    float* hBuf = buf + OFF_H;
    float* WyY  = buf + OFF_WYY;
    float* HWy  = buf + OFF_HWY;
    float* rL   = buf + OFF_RL;
    float* bP   = buf + OFF_BP;
    int*   meta = (int*)(buf + OFF_META);
    __nv_bfloat16* WxS = (__nv_bfloat16*)(buf + OFF_WXS);
    __nv_bfloat16* WyS = (__nv_bfloat16*)(buf + OFF_WYS);
    __nv_bfloat16* WhA = (__nv_bfloat16*)(buf + OFF_WHA);

    k_prep<<<2048, 256>>>(W1, W2, Wy, Wh, Wr, Wt, b1, b2);
    k_sort<<<1, 256>>>(seqlen1, seqlen2);
    k_gather<<<2048, 256>>>(e, tokens1, tokens2, emb);

    const int iidx[4] = {0, 1, 1, 0}, widx[4] = {0, 1, 0, 1};
    const int xcls[4] = {0, 1, 1, 0};

    // X GEMM: row-compacted
    {
        MP p = {};
        for (int r = 0; r < 4; r++) {
            p.z[r].A     = e + (size_t)iidx[r] * B_ * T_ * KPX;
            p.z[r].Bhi   = WxS + (size_t)(widx[r] * 2 + 0) * G4_ * KPX;
            p.z[r].Blo   = WxS + (size_t)(widx[r] * 2 + 1) * G4_ * KPX;
            p.z[r].C     = Xg + (size_t)r * B_ * T_ * G4_;
            p.z[r].bias  = bP + (size_t)widx[r] * G4_;
            p.z[r].rows  = meta + (xcls[r] ? M_ROWL1 : M_ROWL0);
            p.z[r].nactp = meta + M_NACT + xcls[r];
        }
        p.Klen = KPX; p.lda = KPX; p.ldb = KPX; p.ldc = G4_;
        mm_gemm<<<dim3(G4_ / TN, (B_ * T_) / TM, 4), 128, SMEM_MM>>>(p);
    }

    // persistent LSTM scan (256 threads, 8 warps)
    k_lstm_persist<<<128, 256, SMEM_LSTM>>>();

    // WyY + HWy: row-compacted
    {
        MP p = {};
        const int runs[4] = {0, 2, 1, 3};
        const int qcls[4] = {0, 1, 1, 0};
        for (int q = 0; q < 4; q++) {
            p.z[q].A     = Yb + (size_t)runs[q] * B_ * T_ * H_;
            p.z[q].Bhi   = (q < 2 ? WyS : WhA);
            p.z[q].Blo   = (q < 2 ? WyS : WhA) + (size_t)H_ * H_;
            p.z[q].C     = (q < 2 ? WyY + (size_t)q * B_ * T_ * H_
                                  : HWy + (size_t)(q - 2) * B_ * T_ * H_);
            p.z[q].bias  = nullptr;
            p.z[q].rows  = meta + (qcls[q] ? M_ROWL1 : M_ROWL0);
            p.z[q].nactp = meta + M_NACT + qcls[q];
        }
        p.Klen = H_; p.lda = H_; p.ldb = H_; p.ldc = H_;
        mm_gemm<<<dim3(H_ / TN, (B_ * T_) / TM, 4), 128, SMEM_MM>>>(p);
    }

    // persistent attention scan (256 threads, 8 warps)
    k_att_persist<<<128, 256, SMEM_ATT>>>(wv, seqlen1, seqlen2);

    k_final<<<B_, 512>>>(rL, hBuf, Wp, Wx, U, bU, out);
}

// round 12
// speedup vs baseline: 2.0608x; 1.2092x over previous
#include <cuda_runtime.h>
#include <cuda_bf16.h>
#include <math.h>
#include <stdint.h>

#define B_   128
#define T_   64
#define D_   300
#define KPX  320
#define H_   512
#define G4_  2048

// ---- bulk GEMM tile ----
#define TM 64
#define TN 128
#define KC 32
#define PAD 40
#define A_BASE(term,stage) ((uint32_t)(((term)*2+(stage))*5120))
#define B_BASE(term,stage) ((uint32_t)(20480u + ((term)*2+(stage))*10240u))
static constexpr int SMEM_MM   = 61440;
static constexpr int SMEM_LSTM = 133120 + 3 * 20480;   // 194560
static constexpr int SMEM_ATT  = 69632 + 3 * 10240;    // 100352

__device__ __forceinline__ uint32_t smem_u32(const void* p) {
    uint32_t a;
    asm("{ .reg .u64 t; cvta.to.shared.u64 t, %1; cvt.u32.u64 %0, t; }" : "=r"(a) : "l"(p));
    return a;
}
#define CP_ASYNC16(dst, src) \
    asm volatile("cp.async.cg.shared.global [%0], [%1], 16;" :: "r"(dst), "l"(src))
#define CP_COMMIT() asm volatile("cp.async.commit_group;" ::: "memory")
#define CP_WAIT0()  asm volatile("cp.async.wait_group 0;" ::: "memory")
#define CP_WAIT1()  asm volatile("cp.async.wait_group 1;" ::: "memory")
#define LDSM4(r0, r1, r2, r3, addr) \
    asm volatile("ldmatrix.sync.aligned.m8n8.x4.shared.b16 {%0,%1,%2,%3}, [%4];" \
                 : "=r"(r0), "=r"(r1), "=r"(r2), "=r"(r3) : "r"(addr))
#define MMA16816(c, a, b0, b1) \
    asm volatile("mma.sync.aligned.m16n8k16.row.col.f32.bf16.bf16.f32 " \
                 "{%0,%1,%2,%3}, {%4,%5,%6,%7}, {%8,%9}, {%0,%1,%2,%3};" \
                 : "+f"((c)[0]), "+f"((c)[1]), "+f"((c)[2]), "+f"((c)[3]) \
                 : "r"((a)[0]), "r"((a)[1]), "r"((a)[2]), "r"((a)[3]), \
                   "r"(b0), "r"(b1))

__device__ __forceinline__ float sigf(float x) { return __fdividef(1.f, 1.f + __expf(-x)); }
__device__ __forceinline__ float ftanh(float x) { return 1.f - __fdividef(2.f, __expf(2.f * x) + 1.f); }
__device__ __forceinline__ float tanha(float x) {
    float y; asm("tanh.approx.f32 %0, %1;" : "=f"(y) : "f"(x)); return y;
}

static constexpr size_t P_HB = 4ull * B_ * H_;
static constexpr size_t P_RB = 256ull * H_;

// ---------------- scratch layout (float units) ----------------
static constexpr size_t OFF_E    = 0;
static constexpr size_t OFF_XG   = OFF_E   + 2ull * B_ * T_ * KPX;
static constexpr size_t OFF_Y    = OFF_XG  + 4ull * B_ * T_ * G4_;
static constexpr size_t OFF_H    = OFF_Y   + 4ull * B_ * T_ * H_;
static constexpr size_t OFF_HB   = OFF_H   + 2ull * 4 * B_ * H_;
static constexpr size_t OFF_C    = OFF_HB  + (2ull * 2 * P_HB) / 2;
static constexpr size_t OFF_WYY  = OFF_C   + 4ull * B_ * H_;
static constexpr size_t OFF_HWY  = OFF_WYY + 2ull * B_ * T_ * H_;
static constexpr size_t OFF_UPT  = OFF_HWY + 2ull * B_ * T_ * H_;
static constexpr size_t OFF_RB   = OFF_UPT + 4ull * 256 * 1024;
static constexpr size_t OFF_RL   = OFF_RB  + (2ull * P_RB) / 2;
static constexpr size_t OFF_BP   = OFF_RL  + 256ull * H_;
static constexpr size_t OFF_WXS  = OFF_BP  + 2ull * G4_;
static constexpr size_t OFF_WHS  = OFF_WXS + (2ull * 2 * G4_ * KPX) / 2;
static constexpr size_t OFF_WYS  = OFF_WHS + (2ull * 2 * G4_ * H_) / 2;
static constexpr size_t OFF_WHA  = OFF_WYS + (2ull * H_ * H_) / 2;
static constexpr size_t OFF_WCS  = OFF_WHA + (2ull * H_ * H_) / 2;
static constexpr size_t OFF_META = OFF_WCS + (2ull * 2 * H_ * H_) / 2;
#define M_PERM0 0
#define M_PERM1 128
#define M_IPOS0 256
#define M_IPOS1 384
#define M_SLS0  512
#define M_SLS1  640
#define M_MCNT0 768
#define M_MCNT1 832
#define M_PERM2 896
#define M_MCNT2 1152
#define M_ROWL0 1216
#define M_ROWL1 9408
#define M_NACT  17600
#define M_SYNC  17608
static constexpr size_t META_N  = 17640;
static constexpr size_t TOTAL_F = OFF_META + META_N;

__device__ __align__(256) float d_buf[TOTAL_F];

__device__ __forceinline__ void split_store(float v, __nv_bfloat16* hi, __nv_bfloat16* lo) {
    __nv_bfloat16 h = __float2bfloat16_rn(v);
    *hi = h;
    *lo = __float2bfloat16_rn(v - __bfloat162float(h));
}

// ---------------- grid barrier ----------------
__device__ __forceinline__ void gbar(unsigned* cnt, unsigned* rel,
                                     unsigned seq, unsigned ncta) {
    __syncthreads();
    if (threadIdx.x == 0) {
        unsigned old;
        asm volatile("fence.acq_rel.gpu;" ::: "memory");
        asm volatile("atom.relaxed.gpu.global.add.u32 %0, [%1], 1;"
                     : "=r"(old) : "l"(cnt) : "memory");
        if (old + 1u == ncta * seq) {
            asm volatile("st.release.gpu.global.u32 [%0], %1;"
                         :: "l"(rel), "r"(seq) : "memory");
        }
        unsigned v;
        do {
            asm volatile("ld.acquire.gpu.global.u32 %0, [%1];"
                         : "=r"(v) : "l"(rel) : "memory");
        } while (v < seq);
    }
    __syncthreads();
}

// ---------------- prep ----------------
__global__ void k_prep(const float* __restrict__ W1, const float* __restrict__ W2,
                       const float* __restrict__ Wy, const float* __restrict__ Wh,
                       const float* __restrict__ Wr, const float* __restrict__ Wt,
                       const float* __restrict__ b1, const float* __restrict__ b2) {
    float* buf = d_buf;
    __nv_bfloat16* WxS = (__nv_bfloat16*)(buf + OFF_WXS);
    __nv_bfloat16* WhS = (__nv_bfloat16*)(buf + OFF_WHS);
    __nv_bfloat16* WyS = (__nv_bfloat16*)(buf + OFF_WYS);
    __nv_bfloat16* WhA = (__nv_bfloat16*)(buf + OFF_WHA);
    __nv_bfloat16* WcS = (__nv_bfloat16*)(buf + OFF_WCS);
    float* bP = buf + OFF_BP;

    const size_t R1 = 2ull * G4_ * KPX;
    const size_t R2 = 2ull * G4_ * H_;
    const size_t R3 = (size_t)H_ * H_;
    const size_t R4 = (size_t)H_ * H_;
    const size_t R5 = 2ull * H_ * H_;
    const size_t R6 = 2ull * G4_;
    const size_t R7 = OFF_WYY - OFF_H;
    const size_t R8 = OFF_RL - OFF_RB;
    const size_t R9 = 4ull * B_ * T_ * H_;
    const size_t R10 = 16;
    const size_t TOT = R1 + R2 + R3 + R4 + R5 + R6 + R7 + R8 + R9 + R10;
    size_t stride = (size_t)gridDim.x * blockDim.x;
    for (size_t id = (size_t)blockIdx.x * blockDim.x + threadIdx.x; id < TOT; id += stride) {
        size_t i = id;
        if (i < R1) {
            int w = (int)(i / ((size_t)G4_ * KPX));
            size_t rem = i % ((size_t)G4_ * KPX);
            int np = (int)(rem / KPX), k = (int)(rem % KPX);
            int col = (np & 3) * H_ + (np >> 2);
            const float* W = w ? W2 : W1;
            float v = (k < D_) ? W[(size_t)k * G4_ + col] : 0.f;
            size_t o = ((size_t)(w * 2) * G4_ + np) * KPX + k;
            split_store(v, WxS + o, WxS + o + (size_t)G4_ * KPX);
            continue;
        }
        i -= R1;
        if (i < R2) {
            int w = (int)(i / ((size_t)G4_ * H_));
            size_t rem = i % ((size_t)G4_ * H_);
            int np = (int)(rem / H_), k = (int)(rem % H_);
            int col = (np & 3) * H_ + (np >> 2);
            const float* W = w ? W2 : W1;
            float v = W[(size_t)(D_ + k) * G4_ + col];
            size_t o = ((size_t)(w * 2) * G4_ + np) * H_ + k;
            split_store(v, WhS + o, WhS + o + (size_t)G4_ * H_);
            continue;
        }
        i -= R2;
        if (i < R3) {
            int n = (int)(i / H_), k = (int)(i % H_);
            size_t o = (size_t)n * H_ + k;
            split_store(Wy[(size_t)k * H_ + n], WyS + o, WyS + o + (size_t)H_ * H_);
            continue;
        }
        i -= R3;
        if (i < R4) {
            int n = (int)(i / H_), k = (int)(i % H_);
            size_t o = (size_t)n * H_ + k;
            split_store(Wh[(size_t)k * H_ + n], WhA + o, WhA + o + (size_t)H_ * H_);
            continue;
        }
        i -= R4;
        if (i < R5) {
            int n = (int)(i / H_), k = (int)(i % H_);
            float v = (n < H_) ? Wr[(size_t)k * H_ + n] : Wt[(size_t)k * H_ + (n - H_)];
            size_t o = (size_t)n * H_ + k;
            split_store(v, WcS + o, WcS + o + 2ull * H_ * H_);
            continue;
        }
        i -= R5;
        if (i < R6) {
            int w = (int)(i / G4_), np = (int)(i % G4_);
            int col = (np & 3) * H_ + (np >> 2);
            bP[i] = (w ? b2 : b1)[col];
            continue;
        }
        i -= R6;
        if (i < R7) { (buf + OFF_H)[i] = 0.f; continue; }
        i -= R7;
        if (i < R8) { (buf + OFF_RB)[i] = 0.f; continue; }
        i -= R8;
        if (i < R9) { (buf + OFF_Y)[i] = 0.f; continue; }
        i -= R9;
        ((int*)(buf + OFF_META))[M_SYNC + i] = 0;
    }
}

// ---------------- sort + row lists ----------------
__global__ void __launch_bounds__(256) k_sort(const int* __restrict__ s1,
                                              const int* __restrict__ s2) {
    int* meta = (int*)(d_buf + OFF_META);
    int tid = threadIdx.x;
    __shared__ int sl[2][128];
    __shared__ int sl2s[256];
    __shared__ int cntA[256];
    __shared__ int totA;
    if (tid < 128) { sl[0][tid] = s1[tid]; sl[1][tid] = s2[tid]; }
    __syncthreads();
    {
        int c = tid >> 7, i = tid & 127;
        int v = sl[c][i], r = 0;
        for (int j = 0; j < 128; j++) {
            int u = sl[c][j];
            if (u > v || (u == v && j < i)) r++;
        }
        meta[(c ? M_PERM1 : M_PERM0) + r] = i;
        meta[(c ? M_IPOS1 : M_IPOS0) + i] = r;
        meta[(c ? M_SLS1  : M_SLS0)  + r] = v;
    }
    if (tid < 128) {
        int c = tid >> 6, t = tid & 63;
        int cnt = 0;
        for (int i = 0; i < 128; i++) cnt += (sl[c][i] > t);
        meta[(c ? M_MCNT1 : M_MCNT0) + t] = cnt;
    }
    {
        int a = tid >> 7, b = tid & 127;
        sl2s[tid] = a ? sl[0][b] : sl[1][b];
    }
    __syncthreads();
    {
        int v = sl2s[tid], r = 0;
        for (int j = 0; j < 256; j++) {
            int u = sl2s[j];
            if (u > v || (u == v && j < tid)) r++;
        }
        meta[M_PERM2 + r] = tid;
    }
    if (tid < 64) {
        int cnt = 0;
        for (int j = 0; j < 256; j++) cnt += (sl2s[j] > tid);
        meta[M_MCNT2 + tid] = cnt;
    }
    for (int c = 0; c < 2; c++) {
        int base = c ? M_ROWL1 : M_ROWL0;
        int myA = 0;
        for (int k = 0; k < 32; k++) {
            int row = tid * 32 + k;
            myA += ((row & 63) < sl[c][row >> 6]);
        }
        __syncthreads();
        cntA[tid] = myA;
        __syncthreads();
        if (tid == 0) {
            int s = 0;
            for (int i = 0; i < 256; i++) { int v = cntA[i]; cntA[i] = s; s += v; }
            totA = s;
            meta[M_NACT + c] = s;
        }
        __syncthreads();
        int pa = cntA[tid];
        int pd = totA + (tid * 32 - pa);
        for (int k = 0; k < 32; k++) {
            int row = tid * 32 + k;
            if ((row & 63) < sl[c][row >> 6]) meta[base + pa++] = row;
            else                              meta[base + pd++] = row;
        }
        __syncthreads();
    }
}

__global__ void k_gather(float* __restrict__ e, const int* __restrict__ t1,
                         const int* __restrict__ t2, const float* __restrict__ emb) {
    size_t total = 2ull * B_ * T_ * KPX;
    size_t stride = (size_t)gridDim.x * blockDim.x;
    for (size_t i = (size_t)blockIdx.x * blockDim.x + threadIdx.x; i < total; i += stride) {
        int which = (int)(i / ((size_t)B_ * T_ * KPX));
        size_t rem = i % ((size_t)B_ * T_ * KPX);
        int bt = (int)(rem / KPX), k = (int)(rem % KPX);
        int tok = (which ? t2 : t1)[bt];
        e[i] = (k < D_) ? emb[(size_t)tok * D_ + k] : 0.f;
    }
}

// ---------------------------------------------------------------------------
// bulk GEMM engine, 256 threads / 8 warps sharing one pipeline.
// A loaded by threads <128 (fp32->hi/lo), B hi/lo split across thread halves.
// Warps: wg_n = wid&3 (N columns), wg_m = wid>>2 (2 mts each).
// ---------------------------------------------------------------------------
struct MZ {
    const float*         A;
    const __nv_bfloat16* Bhi;
    const __nv_bfloat16* Blo;
    float*               C;
    const float*         bias;
    const int*           rows;
    const int*           nactp;
};
struct MP {
    MZ z[4];
    int Klen, lda, ldb, ldc;
};

__global__ void __launch_bounds__(256) mm_gemm(MP p) {
    extern __shared__ __align__(16) char smem_raw[];
    uint32_t sb = smem_u32(smem_raw);
    const MZ z = p.z[blockIdx.z];
    int tid = threadIdx.x, lane = tid & 31, wid = tid >> 5;
    int wg_n = wid & 3, wg_m = wid >> 2;
    int n0 = blockIdx.x * TN, m0 = blockIdx.y * TM;

    if (z.rows && m0 >= __ldg(z.nactp)) return;

    int tl = tid & 127;
    bool aAct = tid < 128;
    int arow = z.rows ? __ldg(z.rows + m0 + (tl >> 1)) : (m0 + (tl >> 1));
    const float* Ag = z.A + (size_t)arow * p.lda + (tl & 1) * 16;
    int brow = tid & 127, term = tid >> 7;
    const __nv_bfloat16* Bg = (term ? z.Blo : z.Bhi) + (size_t)(n0 + brow) * p.ldb;
    uint32_t aSt = (uint32_t)((tl >> 1) * PAD + (tl & 1) * 16) * 2;
    uint32_t bSt = (uint32_t)(brow * PAD) * 2;
    uint32_t aLd = (uint32_t)((lane & 15) * PAD + ((lane >> 4) << 3)) * 2;
    uint32_t bLd = (uint32_t)(((lane & 7) + ((lane & 16) >> 1)) * PAD + (lane & 8)) * 2;

    int nch = p.Klen / KC;
    float acc[2][4][4] = {};
    float fA[16];
    // prologue
    {
#pragma unroll
        for (int q = 0; q < 4; q++)
            CP_ASYNC16(sb + B_BASE(term, 0) + bSt + q * 16, Bg + q * 8);
        CP_COMMIT();
        if (aAct) {
            const float4* s4 = (const float4*)Ag;
#pragma unroll
            for (int q = 0; q < 4; q++) {
                float4 v = __ldcg(s4 + q);
                fA[4 * q] = v.x; fA[4 * q + 1] = v.y; fA[4 * q + 2] = v.z; fA[4 * q + 3] = v.w;
            }
            ushort hi[16], lo[16];
#pragma unroll
            for (int q = 0; q < 16; q++) {
                __nv_bfloat16 hb = __float2bfloat16_rn(fA[q]);
                __nv_bfloat16 lb = __float2bfloat16_rn(fA[q] - __bfloat162float(hb));
                hi[q] = *(ushort*)&hb; lo[q] = *(ushort*)&lb;
            }
            *(uint4*)(smem_raw + A_BASE(0, 0) + aSt)      = *(uint4*)(hi);
            *(uint4*)(smem_raw + A_BASE(0, 0) + aSt + 16) = *(uint4*)(hi + 8);
            *(uint4*)(smem_raw + A_BASE(1, 0) + aSt)      = *(uint4*)(lo);
            *(uint4*)(smem_raw + A_BASE(1, 0) + aSt + 16) = *(uint4*)(lo + 8);
        }
        CP_WAIT0();
        __syncthreads();
    }
    for (int ch = 0; ch < nch; ch++) {
        int s = ch & 1, ns = s ^ 1;
        bool more = (ch + 1) < nch;
        if (more) {
            const __nv_bfloat16* b2p = Bg + (ch + 1) * KC;
#pragma unroll
            for (int q = 0; q < 4; q++)
                CP_ASYNC16(sb + B_BASE(term, ns) + bSt + q * 16, b2p + q * 8);
            CP_COMMIT();
            if (aAct) {
                const float4* s4 = (const float4*)(Ag + (ch + 1) * KC);
#pragma unroll
                for (int q = 0; q < 4; q++) {
                    float4 v = __ldcg(s4 + q);
                    fA[4 * q] = v.x; fA[4 * q + 1] = v.y; fA[4 * q + 2] = v.z; fA[4 * q + 3] = v.w;
                }
            }
        }
#pragma unroll
        for (int h16 = 0; h16 < 2; h16++) {
            uint32_t kb = (uint32_t)h16 * 32;
            uint32_t bh[8], bl[8];
#pragma unroll
            for (int g2 = 0; g2 < 2; g2++) {
                uint32_t rowb = (uint32_t)((wg_n * 32 + g2 * 16) * PAD) * 2;
                LDSM4(bh[g2 * 4 + 0], bh[g2 * 4 + 1], bh[g2 * 4 + 2], bh[g2 * 4 + 3],
                      sb + B_BASE(0, s) + bLd + rowb + kb);
                LDSM4(bl[g2 * 4 + 0], bl[g2 * 4 + 1], bl[g2 * 4 + 2], bl[g2 * 4 + 3],
                      sb + B_BASE(1, s) + bLd + rowb + kb);
            }
#pragma unroll
            for (int k = 0; k < 2; k++) {
                int mt = 2 * wg_m + k;
                uint32_t ah[4], al[4];
                uint32_t rowa = (uint32_t)(mt * 16 * PAD) * 2;
                LDSM4(ah[0], ah[1], ah[2], ah[3], sb + A_BASE(0, s) + aLd + rowa + kb);
                LDSM4(al[0], al[1], al[2], al[3], sb + A_BASE(1, s) + aLd + rowa + kb);
#pragma unroll
                for (int nt = 0; nt < 4; nt++) {
                    int bi = (nt >> 1) * 4 + (nt & 1) * 2;
                    MMA16816(acc[k][nt], ah, bh[bi], bh[bi + 1]);
                    MMA16816(acc[k][nt], ah, bl[bi], bl[bi + 1]);
                    MMA16816(acc[k][nt], al, bh[bi], bh[bi + 1]);
                }
            }
        }
        if (more) {
            if (aAct) {
                ushort hi[16], lo[16];
#pragma unroll
                for (int q = 0; q < 16; q++) {
                    __nv_bfloat16 hb = __float2bfloat16_rn(fA[q]);
                    __nv_bfloat16 lb = __float2bfloat16_rn(fA[q] - __bfloat162float(hb));
                    hi[q] = *(ushort*)&hb; lo[q] = *(ushort*)&lb;
                }
                *(uint4*)(smem_raw + A_BASE(0, ns) + aSt)      = *(uint4*)(hi);
                *(uint4*)(smem_raw + A_BASE(0, ns) + aSt + 16) = *(uint4*)(hi + 8);
                *(uint4*)(smem_raw + A_BASE(1, ns) + aSt)      = *(uint4*)(lo);
                *(uint4*)(smem_raw + A_BASE(1, ns) + aSt + 16) = *(uint4*)(lo + 8);
            }
            CP_WAIT0();
        }
        __syncthreads();
    }

#pragma unroll
    for (int k = 0; k < 2; k++) {
        int mt = 2 * wg_m + k;
        int r = m0 + mt * 16 + (lane >> 2);
        int r0 = z.rows ? __ldg(z.rows + r) : r;
        int r1 = z.rows ? __ldg(z.rows + r + 8) : (r + 8);
#pragma unroll
        for (int nt = 0; nt < 4; nt++) {
            int c = n0 + wg_n * 32 + nt * 8 + (lane & 3) * 2;
            float b0 = 0.f, b1 = 0.f;
            if (z.bias) { b0 = z.bias[c]; b1 = z.bias[c + 1]; }
            *(float2*)(z.C + (size_t)r0 * p.ldc + c) =
                make_float2(acc[k][nt][0] + b0, acc[k][nt][1] + b1);
            *(float2*)(z.C + (size_t)r1 * p.ldc + c) =
                make_float2(acc[k][nt][2] + b0, acc[k][nt][3] + b1);
        }
    }
}

// ---------------------------------------------------------------------------
// Persistent LSTM scan: 512 threads / 16 warps. wg_n 4-way N, wg_m 4-way M
// (mts {wg_m, wg_m+4}). Wh resident, sorted batches, frag skipping.
// ---------------------------------------------------------------------------
__global__ void __launch_bounds__(512) k_lstm_persist() {
    extern __shared__ __align__(16) char smem[];
    uint32_t sb = smem_u32(smem);
    float* buf = d_buf;
    int* meta = (int*)(buf + OFF_META);
    int tid = threadIdx.x, lane = tid & 31, wid = tid >> 5;
    int wg_n = wid & 3, wg_m = wid >> 2;
    int blk = blockIdx.x;
    int r = blk >> 5, nt_ = blk & 31;
    int n0 = nt_ * 64;
    int widx = (r == 0 || r == 2) ? 0 : 1;
    int cls  = (r == 0 || r == 3) ? 0 : 1;
    const int* permc = meta + (cls ? M_PERM1 : M_PERM0);
    const int* slsrt = meta + (cls ? M_SLS1  : M_SLS0);
    const int* mcnt  = meta + (cls ? M_MCNT1 : M_MCNT0);

    // resident Wh slab: 2 terms x 64 rows x 4 quarters (256B each)
    {
        const __nv_bfloat16* WhS = (const __nv_bfloat16*)(buf + OFF_WHS);
        int tau = tid >> 8, rem = tid & 255;
        int n = rem >> 2, quar = rem & 3;
        const __nv_bfloat16* src = WhS + (size_t)(widx * 2 + tau) * G4_ * H_
                                   + (size_t)(n0 + n) * H_ + quar * 128;
        uint32_t dst = sb + (uint32_t)tau * 66560u + (uint32_t)n * 1040u + (uint32_t)quar * 256u;
#pragma unroll
        for (int q = 0; q < 16; q++) CP_ASYNC16(dst + q * 16, src + q * 8);
        CP_COMMIT(); CP_WAIT0(); __syncthreads();
    }

    const float* Xg  = buf + OFF_XG + (size_t)r * B_ * T_ * G4_;
    float*       cst = buf + OFF_C + (size_t)r * B_ * H_;
    float*       Yst = buf + OFF_Y + (size_t)r * B_ * T_ * H_;
    float*       hB  = buf + OFF_H;
    __nv_bfloat16* HBb = (__nv_bfloat16*)(buf + OFF_HB);
    unsigned* sync = (unsigned*)(meta + M_SYNC);
    const size_t HBUF = 4ull * B_ * H_;

    uint32_t aLd   = (uint32_t)((lane & 15) * 40 + ((lane >> 4) << 3)) * 2;
    uint32_t bBase = (uint32_t)(wg_n * 16) * 1040u
                   + (uint32_t)(((lane & 7) + ((lane & 16) >> 1)) * 520 + (lane & 8)) * 2;

    for (int t = 0; t < T_; t++) {
        int mcur  = __ldg(mcnt + t);
        int mtmax = (mcur + 15) >> 4;
        int ppi = t & 1, ppo = ppi ^ 1;
        const float* hin  = hB + (size_t)ppi * HBUF + (size_t)r * B_ * H_;
        float*       hout = hB + (size_t)ppo * HBUF + (size_t)r * B_ * H_;
        const __nv_bfloat16* Ain = HBb + (size_t)ppi * 2 * P_HB + (size_t)r * B_ * H_;
        __nv_bfloat16*       ho  = HBb + (size_t)ppo * 2 * P_HB + (size_t)r * B_ * H_;

        float acc[2][2][4] = {};   // k (mt = 4k+wg_m) x nt x frag
        if (mtmax > 0) {
            int nrows = mtmax << 4;
            auto issueA = [&](int ch, int slot) {
                int tau = tid >> 8, rem = tid & 255;
                int row = rem >> 1, half = rem & 1;
                if (row < nrows) {
                    const __nv_bfloat16* src = Ain + (size_t)tau * P_HB + (size_t)row * H_
                                               + ch * 32 + half * 16;
                    uint32_t dst = sb + 133120u + (uint32_t)slot * 20480u
                                 + (uint32_t)tau * 10240u + (uint32_t)row * 80u + (uint32_t)half * 32u;
                    CP_ASYNC16(dst,      src);
                    CP_ASYNC16(dst + 16, src + 8);
                }
                CP_COMMIT();
            };
            issueA(0, 0); issueA(1, 1);
            for (int ch = 0; ch < 16; ch++) {
                if (ch == 15) { CP_WAIT0(); } else { CP_WAIT1(); }
                __syncthreads();
                if (ch + 2 < 16) issueA(ch + 2, (ch + 2) % 3);
                uint32_t abase = sb + 133120u + (uint32_t)(ch % 3) * 20480u;
#pragma unroll
                for (int h16 = 0; h16 < 2; h16++) {
                    uint32_t kb = (uint32_t)(ch * 32 + h16 * 16) * 2;
                    uint32_t bA[4], bB[4];
                    LDSM4(bA[0], bA[1], bA[2], bA[3], sb + bBase + kb);
                    LDSM4(bB[0], bB[1], bB[2], bB[3], sb + 66560u + bBase + kb);
#pragma unroll
                    for (int k = 0; k < 2; k++) {
                        int mt = 4 * k + wg_m;
                        if (mt < mtmax) {
                            uint32_t ah[4], al[4];
                            uint32_t rowa = (uint32_t)(mt * 16 * 80);
                            LDSM4(ah[0], ah[1], ah[2], ah[3], abase + aLd + rowa + h16 * 32);
                            LDSM4(al[0], al[1], al[2], al[3], abase + 10240u + aLd + rowa + h16 * 32);
                            MMA16816(acc[k][0], ah, bA[0], bA[1]);
                            MMA16816(acc[k][0], ah, bB[0], bB[1]);
                            MMA16816(acc[k][0], al, bA[0], bA[1]);
                            MMA16816(acc[k][1], ah, bA[2], bA[3]);
                            MMA16816(acc[k][1], ah, bB[2], bB[3]);
                            MMA16816(acc[k][1], al, bA[2], bA[3]);
                        }
                    }
                }
            }
        }

        // epilogue: active mts owned by this warp
#pragma unroll
        for (int k = 0; k < 2; k++) {
            int mt = 4 * k + wg_m;
            if (mt < mtmax) {
                int b = mt * 16 + (lane >> 2);
#pragma unroll
                for (int nt = 0; nt < 2; nt++) {
                    float fo0 = __shfl_xor_sync(0xffffffffu, acc[k][nt][0], 1);
                    float fo1 = __shfl_xor_sync(0xffffffffu, acc[k][nt][1], 1);
                    float fo2 = __shfl_xor_sync(0xffffffffu, acc[k][nt][2], 1);
                    float fo3 = __shfl_xor_sync(0xffffffffu, acc[k][nt][3], 1);
                    if (!(lane & 1)) {
#pragma unroll
                        for (int half = 0; half < 2; half++) {
                            int bb = b + half * 8;
                            float gi = half ? acc[k][nt][2] : acc[k][nt][0];
                            float gj = half ? acc[k][nt][3] : acc[k][nt][1];
                            float gf = half ? fo2 : fo0;
                            float go = half ? fo3 : fo1;
                            int c0 = n0 + wg_n * 16 + nt * 8 + (lane & 3) * 2;
                            int j = c0 >> 2;
                            size_t ci = (size_t)bb * H_ + j;
                            int slv = __ldg(slsrt + bb);
                            float hv;
                            if (t < slv) {
                                int ob = __ldg(permc + bb);
                                float4 x = *(const float4*)(Xg + ((size_t)ob * T_ + t) * G4_ + c0);
                                gi += x.x; gj += x.y; gf += x.z; go += x.w;
                                float cc = cst[ci];
                                float cn = cc * sigf(gf + 1.f) + sigf(gi) * ftanh(gj);
                                hv = ftanh(cn) * sigf(go);
                                cst[ci] = cn;
                                Yst[((size_t)ob * T_ + t) * H_ + j] = hv;
                            } else {
                                hv = __ldcg(hin + ci);
                            }
                            hout[ci] = hv;
                            split_store(hv, ho + ci, ho + P_HB + ci);
                        }
                    }
                }
            }
        }
        // frozen copies (threads < 256)
        if (tid < 256) {
            for (int mt = mtmax; mt < 8; mt++) {
                int rr = mt * 16 + (tid >> 4);
                int jj = (n0 >> 2) + (tid & 15);
                size_t ci = (size_t)rr * H_ + jj;
                float hv = __ldcg(hin + ci);
                hout[ci] = hv;
                ho[ci]        = Ain[ci];
                ho[P_HB + ci] = Ain[P_HB + ci];
            }
        }
        gbar(sync + 0, sync + 1, (unsigned)(t + 1), 128u);
    }
}

// ---------------------------------------------------------------------------
// Persistent attention scan: 512 threads / 16 warps, wg_m 4-way (1 mt each).
// ---------------------------------------------------------------------------
__global__ void __launch_bounds__(512) k_att_persist(
    const float* __restrict__ wv,
    const int* __restrict__ s1, const int* __restrict__ s2) {
    extern __shared__ __align__(16) char smem[];
    uint32_t sb = smem_u32(smem);
    float* smf = (float*)(smem + 69632);
    float* buf = d_buf;
    int* meta = (int*)(buf + OFF_META);
    int tid = threadIdx.x, lane = tid & 31, wid = tid >> 5;
    int wg_n = wid & 3, wg_m = wid >> 2;
    int blk = blockIdx.x;

    int ks  = blk & 3;
    int mt_ = (blk >> 2) & 3;
    int nt_ = blk >> 4;
    int m0 = mt_ * 64, n0 = nt_ * 128, kst = ks * 128;

    // resident Wc slab: 2 terms x 128 rows x 2 halves (128B each)
    {
        const __nv_bfloat16* WcS = (const __nv_bfloat16*)(buf + OFF_WCS);
        int tau = tid >> 8, rem = tid & 255;
        int row = rem >> 1, half = rem & 1;
        const __nv_bfloat16* src = WcS + (size_t)tau * 2 * H_ * H_
                                   + (size_t)(n0 + row) * H_ + kst + half * 64;
        uint32_t dst = sb + (uint32_t)tau * 34816u + (uint32_t)row * 272u + (uint32_t)half * 128u;
#pragma unroll
        for (int q = 0; q < 8; q++) CP_ASYNC16(dst + q * 16, src + q * 8);
        CP_COMMIT(); CP_WAIT0(); __syncthreads();
    }

    __nv_bfloat16* RBb = (__nv_bfloat16*)(buf + OFF_RB);
    float* uPt4 = buf + OFF_UPT;
    float* rL   = buf + OFF_RL;
    const float* WyY = buf + OFF_WYY;
    const float* HWy = buf + OFF_HWY;
    const float* Yb  = buf + OFF_Y;
    unsigned* sync = (unsigned*)(meta + M_SYNC);
    const int* mcnt2 = meta + M_MCNT2;

    uint32_t aLd = (uint32_t)((lane & 15) * 40 + ((lane >> 4) << 3)) * 2;
    uint32_t bLd = (uint32_t)(((lane & 7) + ((lane & 16) >> 1)) * 136 + (lane & 8)) * 2;

    float wvr[16];
#pragma unroll
    for (int k = 0; k < 16; k++) wvr[k] = __ldg(wv + lane + 32 * k);

    int spA = blk * 2, spB = blk * 2 + 1;
    int pA = meta[M_PERM2 + spA], pB = meta[M_PERM2 + spB];
    int aA = pA >> 7, bA = pA & 127;
    int aB = pB >> 7, bB = pB & 127;
    int sl2A = aA ? s1[bA] : s2[bA];
    int sl2B = aB ? s1[bB] : s2[bB];
    int slmA = aA ? s2[bA] : s1[bA];
    int slmB = aB ? s2[bB] : s1[bB];

    for (int t = 0; t < T_; t++) {
        int mcur2 = __ldg(mcnt2 + t);
        int mtloc = 0;
        if (mcur2 > m0) { mtloc = (mcur2 - m0 + 15) >> 4; if (mtloc > 4) mtloc = 4; }

        if (mtloc > 0) {
            int nrows = mtloc << 4;
            auto issueA = [&](int ch, int slot) {
                int row = tid >> 1, tau = tid & 1;
                if (tid < 128 && row < nrows) {
                    const __nv_bfloat16* src = RBb + (size_t)tau * P_RB
                                               + (size_t)(m0 + row) * H_ + kst + ch * 32;
                    uint32_t dst = sb + 69632u + (uint32_t)slot * 10240u
                                 + (uint32_t)tau * 5120u + (uint32_t)row * 80u;
                    CP_ASYNC16(dst,      src);
                    CP_ASYNC16(dst + 16, src + 8);
                    CP_ASYNC16(dst + 32, src + 16);
                    CP_ASYNC16(dst + 48, src + 24);
                }
                CP_COMMIT();
            };
            issueA(0, 0); issueA(1, 1);
            float acc[4][4] = {};
            for (int ch = 0; ch < 4; ch++) {
                if (ch == 3) { CP_WAIT0(); } else { CP_WAIT1(); }
                __syncthreads();
                if (ch + 2 < 4) issueA(ch + 2, (ch + 2) % 3);
                uint32_t abase = sb + 69632u + (uint32_t)(ch % 3) * 10240u;
#pragma unroll
                for (int h16 = 0; h16 < 2; h16++) {
                    uint32_t kb = (uint32_t)(ch * 32 + h16 * 16) * 2;
                    uint32_t bh[8], bl[8];
#pragma unroll
                    for (int g2 = 0; g2 < 2; g2++) {
                        uint32_t rowb = (uint32_t)((wg_n * 32 + g2 * 16) * 136) * 2;
                        LDSM4(bh[g2 * 4 + 0], bh[g2 * 4 + 1], bh[g2 * 4 + 2], bh[g2 * 4 + 3],
                              sb + bLd + rowb + kb);
                        LDSM4(bl[g2 * 4 + 0], bl[g2 * 4 + 1], bl[g2 * 4 + 2], bl[g2 * 4 + 3],
                              sb + 34816u + bLd + rowb + kb);
                    }
                    if (wg_m < mtloc) {
                        uint32_t ah[4], al[4];
                        uint32_t rowa = (uint32_t)(wg_m * 16 * 80);
                        LDSM4(ah[0], ah[1], ah[2], ah[3], abase + aLd + rowa + h16 * 32);
                        LDSM4(al[0], al[1], al[2], al[3], abase + 5120u + aLd + rowa + h16 * 32);
#pragma unroll
                        for (int nt = 0; nt < 4; nt++) {
                            int bi = (nt >> 1) * 4 + (nt & 1) * 2;
                            MMA16816(acc[nt], ah, bh[bi], bh[bi + 1]);
                            MMA16816(acc[nt], ah, bl[bi], bl[bi + 1]);
                            MMA16816(acc[nt], al, bh[bi], bh[bi + 1]);
                        }
                    }
                }
            }
            if (wg_m < mtloc) {
                float* Cb = uPt4 + (size_t)ks * 256 * 1024;
                int rr = m0 + wg_m * 16 + (lane >> 2);
#pragma unroll
                for (int nt = 0; nt < 4; nt++) {
                    int c = n0 + wg_n * 32 + nt * 8 + (lane & 3) * 2;
                    *(float2*)(Cb + (size_t)rr * 1024 + c) =
                        make_float2(acc[nt][0], acc[nt][1]);
                    *(float2*)(Cb + (size_t)(rr + 8) * 1024 + c) =
                        make_float2(acc[nt][2], acc[nt][3]);
                }
            }
        }
        gbar(sync + 2, sync + 3, (unsigned)(2 * t + 1), 128u);

        // phase A: two sorted pairs, exact skipping, 16 warps
        for (int pi = 0; pi < 2; pi++) {
            int sp   = pi ? spB : spA;
            int p    = pi ? pB : pA;
            int a    = pi ? aB : aA;
            int b    = pi ? bB : bA;
            int sl2  = pi ? sl2B : sl2A;
            int slm  = pi ? slmB : slmA;
            if (t >= sl2) continue;

            float* su  = smf;
            float* spt = smf + 512;
            float* sc  = smf + 1024;
            const float* hb = HWy + (size_t)a * B_ * T_ * H_ + ((size_t)b * T_ + t) * H_;
            {
                int h = tid;
                float s0 = 0.f, s1v = 0.f;
#pragma unroll
                for (int k = 0; k < 4; k++) {
                    const float* up = uPt4 + ((size_t)k * 256 + sp) * 1024;
                    s0  += __ldcg(up + h);
                    s1v += __ldcg(up + 512 + h);
                }
                su[h]  = s0 + __ldg(hb + h);
                spt[h] = s1v;
            }
            __syncthreads();
            const float* WyYb = WyY + (size_t)a * B_ * T_ * H_ + (size_t)b * T_ * H_;
#pragma unroll
            for (int q = 0; q < 4; q++) {
                int t2 = wid * 4 + q;
                if (t2 < slm) {
                    const float* row = WyYb + (size_t)t2 * H_;
                    float s = 0.f;
#pragma unroll
                    for (int k = 0; k < 16; k++) {
                        int hh = lane + 32 * k;
                        s += tanha(__ldg(row + hh) + su[hh]) * wvr[k];
                    }
                    for (int o = 16; o; o >>= 1) s += __shfl_xor_sync(0xffffffffu, s, o);
                    if (lane == 0) sc[t2] = s;
                } else if (lane == 0) {
                    sc[t2] = -10000.f;
                }
            }
            __syncthreads();
            if (wid == 0) {
                float v1 = sc[lane], v2 = sc[lane + 32];
                float m = fmaxf(v1, v2);
                for (int o = 16; o; o >>= 1) m = fmaxf(m, __shfl_xor_sync(0xffffffffu, m, o));
                float e1 = __expf(v1 - m), e2 = __expf(v2 - m);
                float s = e1 + e2;
                for (int o = 16; o; o >>= 1) s += __shfl_xor_sync(0xffffffffu, s, o);
                float inv = __fdividef(1.f, s);
                sc[lane] = e1 * inv;
                sc[lane + 32] = e2 * inv;
            }
            __syncthreads();
            const float* Yp = Yb + (size_t)(a ? 2 : 0) * B_ * T_ * H_ + (size_t)b * T_ * H_;
            {
                int h = tid;
                float accv = 0.f;
                for (int t2 = 0; t2 < slm; t2++)
                    accv += sc[t2] * __ldg(Yp + (size_t)t2 * H_ + h);
                float rn = accv + ftanh(spt[h]);
                if (t == sl2 - 1) {
                    rL[(size_t)p * H_ + h] = rn;
                } else {
                    split_store(rn, RBb + (size_t)sp * H_ + h, RBb + P_RB + (size_t)sp * H_ + h);
                }
            }
            __syncthreads();
        }
        gbar(sync + 2, sync + 3, (unsigned)(2 * t + 2), 128u);
    }
}

// ---------------- final projection ----------------
__global__ void __launch_bounds__(512) k_final(
    const float* __restrict__ rL, const float* __restrict__ hfin,
    const float* __restrict__ Wp, const float* __restrict__ Wx,
    const float* __restrict__ U, const float* __restrict__ bU,
    float* __restrict__ out) {
    int b = blockIdx.x;
    int tid = threadIdx.x;
    const int* meta = (const int*)(d_buf + OFF_META);
    int ip1 = meta[M_IPOS1 + b];
    int ip0 = meta[M_IPOS0 + b];
    __shared__ float s_in[4][512];
    __shared__ float s_sum[512];
    __shared__ float red0[16], red1[16];
    s_in[0][tid] = rL[(size_t)b * H_ + tid];
    s_in[1][tid] = hfin[((size_t)1 * B_ + ip1) * H_ + tid];
    s_in[2][tid] = rL[((size_t)B_ + b) * H_ + tid];
    s_in[3][tid] = hfin[((size_t)3 * B_ + ip0) * H_ + tid];
    __syncthreads();
    float acc0 = 0.f, acc1 = 0.f;
    for (int k = 0; k < H_; k++) {
        float wp = Wp[(size_t)k * H_ + tid];
        float wx = Wx[(size_t)k * H_ + tid];
        acc0 += s_in[0][k] * wp + s_in[1][k] * wx;
        acc1 += s_in[2][k] * wp + s_in[3][k] * wx;
    }
    s_sum[tid] = ftanh(acc0) + ftanh(acc1);
    __syncthreads();
    float p0 = s_sum[tid] * U[(size_t)tid * 2 + 0];
    float p1 = s_sum[tid] * U[(size_t)tid * 2 + 1];
    for (int o = 16; o; o >>= 1) {
        p0 += __shfl_xor_sync(0xffffffffu, p0, o);
        p1 += __shfl_xor_sync(0xffffffffu, p1, o);
    }
    int wp_ = tid >> 5;
    if ((tid & 31) == 0) { red0[wp_] = p0; red1[wp_] = p1; }
    __syncthreads();
    if (tid < 16) {
        p0 = red0[tid]; p1 = red1[tid];
        for (int o = 8; o; o >>= 1) {
            p0 += __shfl_xor_sync(0x0000ffffu, p0, o);
            p1 += __shfl_xor_sync(0x0000ffffu, p1, o);
        }
        if (tid == 0) {
            out[b * 2 + 0] = p0 + bU[0];
            out[b * 2 + 1] = p1 + bU[1];
        }
    }
}

// ---------------- host ----------------
extern "C" void kernel_launch(void* const* d_in, const int* in_sizes, int n_in,
                              void* d_out, int out_size) {
    (void)in_sizes; (void)n_in; (void)out_size;
    const int*   tokens1 = (const int*)d_in[0];
    const int*   tokens2 = (const int*)d_in[1];
    const int*   seqlen1 = (const int*)d_in[2];
    const int*   seqlen2 = (const int*)d_in[3];
    const float* emb = (const float*)d_in[4];
    const float* W1  = (const float*)d_in[5];
    const float* b1  = (const float*)d_in[6];
    const float* W2  = (const float*)d_in[7];
    const float* b2  = (const float*)d_in[8];
    const float* Wy  = (const float*)d_in[9];
    const float* Wh  = (const float*)d_in[10];
    const float* Wr  = (const float*)d_in[11];
    const float* wv  = (const float*)d_in[12];
    const float* Wt  = (const float*)d_in[13];
    const float* Wp  = (const float*)d_in[14];
    const float* Wx  = (const float*)d_in[15];
    const float* U   = (const float*)d_in[16];
    const float* bU  = (const float*)d_in[17];
    float* out = (float*)d_out;

    cudaFuncSetAttribute(mm_gemm, cudaFuncAttributeMaxDynamicSharedMemorySize, SMEM_MM);
    cudaFuncSetAttribute(k_lstm_persist, cudaFuncAttributeMaxDynamicSharedMemorySize, SMEM_LSTM);
    cudaFuncSetAttribute(k_att_persist, cudaFuncAttributeMaxDynamicSharedMemorySize, SMEM_ATT);

    float* buf = nullptr;
    cudaGetSymbolAddress((void**)&buf, d_buf);
    float* e    = buf + OFF_E;
    float* Xg   = buf + OFF_XG;
    float* Yb   = buf + OFF_Y;
    float* hBuf = buf + OFF_H;
    float* WyY  = buf + OFF_WYY;
    float* HWy  = buf + OFF_HWY;
    float* rL   = buf + OFF_RL;
    float* bP   = buf + OFF_BP;
    int*   meta = (int*)(buf + OFF_META);
    __nv_bfloat16* WxS = (__nv_bfloat16*)(buf + OFF_WXS);
    __nv_bfloat16* WyS = (__nv_bfloat16*)(buf + OFF_WYS);
    __nv_bfloat16* WhA = (__nv_bfloat16*)(buf + OFF_WHA);

    k_prep<<<2048, 256>>>(W1, W2, Wy, Wh, Wr, Wt, b1, b2);
    k_sort<<<1, 256>>>(seqlen1, seqlen2);
    k_gather<<<2048, 256>>>(e, tokens1, tokens2, emb);

    const int iidx[4] = {0, 1, 1, 0}, widx[4] = {0, 1, 0, 1};
    const int xcls[4] = {0, 1, 1, 0};

    // X GEMM: row-compacted, 256 threads
    {
        MP p = {};
        for (int r = 0; r < 4; r++) {
            p.z[r].A     = e + (size_t)iidx[r] * B_ * T_ * KPX;
            p.z[r].Bhi   = WxS + (size_t)(widx[r] * 2 + 0) * G4_ * KPX;
            p.z[r].Blo   = WxS + (size_t)(widx[r] * 2 + 1) * G4_ * KPX;
            p.z[r].C     = Xg + (size_t)r * B_ * T_ * G4_;
            p.z[r].bias  = bP + (size_t)widx[r] * G4_;
            p.z[r].rows  = meta + (xcls[r] ? M_ROWL1 : M_ROWL0);
            p.z[r].nactp = meta + M_NACT + xcls[r];
        }
        p.Klen = KPX; p.lda = KPX; p.ldb = KPX; p.ldc = G4_;
        mm_gemm<<<dim3(G4_ / TN, (B_ * T_) / TM, 4), 256, SMEM_MM>>>(p);
    }

    // persistent LSTM scan (512 threads, 16 warps)
    k_lstm_persist<<<128, 512, SMEM_LSTM>>>();

    // WyY + HWy: row-compacted, 256 threads
    {
        MP p = {};
        const int runs[4] = {0, 2, 1, 3};
        const int qcls[4] = {0, 1, 1, 0};
        for (int q = 0; q < 4; q++) {
            p.z[q].A     = Yb + (size_t)runs[q] * B_ * T_ * H_;
            p.z[q].Bhi   = (q < 2 ? WyS : WhA);
            p.z[q].Blo   = (q < 2 ? WyS : WhA) + (size_t)H_ * H_;
            p.z[q].C     = (q < 2 ? WyY + (size_t)q * B_ * T_ * H_
                                  : HWy + (size_t)(q - 2) * B_ * T_ * H_);
            p.z[q].bias  = nullptr;
            p.z[q].rows  = meta + (qcls[q] ? M_ROWL1 : M_ROWL0);
            p.z[q].nactp = meta + M_NACT + qcls[q];
        }
        p.Klen = H_; p.lda = H_; p.ldb = H_; p.ldc = H_;
        mm_gemm<<<dim3(H_ / TN, (B_ * T_) / TM, 4), 256, SMEM_MM>>>(p);
    }

    // persistent attention scan (512 threads, 16 warps)
    k_att_persist<<<128, 512, SMEM_ATT>>>(wv, seqlen1, seqlen2);

    k_final<<<B_, 512>>>(rL, hBuf, Wp, Wx, U, bU, out);
}

// round 13
// speedup vs baseline: 2.1025x; 1.0202x over previous
#include <cuda_runtime.h>
#include <cuda_bf16.h>
#include <math.h>
#include <stdint.h>

#define B_   128
#define T_   64
#define D_   300
#define KPX  320
#define H_   512
#define G4_  2048

// ---- bulk GEMM tile ----
#define TM 64
#define TN 128
#define KC 32
#define PAD 40
#define A_BASE(term,stage) ((uint32_t)(((term)*2+(stage))*5120))
#define B_BASE(term,stage) ((uint32_t)(20480u + ((term)*2+(stage))*10240u))
static constexpr int SMEM_MM   = 61440;
static constexpr int SMEM_LSTM = 133120 + 4 * 20480;   // 215040
static constexpr int SMEM_ATT  = 69632 + 4 * 10240;    // 110592

__device__ __forceinline__ uint32_t smem_u32(const void* p) {
    uint32_t a;
    asm("{ .reg .u64 t; cvta.to.shared.u64 t, %1; cvt.u32.u64 %0, t; }" : "=r"(a) : "l"(p));
    return a;
}
#define CP_ASYNC16(dst, src) \
    asm volatile("cp.async.cg.shared.global [%0], [%1], 16;" :: "r"(dst), "l"(src))
#define CP_COMMIT() asm volatile("cp.async.commit_group;" ::: "memory")
#define CP_WAIT0()  asm volatile("cp.async.wait_group 0;" ::: "memory")
#define CP_WAIT1()  asm volatile("cp.async.wait_group 1;" ::: "memory")
#define CP_WAIT2()  asm volatile("cp.async.wait_group 2;" ::: "memory")
#define LDSM4(r0, r1, r2, r3, addr) \
    asm volatile("ldmatrix.sync.aligned.m8n8.x4.shared.b16 {%0,%1,%2,%3}, [%4];" \
                 : "=r"(r0), "=r"(r1), "=r"(r2), "=r"(r3) : "r"(addr))
#define MMA16816(c, a, b0, b1) \
    asm volatile("mma.sync.aligned.m16n8k16.row.col.f32.bf16.bf16.f32 " \
                 "{%0,%1,%2,%3}, {%4,%5,%6,%7}, {%8,%9}, {%0,%1,%2,%3};" \
                 : "+f"((c)[0]), "+f"((c)[1]), "+f"((c)[2]), "+f"((c)[3]) \
                 : "r"((a)[0]), "r"((a)[1]), "r"((a)[2]), "r"((a)[3]), \
                   "r"(b0), "r"(b1))

__device__ __forceinline__ float sigf(float x) { return __fdividef(1.f, 1.f + __expf(-x)); }
__device__ __forceinline__ float ftanh(float x) { return 1.f - __fdividef(2.f, __expf(2.f * x) + 1.f); }
__device__ __forceinline__ float tanha(float x) {
    float y; asm("tanh.approx.f32 %0, %1;" : "=f"(y) : "f"(x)); return y;
}

static constexpr size_t P_HB = 4ull * B_ * H_;
static constexpr size_t P_RB = 256ull * H_;

// ---------------- scratch layout (float units) ----------------
static constexpr size_t OFF_E    = 0;
static constexpr size_t OFF_XG   = OFF_E   + 2ull * B_ * T_ * KPX;
static constexpr size_t OFF_Y    = OFF_XG  + 4ull * B_ * T_ * G4_;
static constexpr size_t OFF_H    = OFF_Y   + 4ull * B_ * T_ * H_;
static constexpr size_t OFF_HB   = OFF_H   + 2ull * 4 * B_ * H_;
static constexpr size_t OFF_C    = OFF_HB  + (2ull * 2 * P_HB) / 2;
static constexpr size_t OFF_WYY  = OFF_C   + 4ull * B_ * H_;
static constexpr size_t OFF_HWY  = OFF_WYY + 2ull * B_ * T_ * H_;
static constexpr size_t OFF_UPT  = OFF_HWY + 2ull * B_ * T_ * H_;
static constexpr size_t OFF_RB   = OFF_UPT + 4ull * 256 * 1024;
static constexpr size_t OFF_RL   = OFF_RB  + (2ull * P_RB) / 2;
static constexpr size_t OFF_BP   = OFF_RL  + 256ull * H_;
static constexpr size_t OFF_WXS  = OFF_BP  + 2ull * G4_;
static constexpr size_t OFF_WHS  = OFF_WXS + (2ull * 2 * G4_ * KPX) / 2;
static constexpr size_t OFF_WYS  = OFF_WHS + (2ull * 2 * G4_ * H_) / 2;
static constexpr size_t OFF_WHA  = OFF_WYS + (2ull * H_ * H_) / 2;
static constexpr size_t OFF_WCS  = OFF_WHA + (2ull * H_ * H_) / 2;
static constexpr size_t OFF_META = OFF_WCS + (2ull * 2 * H_ * H_) / 2;
#define M_PERM0 0
#define M_PERM1 128
#define M_IPOS0 256
#define M_IPOS1 384
#define M_SLS0  512
#define M_SLS1  640
#define M_MCNT0 768
#define M_MCNT1 832
#define M_PERM2 896
#define M_MCNT2 1152
#define M_ROWL0 1216
#define M_ROWL1 9408
#define M_NACT  17600
#define M_SYNC  17608
static constexpr size_t META_N  = 17640;
static constexpr size_t TOTAL_F = OFF_META + META_N;

__device__ __align__(256) float d_buf[TOTAL_F];

__device__ __forceinline__ void split_store(float v, __nv_bfloat16* hi, __nv_bfloat16* lo) {
    __nv_bfloat16 h = __float2bfloat16_rn(v);
    *hi = h;
    *lo = __float2bfloat16_rn(v - __bfloat162float(h));
}

// ---------------- grid barrier ----------------
__device__ __forceinline__ void gbar(unsigned* cnt, unsigned* rel,
                                     unsigned seq, unsigned ncta) {
    __syncthreads();
    if (threadIdx.x == 0) {
        unsigned old;
        asm volatile("fence.acq_rel.gpu;" ::: "memory");
        asm volatile("atom.relaxed.gpu.global.add.u32 %0, [%1], 1;"
                     : "=r"(old) : "l"(cnt) : "memory");
        if (old + 1u == ncta * seq) {
            asm volatile("st.release.gpu.global.u32 [%0], %1;"
                         :: "l"(rel), "r"(seq) : "memory");
        }
        unsigned v;
        do {
            asm volatile("ld.acquire.gpu.global.u32 %0, [%1];"
                         : "=r"(v) : "l"(rel) : "memory");
        } while (v < seq);
    }
    __syncthreads();
}

// ---------------- prep ----------------
__global__ void k_prep(const float* __restrict__ W1, const float* __restrict__ W2,
                       const float* __restrict__ Wy, const float* __restrict__ Wh,
                       const float* __restrict__ Wr, const float* __restrict__ Wt,
                       const float* __restrict__ b1, const float* __restrict__ b2) {
    float* buf = d_buf;
    __nv_bfloat16* WxS = (__nv_bfloat16*)(buf + OFF_WXS);
    __nv_bfloat16* WhS = (__nv_bfloat16*)(buf + OFF_WHS);
    __nv_bfloat16* WyS = (__nv_bfloat16*)(buf + OFF_WYS);
    __nv_bfloat16* WhA = (__nv_bfloat16*)(buf + OFF_WHA);
    __nv_bfloat16* WcS = (__nv_bfloat16*)(buf + OFF_WCS);
    float* bP = buf + OFF_BP;

    const size_t R1 = 2ull * G4_ * KPX;
    const size_t R2 = 2ull * G4_ * H_;
    const size_t R3 = (size_t)H_ * H_;
    const size_t R4 = (size_t)H_ * H_;
    const size_t R5 = 2ull * H_ * H_;
    const size_t R6 = 2ull * G4_;
    const size_t R7 = OFF_WYY - OFF_H;
    const size_t R8 = OFF_RL - OFF_RB;
    const size_t R9 = 4ull * B_ * T_ * H_;
    const size_t R10 = 16;
    const size_t TOT = R1 + R2 + R3 + R4 + R5 + R6 + R7 + R8 + R9 + R10;
    size_t stride = (size_t)gridDim.x * blockDim.x;
    for (size_t id = (size_t)blockIdx.x * blockDim.x + threadIdx.x; id < TOT; id += stride) {
        size_t i = id;
        if (i < R1) {
            int w = (int)(i / ((size_t)G4_ * KPX));
            size_t rem = i % ((size_t)G4_ * KPX);
            int np = (int)(rem / KPX), k = (int)(rem % KPX);
            int col = (np & 3) * H_ + (np >> 2);
            const float* W = w ? W2 : W1;
            float v = (k < D_) ? W[(size_t)k * G4_ + col] : 0.f;
            size_t o = ((size_t)(w * 2) * G4_ + np) * KPX + k;
            split_store(v, WxS + o, WxS + o + (size_t)G4_ * KPX);
            continue;
        }
        i -= R1;
        if (i < R2) {
            int w = (int)(i / ((size_t)G4_ * H_));
            size_t rem = i % ((size_t)G4_ * H_);
            int np = (int)(rem / H_), k = (int)(rem % H_);
            int col = (np & 3) * H_ + (np >> 2);
            const float* W = w ? W2 : W1;
            float v = W[(size_t)(D_ + k) * G4_ + col];
            size_t o = ((size_t)(w * 2) * G4_ + np) * H_ + k;
            split_store(v, WhS + o, WhS + o + (size_t)G4_ * H_);
            continue;
        }
        i -= R2;
        if (i < R3) {
            int n = (int)(i / H_), k = (int)(i % H_);
            size_t o = (size_t)n * H_ + k;
            split_store(Wy[(size_t)k * H_ + n], WyS + o, WyS + o + (size_t)H_ * H_);
            continue;
        }
        i -= R3;
        if (i < R4) {
            int n = (int)(i / H_), k = (int)(i % H_);
            size_t o = (size_t)n * H_ + k;
            split_store(Wh[(size_t)k * H_ + n], WhA + o, WhA + o + (size_t)H_ * H_);
            continue;
        }
        i -= R4;
        if (i < R5) {
            int n = (int)(i / H_), k = (int)(i % H_);
            float v = (n < H_) ? Wr[(size_t)k * H_ + n] : Wt[(size_t)k * H_ + (n - H_)];
            size_t o = (size_t)n * H_ + k;
            split_store(v, WcS + o, WcS + o + 2ull * H_ * H_);
            continue;
        }
        i -= R5;
        if (i < R6) {
            int w = (int)(i / G4_), np = (int)(i % G4_);
            int col = (np & 3) * H_ + (np >> 2);
            bP[i] = (w ? b2 : b1)[col];
            continue;
        }
        i -= R6;
        if (i < R7) { (buf + OFF_H)[i] = 0.f; continue; }
        i -= R7;
        if (i < R8) { (buf + OFF_RB)[i] = 0.f; continue; }
        i -= R8;
        if (i < R9) { (buf + OFF_Y)[i] = 0.f; continue; }
        i -= R9;
        ((int*)(buf + OFF_META))[M_SYNC + i] = 0;
    }
}

// ---------------- gather + sort (sort folded into CTA 0) ----------------
__global__ void __launch_bounds__(256) k_gather(
    float* __restrict__ e, const int* __restrict__ t1, const int* __restrict__ t2,
    const float* __restrict__ emb, const int* __restrict__ s1, const int* __restrict__ s2) {
    int tid = threadIdx.x;
    if (blockIdx.x == 0) {
        int* meta = (int*)(d_buf + OFF_META);
        __shared__ int sl[2][128];
        __shared__ int sl2s[256];
        __shared__ int cntA[256];
        __shared__ int totA;
        if (tid < 128) { sl[0][tid] = s1[tid]; sl[1][tid] = s2[tid]; }
        __syncthreads();
        {
            int c = tid >> 7, i = tid & 127;
            int v = sl[c][i], r = 0;
            for (int j = 0; j < 128; j++) {
                int u = sl[c][j];
                if (u > v || (u == v && j < i)) r++;
            }
            meta[(c ? M_PERM1 : M_PERM0) + r] = i;
            meta[(c ? M_IPOS1 : M_IPOS0) + i] = r;
            meta[(c ? M_SLS1  : M_SLS0)  + r] = v;
        }
        if (tid < 128) {
            int c = tid >> 6, t = tid & 63;
            int cnt = 0;
            for (int i = 0; i < 128; i++) cnt += (sl[c][i] > t);
            meta[(c ? M_MCNT1 : M_MCNT0) + t] = cnt;
        }
        {
            int a = tid >> 7, b = tid & 127;
            sl2s[tid] = a ? sl[0][b] : sl[1][b];
        }
        __syncthreads();
        {
            int v = sl2s[tid], r = 0;
            for (int j = 0; j < 256; j++) {
                int u = sl2s[j];
                if (u > v || (u == v && j < tid)) r++;
            }
            meta[M_PERM2 + r] = tid;
        }
        if (tid < 64) {
            int cnt = 0;
            for (int j = 0; j < 256; j++) cnt += (sl2s[j] > tid);
            meta[M_MCNT2 + tid] = cnt;
        }
        for (int c = 0; c < 2; c++) {
            int base = c ? M_ROWL1 : M_ROWL0;
            int myA = 0;
            for (int k = 0; k < 32; k++) {
                int row = tid * 32 + k;
                myA += ((row & 63) < sl[c][row >> 6]);
            }
            __syncthreads();
            cntA[tid] = myA;
            __syncthreads();
            if (tid == 0) {
                int s = 0;
                for (int i = 0; i < 256; i++) { int v = cntA[i]; cntA[i] = s; s += v; }
                totA = s;
                meta[M_NACT + c] = s;
            }
            __syncthreads();
            int pa = cntA[tid];
            int pd = totA + (tid * 32 - pa);
            for (int k = 0; k < 32; k++) {
                int row = tid * 32 + k;
                if ((row & 63) < sl[c][row >> 6]) meta[base + pa++] = row;
                else                              meta[base + pd++] = row;
            }
            __syncthreads();
        }
    }
    size_t total = 2ull * B_ * T_ * KPX;
    size_t stride = (size_t)gridDim.x * blockDim.x;
    for (size_t i = (size_t)blockIdx.x * blockDim.x + tid; i < total; i += stride) {
        int which = (int)(i / ((size_t)B_ * T_ * KPX));
        size_t rem = i % ((size_t)B_ * T_ * KPX);
        int bt = (int)(rem / KPX), k = (int)(rem % KPX);
        int tok = (which ? t2 : t1)[bt];
        e[i] = (k < D_) ? emb[(size_t)tok * D_ + k] : 0.f;
    }
}

// ---------------------------------------------------------------------------
// bulk GEMM engine, 256 threads / 8 warps sharing one pipeline (as R12).
// ---------------------------------------------------------------------------
struct MZ {
    const float*         A;
    const __nv_bfloat16* Bhi;
    const __nv_bfloat16* Blo;
    float*               C;
    const float*         bias;
    const int*           rows;
    const int*           nactp;
};
struct MP {
    MZ z[4];
    int Klen, lda, ldb, ldc;
};

__global__ void __launch_bounds__(256) mm_gemm(MP p) {
    extern __shared__ __align__(16) char smem_raw[];
    uint32_t sb = smem_u32(smem_raw);
    const MZ z = p.z[blockIdx.z];
    int tid = threadIdx.x, lane = tid & 31, wid = tid >> 5;
    int wg_n = wid & 3, wg_m = wid >> 2;
    int n0 = blockIdx.x * TN, m0 = blockIdx.y * TM;

    if (z.rows && m0 >= __ldg(z.nactp)) return;

    int tl = tid & 127;
    bool aAct = tid < 128;
    int arow = z.rows ? __ldg(z.rows + m0 + (tl >> 1)) : (m0 + (tl >> 1));
    const float* Ag = z.A + (size_t)arow * p.lda + (tl & 1) * 16;
    int brow = tid & 127, term = tid >> 7;
    const __nv_bfloat16* Bg = (term ? z.Blo : z.Bhi) + (size_t)(n0 + brow) * p.ldb;
    uint32_t aSt = (uint32_t)((tl >> 1) * PAD + (tl & 1) * 16) * 2;
    uint32_t bSt = (uint32_t)(brow * PAD) * 2;
    uint32_t aLd = (uint32_t)((lane & 15) * PAD + ((lane >> 4) << 3)) * 2;
    uint32_t bLd = (uint32_t)(((lane & 7) + ((lane & 16) >> 1)) * PAD + (lane & 8)) * 2;

    int nch = p.Klen / KC;
    float acc[2][4][4] = {};
    float fA[16];
    {
#pragma unroll
        for (int q = 0; q < 4; q++)
            CP_ASYNC16(sb + B_BASE(term, 0) + bSt + q * 16, Bg + q * 8);
        CP_COMMIT();
        if (aAct) {
            const float4* s4 = (const float4*)Ag;
#pragma unroll
            for (int q = 0; q < 4; q++) {
                float4 v = __ldcg(s4 + q);
                fA[4 * q] = v.x; fA[4 * q + 1] = v.y; fA[4 * q + 2] = v.z; fA[4 * q + 3] = v.w;
            }
            ushort hi[16], lo[16];
#pragma unroll
            for (int q = 0; q < 16; q++) {
                __nv_bfloat16 hb = __float2bfloat16_rn(fA[q]);
                __nv_bfloat16 lb = __float2bfloat16_rn(fA[q] - __bfloat162float(hb));
                hi[q] = *(ushort*)&hb; lo[q] = *(ushort*)&lb;
            }
            *(uint4*)(smem_raw + A_BASE(0, 0) + aSt)      = *(uint4*)(hi);
            *(uint4*)(smem_raw + A_BASE(0, 0) + aSt + 16) = *(uint4*)(hi + 8);
            *(uint4*)(smem_raw + A_BASE(1, 0) + aSt)      = *(uint4*)(lo);
            *(uint4*)(smem_raw + A_BASE(1, 0) + aSt + 16) = *(uint4*)(lo + 8);
        }
        CP_WAIT0();
        __syncthreads();
    }
    for (int ch = 0; ch < nch; ch++) {
        int s = ch & 1, ns = s ^ 1;
        bool more = (ch + 1) < nch;
        if (more) {
            const __nv_bfloat16* b2p = Bg + (ch + 1) * KC;
#pragma unroll
            for (int q = 0; q < 4; q++)
                CP_ASYNC16(sb + B_BASE(term, ns) + bSt + q * 16, b2p + q * 8);
            CP_COMMIT();
            if (aAct) {
                const float4* s4 = (const float4*)(Ag + (ch + 1) * KC);
#pragma unroll
                for (int q = 0; q < 4; q++) {
                    float4 v = __ldcg(s4 + q);
                    fA[4 * q] = v.x; fA[4 * q + 1] = v.y; fA[4 * q + 2] = v.z; fA[4 * q + 3] = v.w;
                }
            }
        }
#pragma unroll
        for (int h16 = 0; h16 < 2; h16++) {
            uint32_t kb = (uint32_t)h16 * 32;
            uint32_t bh[8], bl[8];
#pragma unroll
            for (int g2 = 0; g2 < 2; g2++) {
                uint32_t rowb = (uint32_t)((wg_n * 32 + g2 * 16) * PAD) * 2;
                LDSM4(bh[g2 * 4 + 0], bh[g2 * 4 + 1], bh[g2 * 4 + 2], bh[g2 * 4 + 3],
                      sb + B_BASE(0, s) + bLd + rowb + kb);
                LDSM4(bl[g2 * 4 + 0], bl[g2 * 4 + 1], bl[g2 * 4 + 2], bl[g2 * 4 + 3],
                      sb + B_BASE(1, s) + bLd + rowb + kb);
            }
#pragma unroll
            for (int k = 0; k < 2; k++) {
                int mt = 2 * wg_m + k;
                uint32_t ah[4], al[4];
                uint32_t rowa = (uint32_t)(mt * 16 * PAD) * 2;
                LDSM4(ah[0], ah[1], ah[2], ah[3], sb + A_BASE(0, s) + aLd + rowa + kb);
                LDSM4(al[0], al[1], al[2], al[3], sb + A_BASE(1, s) + aLd + rowa + kb);
#pragma unroll
                for (int nt = 0; nt < 4; nt++) {
                    int bi = (nt >> 1) * 4 + (nt & 1) * 2;
                    MMA16816(acc[k][nt], ah, bh[bi], bh[bi + 1]);
                    MMA16816(acc[k][nt], ah, bl[bi], bl[bi + 1]);
                    MMA16816(acc[k][nt], al, bh[bi], bh[bi + 1]);
                }
            }
        }
        if (more) {
            if (aAct) {
                ushort hi[16], lo[16];
#pragma unroll
                for (int q = 0; q < 16; q++) {
                    __nv_bfloat16 hb = __float2bfloat16_rn(fA[q]);
                    __nv_bfloat16 lb = __float2bfloat16_rn(fA[q] - __bfloat162float(hb));
                    hi[q] = *(ushort*)&hb; lo[q] = *(ushort*)&lb;
                }
                *(uint4*)(smem_raw + A_BASE(0, ns) + aSt)      = *(uint4*)(hi);
                *(uint4*)(smem_raw + A_BASE(0, ns) + aSt + 16) = *(uint4*)(hi + 8);
                *(uint4*)(smem_raw + A_BASE(1, ns) + aSt)      = *(uint4*)(lo);
                *(uint4*)(smem_raw + A_BASE(1, ns) + aSt + 16) = *(uint4*)(lo + 8);
            }
            CP_WAIT0();
        }
        __syncthreads();
    }

#pragma unroll
    for (int k = 0; k < 2; k++) {
        int mt = 2 * wg_m + k;
        int r = m0 + mt * 16 + (lane >> 2);
        int r0 = z.rows ? __ldg(z.rows + r) : r;
        int r1 = z.rows ? __ldg(z.rows + r + 8) : (r + 8);
#pragma unroll
        for (int nt = 0; nt < 4; nt++) {
            int c = n0 + wg_n * 32 + nt * 8 + (lane & 3) * 2;
            float b0 = 0.f, b1 = 0.f;
            if (z.bias) { b0 = z.bias[c]; b1 = z.bias[c + 1]; }
            *(float2*)(z.C + (size_t)r0 * p.ldc + c) =
                make_float2(acc[k][nt][0] + b0, acc[k][nt][1] + b1);
            *(float2*)(z.C + (size_t)r1 * p.ldc + c) =
                make_float2(acc[k][nt][2] + b0, acc[k][nt][3] + b1);
        }
    }
}

// ---------------------------------------------------------------------------
// Persistent LSTM scan: 512 threads / 16 warps, 4-slot 3-deep A pipeline,
// newly-frozen-band copy only.
// ---------------------------------------------------------------------------
__global__ void __launch_bounds__(512) k_lstm_persist() {
    extern __shared__ __align__(16) char smem[];
    uint32_t sb = smem_u32(smem);
    float* buf = d_buf;
    int* meta = (int*)(buf + OFF_META);
    int tid = threadIdx.x, lane = tid & 31, wid = tid >> 5;
    int wg_n = wid & 3, wg_m = wid >> 2;
    int blk = blockIdx.x;
    int r = blk >> 5, nt_ = blk & 31;
    int n0 = nt_ * 64;
    int widx = (r == 0 || r == 2) ? 0 : 1;
    int cls  = (r == 0 || r == 3) ? 0 : 1;
    const int* permc = meta + (cls ? M_PERM1 : M_PERM0);
    const int* slsrt = meta + (cls ? M_SLS1  : M_SLS0);
    const int* mcnt  = meta + (cls ? M_MCNT1 : M_MCNT0);

    // resident Wh slab
    {
        const __nv_bfloat16* WhS = (const __nv_bfloat16*)(buf + OFF_WHS);
        int tau = tid >> 8, rem = tid & 255;
        int n = rem >> 2, quar = rem & 3;
        const __nv_bfloat16* src = WhS + (size_t)(widx * 2 + tau) * G4_ * H_
                                   + (size_t)(n0 + n) * H_ + quar * 128;
        uint32_t dst = sb + (uint32_t)tau * 66560u + (uint32_t)n * 1040u + (uint32_t)quar * 256u;
#pragma unroll
        for (int q = 0; q < 16; q++) CP_ASYNC16(dst + q * 16, src + q * 8);
        CP_COMMIT(); CP_WAIT0(); __syncthreads();
    }

    const float* Xg  = buf + OFF_XG + (size_t)r * B_ * T_ * G4_;
    float*       cst = buf + OFF_C + (size_t)r * B_ * H_;
    float*       Yst = buf + OFF_Y + (size_t)r * B_ * T_ * H_;
    float*       hB  = buf + OFF_H;
    __nv_bfloat16* HBb = (__nv_bfloat16*)(buf + OFF_HB);
    unsigned* sync = (unsigned*)(meta + M_SYNC);
    const size_t HBUF = 4ull * B_ * H_;

    uint32_t aLd   = (uint32_t)((lane & 15) * 40 + ((lane >> 4) << 3)) * 2;
    uint32_t bBase = (uint32_t)(wg_n * 16) * 1040u
                   + (uint32_t)(((lane & 7) + ((lane & 16) >> 1)) * 520 + (lane & 8)) * 2;

    for (int t = 0; t < T_; t++) {
        int mcur  = __ldg(mcnt + t);
        int mtmax = (mcur + 15) >> 4;
        int mprev = (t >= 2) ? __ldg(mcnt + (t - 2)) : 128;
        int ppi = t & 1, ppo = ppi ^ 1;
        const float* hin  = hB + (size_t)ppi * HBUF + (size_t)r * B_ * H_;
        float*       hout = hB + (size_t)ppo * HBUF + (size_t)r * B_ * H_;
        const __nv_bfloat16* Ain = HBb + (size_t)ppi * 2 * P_HB + (size_t)r * B_ * H_;
        __nv_bfloat16*       ho  = HBb + (size_t)ppo * 2 * P_HB + (size_t)r * B_ * H_;

        float acc[2][2][4] = {};
        if (mtmax > 0) {
            int nrows = mtmax << 4;
            auto issueA = [&](int ch) {
                int slot = ch & 3;
                int tau = tid >> 8, rem = tid & 255;
                int row = rem >> 1, half = rem & 1;
                if (row < nrows) {
                    const __nv_bfloat16* src = Ain + (size_t)tau * P_HB + (size_t)row * H_
                                               + ch * 32 + half * 16;
                    uint32_t dst = sb + 133120u + (uint32_t)slot * 20480u
                                 + (uint32_t)tau * 10240u + (uint32_t)row * 80u + (uint32_t)half * 32u;
                    CP_ASYNC16(dst,      src);
                    CP_ASYNC16(dst + 16, src + 8);
                }
                CP_COMMIT();
            };
            issueA(0); issueA(1); issueA(2);
            for (int ch = 0; ch < 16; ch++) {
                if (ch <= 12) { CP_WAIT2(); }
                else if (ch == 13) { CP_WAIT1(); }
                else { CP_WAIT0(); }
                __syncthreads();
                if (ch + 3 < 16) issueA(ch + 3);
                uint32_t abase = sb + 133120u + (uint32_t)(ch & 3) * 20480u;
#pragma unroll
                for (int h16 = 0; h16 < 2; h16++) {
                    uint32_t kb = (uint32_t)(ch * 32 + h16 * 16) * 2;
                    uint32_t bA[4], bB[4];
                    LDSM4(bA[0], bA[1], bA[2], bA[3], sb + bBase + kb);
                    LDSM4(bB[0], bB[1], bB[2], bB[3], sb + 66560u + bBase + kb);
#pragma unroll
                    for (int k = 0; k < 2; k++) {
                        int mt = 4 * k + wg_m;
                        if (mt < mtmax) {
                            uint32_t ah[4], al[4];
                            uint32_t rowa = (uint32_t)(mt * 16 * 80);
                            LDSM4(ah[0], ah[1], ah[2], ah[3], abase + aLd + rowa + h16 * 32);
                            LDSM4(al[0], al[1], al[2], al[3], abase + 10240u + aLd + rowa + h16 * 32);
                            MMA16816(acc[k][0], ah, bA[0], bA[1]);
                            MMA16816(acc[k][0], ah, bB[0], bB[1]);
                            MMA16816(acc[k][0], al, bA[0], bA[1]);
                            MMA16816(acc[k][1], ah, bA[2], bA[3]);
                            MMA16816(acc[k][1], ah, bB[2], bB[3]);
                            MMA16816(acc[k][1], al, bA[2], bA[3]);
                        }
                    }
                }
            }
        }

        // epilogue: active mts owned by this warp
#pragma unroll
        for (int k = 0; k < 2; k++) {
            int mt = 4 * k + wg_m;
            if (mt < mtmax) {
                int b = mt * 16 + (lane >> 2);
#pragma unroll
                for (int nt = 0; nt < 2; nt++) {
                    float fo0 = __shfl_xor_sync(0xffffffffu, acc[k][nt][0], 1);
                    float fo1 = __shfl_xor_sync(0xffffffffu, acc[k][nt][1], 1);
                    float fo2 = __shfl_xor_sync(0xffffffffu, acc[k][nt][2], 1);
                    float fo3 = __shfl_xor_sync(0xffffffffu, acc[k][nt][3], 1);
                    if (!(lane & 1)) {
#pragma unroll
                        for (int half = 0; half < 2; half++) {
                            int bb = b + half * 8;
                            float gi = half ? acc[k][nt][2] : acc[k][nt][0];
                            float gj = half ? acc[k][nt][3] : acc[k][nt][1];
                            float gf = half ? fo2 : fo0;
                            float go = half ? fo3 : fo1;
                            int c0 = n0 + wg_n * 16 + nt * 8 + (lane & 3) * 2;
                            int j = c0 >> 2;
                            size_t ci = (size_t)bb * H_ + j;
                            int slv = __ldg(slsrt + bb);
                            float hv;
                            if (t < slv) {
                                int ob = __ldg(permc + bb);
                                float4 x = *(const float4*)(Xg + ((size_t)ob * T_ + t) * G4_ + c0);
                                gi += x.x; gj += x.y; gf += x.z; go += x.w;
                                float cc = cst[ci];
                                float cn = cc * sigf(gf + 1.f) + sigf(gi) * ftanh(gj);
                                hv = ftanh(cn) * sigf(go);
                                cst[ci] = cn;
                                Yst[((size_t)ob * T_ + t) * H_ + j] = hv;
                            } else {
                                hv = __ldcg(hin + ci);
                            }
                            hout[ci] = hv;
                            split_store(hv, ho + ci, ho + P_HB + ci);
                        }
                    }
                }
            }
        }
        // newly-frozen band copy: rows [mcur, mprev), this CTA's 16 j-slice
        {
            int band = mprev - mcur;
            for (int idx = tid; idx < band * 16; idx += 512) {
                int rr = mcur + (idx >> 4);
                int jj = (n0 >> 2) + (idx & 15);
                size_t ci = (size_t)rr * H_ + jj;
                float hv = __ldcg(hin + ci);
                hout[ci] = hv;
                ho[ci]        = Ain[ci];
                ho[P_HB + ci] = Ain[P_HB + ci];
            }
        }
        gbar(sync + 0, sync + 1, (unsigned)(t + 1), 128u);
    }
}

// ---------------------------------------------------------------------------
// Persistent attention scan: 512 threads / 16 warps, 4-slot 3-deep pipeline.
// ---------------------------------------------------------------------------
__global__ void __launch_bounds__(512) k_att_persist(
    const float* __restrict__ wv,
    const int* __restrict__ s1, const int* __restrict__ s2) {
    extern __shared__ __align__(16) char smem[];
    uint32_t sb = smem_u32(smem);
    float* smf = (float*)(smem + 69632);
    float* buf = d_buf;
    int* meta = (int*)(buf + OFF_META);
    int tid = threadIdx.x, lane = tid & 31, wid = tid >> 5;
    int wg_n = wid & 3, wg_m = wid >> 2;
    int blk = blockIdx.x;

    int ks  = blk & 3;
    int mt_ = (blk >> 2) & 3;
    int nt_ = blk >> 4;
    int m0 = mt_ * 64, n0 = nt_ * 128, kst = ks * 128;

    // resident Wc slab
    {
        const __nv_bfloat16* WcS = (const __nv_bfloat16*)(buf + OFF_WCS);
        int tau = tid >> 8, rem = tid & 255;
        int row = rem >> 1, half = rem & 1;
        const __nv_bfloat16* src = WcS + (size_t)tau * 2 * H_ * H_
                                   + (size_t)(n0 + row) * H_ + kst + half * 64;
        uint32_t dst = sb + (uint32_t)tau * 34816u + (uint32_t)row * 272u + (uint32_t)half * 128u;
#pragma unroll
        for (int q = 0; q < 8; q++) CP_ASYNC16(dst + q * 16, src + q * 8);
        CP_COMMIT(); CP_WAIT0(); __syncthreads();
    }

    __nv_bfloat16* RBb = (__nv_bfloat16*)(buf + OFF_RB);
    float* uPt4 = buf + OFF_UPT;
    float* rL   = buf + OFF_RL;
    const float* WyY = buf + OFF_WYY;
    const float* HWy = buf + OFF_HWY;
    const float* Yb  = buf + OFF_Y;
    unsigned* sync = (unsigned*)(meta + M_SYNC);
    const int* mcnt2 = meta + M_MCNT2;

    uint32_t aLd = (uint32_t)((lane & 15) * 40 + ((lane >> 4) << 3)) * 2;
    uint32_t bLd = (uint32_t)(((lane & 7) + ((lane & 16) >> 1)) * 136 + (lane & 8)) * 2;

    float wvr[16];
#pragma unroll
    for (int k = 0; k < 16; k++) wvr[k] = __ldg(wv + lane + 32 * k);

    int spA = blk * 2, spB = blk * 2 + 1;
    int pA = meta[M_PERM2 + spA], pB = meta[M_PERM2 + spB];
    int aA = pA >> 7, bA = pA & 127;
    int aB = pB >> 7, bB = pB & 127;
    int sl2A = aA ? s1[bA] : s2[bA];
    int sl2B = aB ? s1[bB] : s2[bB];
    int slmA = aA ? s2[bA] : s1[bA];
    int slmB = aB ? s2[bB] : s1[bB];

    for (int t = 0; t < T_; t++) {
        int mcur2 = __ldg(mcnt2 + t);
        int mtloc = 0;
        if (mcur2 > m0) { mtloc = (mcur2 - m0 + 15) >> 4; if (mtloc > 4) mtloc = 4; }

        if (mtloc > 0) {
            int nrows = mtloc << 4;
            auto issueA = [&](int ch) {
                int slot = ch & 3;
                int row = tid >> 1, tau = tid & 1;
                if (tid < 128 && row < nrows) {
                    const __nv_bfloat16* src = RBb + (size_t)tau * P_RB
                                               + (size_t)(m0 + row) * H_ + kst + ch * 32;
                    uint32_t dst = sb + 69632u + (uint32_t)slot * 10240u
                                 + (uint32_t)tau * 5120u + (uint32_t)row * 80u;
                    CP_ASYNC16(dst,      src);
                    CP_ASYNC16(dst + 16, src + 8);
                    CP_ASYNC16(dst + 32, src + 16);
                    CP_ASYNC16(dst + 48, src + 24);
                }
                CP_COMMIT();
            };
            issueA(0); issueA(1); issueA(2);
            float acc[4][4] = {};
            for (int ch = 0; ch < 4; ch++) {
                if (ch <= 1) { CP_WAIT2(); }
                else if (ch == 2) { CP_WAIT1(); }
                else { CP_WAIT0(); }
                __syncthreads();
                if (ch + 3 < 4) issueA(ch + 3);
                uint32_t abase = sb + 69632u + (uint32_t)(ch & 3) * 10240u;
#pragma unroll
                for (int h16 = 0; h16 < 2; h16++) {
                    uint32_t kb = (uint32_t)(ch * 32 + h16 * 16) * 2;
                    uint32_t bh[8], bl[8];
#pragma unroll
                    for (int g2 = 0; g2 < 2; g2++) {
                        uint32_t rowb = (uint32_t)((wg_n * 32 + g2 * 16) * 136) * 2;
                        LDSM4(bh[g2 * 4 + 0], bh[g2 * 4 + 1], bh[g2 * 4 + 2], bh[g2 * 4 + 3],
                              sb + bLd + rowb + kb);
                        LDSM4(bl[g2 * 4 + 0], bl[g2 * 4 + 1], bl[g2 * 4 + 2], bl[g2 * 4 + 3],
                              sb + 34816u + bLd + rowb + kb);
                    }
                    if (wg_m < mtloc) {
                        uint32_t ah[4], al[4];
                        uint32_t rowa = (uint32_t)(wg_m * 16 * 80);
                        LDSM4(ah[0], ah[1], ah[2], ah[3], abase + aLd + rowa + h16 * 32);
                        LDSM4(al[0], al[1], al[2], al[3], abase + 5120u + aLd + rowa + h16 * 32);
#pragma unroll
                        for (int nt = 0; nt < 4; nt++) {
                            int bi = (nt >> 1) * 4 + (nt & 1) * 2;
                            MMA16816(acc[nt], ah, bh[bi], bh[bi + 1]);
                            MMA16816(acc[nt], ah, bl[bi], bl[bi + 1]);
                            MMA16816(acc[nt], al, bh[bi], bh[bi + 1]);
                        }
                    }
                }
            }
            if (wg_m < mtloc) {
                float* Cb = uPt4 + (size_t)ks * 256 * 1024;
                int rr = m0 + wg_m * 16 + (lane >> 2);
#pragma unroll
                for (int nt = 0; nt < 4; nt++) {
                    int c = n0 + wg_n * 32 + nt * 8 + (lane & 3) * 2;
                    *(float2*)(Cb + (size_t)rr * 1024 + c) =
                        make_float2(acc[nt][0], acc[nt][1]);
                    *(float2*)(Cb + (size_t)(rr + 8) * 1024 + c) =
                        make_float2(acc[nt][2], acc[nt][3]);
                }
            }
        }
        gbar(sync + 2, sync + 3, (unsigned)(2 * t + 1), 128u);

        // phase A: two sorted pairs, exact skipping, 16 warps
        for (int pi = 0; pi < 2; pi++) {
            int sp   = pi ? spB : spA;
            int p    = pi ? pB : pA;
            int a    = pi ? aB : aA;
            int b    = pi ? bB : bA;
            int sl2  = pi ? sl2B : sl2A;
            int slm  = pi ? slmB : slmA;
            if (t >= sl2) continue;

            float* su  = smf;
            float* spt = smf + 512;
            float* sc  = smf + 1024;
            const float* hb = HWy + (size_t)a * B_ * T_ * H_ + ((size_t)b * T_ + t) * H_;
            {
                int h = tid;
                float s0 = 0.f, s1v = 0.f;
#pragma unroll
                for (int k = 0; k < 4; k++) {
                    const float* up = uPt4 + ((size_t)k * 256 + sp) * 1024;
                    s0  += __ldcg(up + h);
                    s1v += __ldcg(up + 512 + h);
                }
                su[h]  = s0 + __ldg(hb + h);
                spt[h] = s1v;
            }
            __syncthreads();
            const float* WyYb = WyY + (size_t)a * B_ * T_ * H_ + (size_t)b * T_ * H_;
#pragma unroll
            for (int q = 0; q < 4; q++) {
                int t2 = wid * 4 + q;
                if (t2 < slm) {
                    const float* row = WyYb + (size_t)t2 * H_;
                    float s = 0.f;
#pragma unroll
                    for (int k = 0; k < 16; k++) {
                        int hh = lane + 32 * k;
                        s += tanha(__ldg(row + hh) + su[hh]) * wvr[k];
                    }
                    for (int o = 16; o; o >>= 1) s += __shfl_xor_sync(0xffffffffu, s, o);
                    if (lane == 0) sc[t2] = s;
                } else if (lane == 0) {
                    sc[t2] = -10000.f;
                }
            }
            __syncthreads();
            if (wid == 0) {
                float v1 = sc[lane], v2 = sc[lane + 32];
                float m = fmaxf(v1, v2);
                for (int o = 16; o; o >>= 1) m = fmaxf(m, __shfl_xor_sync(0xffffffffu, m, o));
                float e1 = __expf(v1 - m), e2 = __expf(v2 - m);
                float s = e1 + e2;
                for (int o = 16; o; o >>= 1) s += __shfl_xor_sync(0xffffffffu, s, o);
                float inv = __fdividef(1.f, s);
                sc[lane] = e1 * inv;
                sc[lane + 32] = e2 * inv;
            }
            __syncthreads();
            const float* Yp = Yb + (size_t)(a ? 2 : 0) * B_ * T_ * H_ + (size_t)b * T_ * H_;
            {
                int h = tid;
                float accv = 0.f;
                for (int t2 = 0; t2 < slm; t2++)
                    accv += sc[t2] * __ldg(Yp + (size_t)t2 * H_ + h);
                float rn = accv + ftanh(spt[h]);
                if (t == sl2 - 1) {
                    rL[(size_t)p * H_ + h] = rn;
                } else {
                    split_store(rn, RBb + (size_t)sp * H_ + h, RBb + P_RB + (size_t)sp * H_ + h);
                }
            }
            __syncthreads();
        }
        gbar(sync + 2, sync + 3, (unsigned)(2 * t + 2), 128u);
    }
}

// ---------------- final projection ----------------
__global__ void __launch_bounds__(512) k_final(
    const float* __restrict__ rL, const float* __restrict__ hfin,
    const float* __restrict__ Wp, const float* __restrict__ Wx,
    const float* __restrict__ U, const float* __restrict__ bU,
    float* __restrict__ out) {
    int b = blockIdx.x;
    int tid = threadIdx.x;
    const int* meta = (const int*)(d_buf + OFF_META);
    int ip1 = meta[M_IPOS1 + b];
    int ip0 = meta[M_IPOS0 + b];
    __shared__ float s_in[4][512];
    __shared__ float s_sum[512];
    __shared__ float red0[16], red1[16];
    s_in[0][tid] = rL[(size_t)b * H_ + tid];
    s_in[1][tid] = hfin[((size_t)1 * B_ + ip1) * H_ + tid];
    s_in[2][tid] = rL[((size_t)B_ + b) * H_ + tid];
    s_in[3][tid] = hfin[((size_t)3 * B_ + ip0) * H_ + tid];
    __syncthreads();
    float acc0 = 0.f, acc1 = 0.f;
    for (int k = 0; k < H_; k++) {
        float wp = Wp[(size_t)k * H_ + tid];
        float wx = Wx[(size_t)k * H_ + tid];
        acc0 += s_in[0][k] * wp + s_in[1][k] * wx;
        acc1 += s_in[2][k] * wp + s_in[3][k] * wx;
    }
    s_sum[tid] = ftanh(acc0) + ftanh(acc1);
    __syncthreads();
    float p0 = s_sum[tid] * U[(size_t)tid * 2 + 0];
    float p1 = s_sum[tid] * U[(size_t)tid * 2 + 1];
    for (int o = 16; o; o >>= 1) {
        p0 += __shfl_xor_sync(0xffffffffu, p0, o);
        p1 += __shfl_xor_sync(0xffffffffu, p1, o);
    }
    int wp_ = tid >> 5;
    if ((tid & 31) == 0) { red0[wp_] = p0; red1[wp_] = p1; }
    __syncthreads();
    if (tid < 16) {
        p0 = red0[tid]; p1 = red1[tid];
        for (int o = 8; o; o >>= 1) {
            p0 += __shfl_xor_sync(0x0000ffffu, p0, o);
            p1 += __shfl_xor_sync(0x0000ffffu, p1, o);
        }
        if (tid == 0) {
            out[b * 2 + 0] = p0 + bU[0];
            out[b * 2 + 1] = p1 + bU[1];
        }
    }
}

// ---------------- host ----------------
extern "C" void kernel_launch(void* const* d_in, const int* in_sizes, int n_in,
                              void* d_out, int out_size) {
    (void)in_sizes; (void)n_in; (void)out_size;
    const int*   tokens1 = (const int*)d_in[0];
    const int*   tokens2 = (const int*)d_in[1];
    const int*   seqlen1 = (const int*)d_in[2];
    const int*   seqlen2 = (const int*)d_in[3];
    const float* emb = (const float*)d_in[4];
    const float* W1  = (const float*)d_in[5];
    const float* b1  = (const float*)d_in[6];
    const float* W2  = (const float*)d_in[7];
    const float* b2  = (const float*)d_in[8];
    const float* Wy  = (const float*)d_in[9];
    const float* Wh  = (const float*)d_in[10];
    const float* Wr  = (const float*)d_in[11];
    const float* wv  = (const float*)d_in[12];
    const float* Wt  = (const float*)d_in[13];
    const float* Wp  = (const float*)d_in[14];
    const float* Wx  = (const float*)d_in[15];
    const float* U   = (const float*)d_in[16];
    const float* bU  = (const float*)d_in[17];
    float* out = (float*)d_out;

    cudaFuncSetAttribute(mm_gemm, cudaFuncAttributeMaxDynamicSharedMemorySize, SMEM_MM);
    cudaFuncSetAttribute(k_lstm_persist, cudaFuncAttributeMaxDynamicSharedMemorySize, SMEM_LSTM);
    cudaFuncSetAttribute(k_att_persist, cudaFuncAttributeMaxDynamicSharedMemorySize, SMEM_ATT);

    float* buf = nullptr;
    cudaGetSymbolAddress((void**)&buf, d_buf);
    float* e    = buf + OFF_E;
    float* Xg   = buf + OFF_XG;
    float* Yb   = buf + OFF_Y;
    float* hBuf = buf + OFF_H;
    float* WyY  = buf + OFF_WYY;
    float* HWy  = buf + OFF_HWY;
    float* rL   = buf + OFF_RL;
    float* bP   = buf + OFF_BP;
    int*   meta = (int*)(buf + OFF_META);
    __nv_bfloat16* WxS = (__nv_bfloat16*)(buf + OFF_WXS);
    __nv_bfloat16* WyS = (__nv_bfloat16*)(buf + OFF_WYS);
    __nv_bfloat16* WhA = (__nv_bfloat16*)(buf + OFF_WHA);

    // launch #1: prep, #2: gather+sort
    k_prep<<<2048, 256>>>(W1, W2, Wy, Wh, Wr, Wt, b1, b2);
    k_gather<<<2048, 256>>>(e, tokens1, tokens2, emb, seqlen1, seqlen2);

    const int iidx[4] = {0, 1, 1, 0}, widx[4] = {0, 1, 0, 1};
    const int xcls[4] = {0, 1, 1, 0};

    // launch #3: X GEMM
    {
        MP p = {};
        for (int r = 0; r < 4; r++) {
            p.z[r].A     = e + (size_t)iidx[r] * B_ * T_ * KPX;
            p.z[r].Bhi   = WxS + (size_t)(widx[r] * 2 + 0) * G4_ * KPX;
            p.z[r].Blo   = WxS + (size_t)(widx[r] * 2 + 1) * G4_ * KPX;
            p.z[r].C     = Xg + (size_t)r * B_ * T_ * G4_;
            p.z[r].bias  = bP + (size_t)widx[r] * G4_;
            p.z[r].rows  = meta + (xcls[r] ? M_ROWL1 : M_ROWL0);
            p.z[r].nactp = meta + M_NACT + xcls[r];
        }
        p.Klen = KPX; p.lda = KPX; p.ldb = KPX; p.ldc = G4_;
        mm_gemm<<<dim3(G4_ / TN, (B_ * T_) / TM, 4), 256, SMEM_MM>>>(p);
    }

    // launch #4 (ncu target): persistent LSTM scan
    k_lstm_persist<<<128, 512, SMEM_LSTM>>>();

    // launch #5: WyY + HWy
    {
        MP p = {};
        const int runs[4] = {0, 2, 1, 3};
        const int qcls[4] = {0, 1, 1, 0};
        for (int q = 0; q < 4; q++) {
            p.z[q].A     = Yb + (size_t)runs[q] * B_ * T_ * H_;
            p.z[q].Bhi   = (q < 2 ? WyS : WhA);
            p.z[q].Blo   = (q < 2 ? WyS : WhA) + (size_t)H_ * H_;
            p.z[q].C     = (q < 2 ? WyY + (size_t)q * B_ * T_ * H_
                                  : HWy + (size_t)(q - 2) * B_ * T_ * H_);
            p.z[q].bias  = nullptr;
            p.z[q].rows  = meta + (qcls[q] ? M_ROWL1 : M_ROWL0);
            p.z[q].nactp = meta + M_NACT + qcls[q];
        }
        p.Klen = H_; p.lda = H_; p.ldb = H_; p.ldc = H_;
        mm_gemm<<<dim3(H_ / TN, (B_ * T_) / TM, 4), 256, SMEM_MM>>>(p);
    }

    // launch #6: persistent attention scan
    k_att_persist<<<128, 512, SMEM_ATT>>>(wv, seqlen1, seqlen2);

    // launch #7
    k_final<<<B_, 512>>>(rL, hBuf, Wp, Wx, U, bU, out);
}

// round 14
// speedup vs baseline: 2.1983x; 1.0456x over previous
#include <cuda_runtime.h>
#include <cuda_bf16.h>
#include <math.h>
#include <stdint.h>

#define B_   128
#define T_   64
#define D_   300
#define KPX  320
#define H_   512
#define G4_  2048

#define TM 64
#define TN 128
#define KC 32
#define PAD 40
#define A_BASE(term,stage) ((uint32_t)(((term)*2+(stage))*5120))
#define B_BASE(term,stage) ((uint32_t)(20480u + ((term)*2+(stage))*10240u))
static constexpr int SMEM_MM   = 61440;
static constexpr int SMEM_LSTM = 133120 + 4 * 20480;   // 215040
static constexpr int SMEM_ATT  = 69632 + 4 * 10240;    // 110592

__device__ __forceinline__ uint32_t smem_u32(const void* p) {
    uint32_t a;
    asm("{ .reg .u64 t; cvta.to.shared.u64 t, %1; cvt.u32.u64 %0, t; }" : "=r"(a) : "l"(p));
    return a;
}
#define CP_ASYNC16(dst, src) \
    asm volatile("cp.async.cg.shared.global [%0], [%1], 16;" :: "r"(dst), "l"(src))
#define CP_COMMIT() asm volatile("cp.async.commit_group;" ::: "memory")
#define CP_WAIT0()  asm volatile("cp.async.wait_group 0;" ::: "memory")
#define CP_WAIT1()  asm volatile("cp.async.wait_group 1;" ::: "memory")
#define CP_WAIT2()  asm volatile("cp.async.wait_group 2;" ::: "memory")
#define BARH(id)    asm volatile("bar.sync %0, 256;" :: "r"(id) : "memory")
#define LDSM4(r0, r1, r2, r3, addr) \
    asm volatile("ldmatrix.sync.aligned.m8n8.x4.shared.b16 {%0,%1,%2,%3}, [%4];" \
                 : "=r"(r0), "=r"(r1), "=r"(r2), "=r"(r3) : "r"(addr))
#define MMA16816(c, a, b0, b1) \
    asm volatile("mma.sync.aligned.m16n8k16.row.col.f32.bf16.bf16.f32 " \
                 "{%0,%1,%2,%3}, {%4,%5,%6,%7}, {%8,%9}, {%0,%1,%2,%3};" \
                 : "+f"((c)[0]), "+f"((c)[1]), "+f"((c)[2]), "+f"((c)[3]) \
                 : "r"((a)[0]), "r"((a)[1]), "r"((a)[2]), "r"((a)[3]), \
                   "r"(b0), "r"(b1))

__device__ __forceinline__ float sigf(float x) { return __fdividef(1.f, 1.f + __expf(-x)); }
__device__ __forceinline__ float ftanh(float x) { return 1.f - __fdividef(2.f, __expf(2.f * x) + 1.f); }
__device__ __forceinline__ float tanha(float x) {
    float y; asm("tanh.approx.f32 %0, %1;" : "=f"(y) : "f"(x)); return y;
}

static constexpr size_t P_HB = 4ull * B_ * H_;
static constexpr size_t P_RB = 256ull * H_;

// ---------------- scratch layout (float units) ----------------
static constexpr size_t OFF_E    = 0;
static constexpr size_t OFF_XG   = OFF_E   + 2ull * B_ * T_ * KPX;
static constexpr size_t OFF_Y    = OFF_XG  + 4ull * B_ * T_ * G4_;
static constexpr size_t OFF_H    = OFF_Y   + 4ull * B_ * T_ * H_;
static constexpr size_t OFF_HB   = OFF_H   + 2ull * 4 * B_ * H_;
static constexpr size_t OFF_C    = OFF_HB  + (2ull * 2 * P_HB) / 2;
static constexpr size_t OFF_WYY  = OFF_C   + 4ull * B_ * H_;
static constexpr size_t OFF_HWY  = OFF_WYY + 2ull * B_ * T_ * H_;
static constexpr size_t OFF_UPT  = OFF_HWY + 2ull * B_ * T_ * H_;
static constexpr size_t OFF_RB   = OFF_UPT + 4ull * 256 * 1024;
static constexpr size_t OFF_RL   = OFF_RB  + (2ull * P_RB) / 2;
static constexpr size_t OFF_BP   = OFF_RL  + 256ull * H_;
static constexpr size_t OFF_WXS  = OFF_BP  + 2ull * G4_;
static constexpr size_t OFF_WHS  = OFF_WXS + (2ull * 2 * G4_ * KPX) / 2;
static constexpr size_t OFF_WYS  = OFF_WHS + (2ull * 2 * G4_ * H_) / 2;
static constexpr size_t OFF_WHA  = OFF_WYS + (2ull * H_ * H_) / 2;
static constexpr size_t OFF_WCS  = OFF_WHA + (2ull * H_ * H_) / 2;
static constexpr size_t OFF_META = OFF_WCS + (2ull * 2 * H_ * H_) / 2;
#define M_PERM0 0
#define M_PERM1 128
#define M_IPOS0 256
#define M_IPOS1 384
#define M_SLS0  512
#define M_SLS1  640
#define M_MCNT0 768
#define M_MCNT1 832
#define M_PERM2 896
#define M_MCNT2 1152
#define M_ROWL0 1216
#define M_ROWL1 9408
#define M_NACT  17600
#define M_SYNC  17608
static constexpr size_t META_N  = 17640;
static constexpr size_t TOTAL_F = OFF_META + META_N;

__device__ __align__(256) float d_buf[TOTAL_F];

__device__ __forceinline__ void split_store(float v, __nv_bfloat16* hi, __nv_bfloat16* lo) {
    __nv_bfloat16 h = __float2bfloat16_rn(v);
    *hi = h;
    *lo = __float2bfloat16_rn(v - __bfloat162float(h));
}

// ---------------- grid barrier ----------------
__device__ __forceinline__ void gbar(unsigned* cnt, unsigned* rel,
                                     unsigned seq, unsigned ncta) {
    __syncthreads();
    if (threadIdx.x == 0) {
        unsigned old;
        asm volatile("fence.acq_rel.gpu;" ::: "memory");
        asm volatile("atom.relaxed.gpu.global.add.u32 %0, [%1], 1;"
                     : "=r"(old) : "l"(cnt) : "memory");
        if (old + 1u == ncta * seq) {
            asm volatile("st.release.gpu.global.u32 [%0], %1;"
                         :: "l"(rel), "r"(seq) : "memory");
        }
        unsigned v;
        do {
            asm volatile("ld.acquire.gpu.global.u32 %0, [%1];"
                         : "=r"(v) : "l"(rel) : "memory");
        } while (v < seq);
    }
    __syncthreads();
}

// ---------------- prep ----------------
__global__ void k_prep(const float* __restrict__ W1, const float* __restrict__ W2,
                       const float* __restrict__ Wy, const float* __restrict__ Wh,
                       const float* __restrict__ Wr, const float* __restrict__ Wt,
                       const float* __restrict__ b1, const float* __restrict__ b2) {
    float* buf = d_buf;
    __nv_bfloat16* WxS = (__nv_bfloat16*)(buf + OFF_WXS);
    __nv_bfloat16* WhS = (__nv_bfloat16*)(buf + OFF_WHS);
    __nv_bfloat16* WyS = (__nv_bfloat16*)(buf + OFF_WYS);
    __nv_bfloat16* WhA = (__nv_bfloat16*)(buf + OFF_WHA);
    __nv_bfloat16* WcS = (__nv_bfloat16*)(buf + OFF_WCS);
    float* bP = buf + OFF_BP;

    const size_t R1 = 2ull * G4_ * KPX;
    const size_t R2 = 2ull * G4_ * H_;
    const size_t R3 = (size_t)H_ * H_;
    const size_t R4 = (size_t)H_ * H_;
    const size_t R5 = 2ull * H_ * H_;
    const size_t R6 = 2ull * G4_;
    const size_t R7 = OFF_WYY - OFF_H;
    const size_t R8 = OFF_RL - OFF_RB;
    const size_t R9 = 4ull * B_ * T_ * H_;
    const size_t R10 = 16;
    const size_t TOT = R1 + R2 + R3 + R4 + R5 + R6 + R7 + R8 + R9 + R10;
    size_t stride = (size_t)gridDim.x * blockDim.x;
    for (size_t id = (size_t)blockIdx.x * blockDim.x + threadIdx.x; id < TOT; id += stride) {
        size_t i = id;
        if (i < R1) {
            int w = (int)(i / ((size_t)G4_ * KPX));
            size_t rem = i % ((size_t)G4_ * KPX);
            int np = (int)(rem / KPX), k = (int)(rem % KPX);
            int col = (np & 3) * H_ + (np >> 2);
            const float* W = w ? W2 : W1;
            float v = (k < D_) ? W[(size_t)k * G4_ + col] : 0.f;
            size_t o = ((size_t)(w * 2) * G4_ + np) * KPX + k;
            split_store(v, WxS + o, WxS + o + (size_t)G4_ * KPX);
            continue;
        }
        i -= R1;
        if (i < R2) {
            int w = (int)(i / ((size_t)G4_ * H_));
            size_t rem = i % ((size_t)G4_ * H_);
            int np = (int)(rem / H_), k = (int)(rem % H_);
            int col = (np & 3) * H_ + (np >> 2);
            const float* W = w ? W2 : W1;
            float v = W[(size_t)(D_ + k) * G4_ + col];
            size_t o = ((size_t)(w * 2) * G4_ + np) * H_ + k;
            split_store(v, WhS + o, WhS + o + (size_t)G4_ * H_);
            continue;
        }
        i -= R2;
        if (i < R3) {
            int n = (int)(i / H_), k = (int)(i % H_);
            size_t o = (size_t)n * H_ + k;
            split_store(Wy[(size_t)k * H_ + n], WyS + o, WyS + o + (size_t)H_ * H_);
            continue;
        }
        i -= R3;
        if (i < R4) {
            int n = (int)(i / H_), k = (int)(i % H_);
            size_t o = (size_t)n * H_ + k;
            split_store(Wh[(size_t)k * H_ + n], WhA + o, WhA + o + (size_t)H_ * H_);
            continue;
        }
        i -= R4;
        if (i < R5) {
            int n = (int)(i / H_), k = (int)(i % H_);
            float v = (n < H_) ? Wr[(size_t)k * H_ + n] : Wt[(size_t)k * H_ + (n - H_)];
            size_t o = (size_t)n * H_ + k;
            split_store(v, WcS + o, WcS + o + 2ull * H_ * H_);
            continue;
        }
        i -= R5;
        if (i < R6) {
            int w = (int)(i / G4_), np = (int)(i % G4_);
            int col = (np & 3) * H_ + (np >> 2);
            bP[i] = (w ? b2 : b1)[col];
            continue;
        }
        i -= R6;
        if (i < R7) { (buf + OFF_H)[i] = 0.f; continue; }
        i -= R7;
        if (i < R8) { (buf + OFF_RB)[i] = 0.f; continue; }
        i -= R8;
        if (i < R9) { (buf + OFF_Y)[i] = 0.f; continue; }
        i -= R9;
        ((int*)(buf + OFF_META))[M_SYNC + i] = 0;
    }
}

// ---------------- gather + sort (sort in CTA 0) ----------------
__global__ void __launch_bounds__(256) k_gather(
    float* __restrict__ e, const int* __restrict__ t1, const int* __restrict__ t2,
    const float* __restrict__ emb, const int* __restrict__ s1, const int* __restrict__ s2) {
    int tid = threadIdx.x;
    if (blockIdx.x == 0) {
        int* meta = (int*)(d_buf + OFF_META);
        __shared__ int sl[2][128];
        __shared__ int sl2s[256];
        __shared__ int cntA[256];
        __shared__ int totA;
        if (tid < 128) { sl[0][tid] = s1[tid]; sl[1][tid] = s2[tid]; }
        __syncthreads();
        {
            int c = tid >> 7, i = tid & 127;
            int v = sl[c][i], r = 0;
            for (int j = 0; j < 128; j++) {
                int u = sl[c][j];
                if (u > v || (u == v && j < i)) r++;
            }
            meta[(c ? M_PERM1 : M_PERM0) + r] = i;
            meta[(c ? M_IPOS1 : M_IPOS0) + i] = r;
            meta[(c ? M_SLS1  : M_SLS0)  + r] = v;
        }
        if (tid < 128) {
            int c = tid >> 6, t = tid & 63;
            int cnt = 0;
            for (int i = 0; i < 128; i++) cnt += (sl[c][i] > t);
            meta[(c ? M_MCNT1 : M_MCNT0) + t] = cnt;
        }
        {
            int a = tid >> 7, b = tid & 127;
            sl2s[tid] = a ? sl[0][b] : sl[1][b];
        }
        __syncthreads();
        {
            int v = sl2s[tid], r = 0;
            for (int j = 0; j < 256; j++) {
                int u = sl2s[j];
                if (u > v || (u == v && j < tid)) r++;
            }
            meta[M_PERM2 + r] = tid;
        }
        if (tid < 64) {
            int cnt = 0;
            for (int j = 0; j < 256; j++) cnt += (sl2s[j] > tid);
            meta[M_MCNT2 + tid] = cnt;
        }
        for (int c = 0; c < 2; c++) {
            int base = c ? M_ROWL1 : M_ROWL0;
            int myA = 0;
            for (int k = 0; k < 32; k++) {
                int row = tid * 32 + k;
                myA += ((row & 63) < sl[c][row >> 6]);
            }
            __syncthreads();
            cntA[tid] = myA;
            __syncthreads();
            if (tid == 0) {
                int s = 0;
                for (int i = 0; i < 256; i++) { int v = cntA[i]; cntA[i] = s; s += v; }
                totA = s;
                meta[M_NACT + c] = s;
            }
            __syncthreads();
            int pa = cntA[tid];
            int pd = totA + (tid * 32 - pa);
            for (int k = 0; k < 32; k++) {
                int row = tid * 32 + k;
                if ((row & 63) < sl[c][row >> 6]) meta[base + pa++] = row;
                else                              meta[base + pd++] = row;
            }
            __syncthreads();
        }
    }
    size_t total = 2ull * B_ * T_ * KPX;
    size_t stride = (size_t)gridDim.x * blockDim.x;
    for (size_t i = (size_t)blockIdx.x * blockDim.x + tid; i < total; i += stride) {
        int which = (int)(i / ((size_t)B_ * T_ * KPX));
        size_t rem = i % ((size_t)B_ * T_ * KPX);
        int bt = (int)(rem / KPX), k = (int)(rem % KPX);
        int tok = (which ? t2 : t1)[bt];
        e[i] = (k < D_) ? emb[(size_t)tok * D_ + k] : 0.f;
    }
}

// ---------------------------------------------------------------------------
// bulk GEMM engine (unchanged from R13)
// ---------------------------------------------------------------------------
struct MZ {
    const float*         A;
    const __nv_bfloat16* Bhi;
    const __nv_bfloat16* Blo;
    float*               C;
    const float*         bias;
    const int*           rows;
    const int*           nactp;
};
struct MP {
    MZ z[4];
    int Klen, lda, ldb, ldc;
};

__global__ void __launch_bounds__(256) mm_gemm(MP p) {
    extern __shared__ __align__(16) char smem_raw[];
    uint32_t sb = smem_u32(smem_raw);
    const MZ z = p.z[blockIdx.z];
    int tid = threadIdx.x, lane = tid & 31, wid = tid >> 5;
    int wg_n = wid & 3, wg_m = wid >> 2;
    int n0 = blockIdx.x * TN, m0 = blockIdx.y * TM;

    if (z.rows && m0 >= __ldg(z.nactp)) return;

    int tl = tid & 127;
    bool aAct = tid < 128;
    int arow = z.rows ? __ldg(z.rows + m0 + (tl >> 1)) : (m0 + (tl >> 1));
    const float* Ag = z.A + (size_t)arow * p.lda + (tl & 1) * 16;
    int brow = tid & 127, term = tid >> 7;
    const __nv_bfloat16* Bg = (term ? z.Blo : z.Bhi) + (size_t)(n0 + brow) * p.ldb;
    uint32_t aSt = (uint32_t)((tl >> 1) * PAD + (tl & 1) * 16) * 2;
    uint32_t bSt = (uint32_t)(brow * PAD) * 2;
    uint32_t aLd = (uint32_t)((lane & 15) * PAD + ((lane >> 4) << 3)) * 2;
    uint32_t bLd = (uint32_t)(((lane & 7) + ((lane & 16) >> 1)) * PAD + (lane & 8)) * 2;

    int nch = p.Klen / KC;
    float acc[2][4][4] = {};
    float fA[16];
    {
#pragma unroll
        for (int q = 0; q < 4; q++)
            CP_ASYNC16(sb + B_BASE(term, 0) + bSt + q * 16, Bg + q * 8);
        CP_COMMIT();
        if (aAct) {
            const float4* s4 = (const float4*)Ag;
#pragma unroll
            for (int q = 0; q < 4; q++) {
                float4 v = __ldcg(s4 + q);
                fA[4 * q] = v.x; fA[4 * q + 1] = v.y; fA[4 * q + 2] = v.z; fA[4 * q + 3] = v.w;
            }
            ushort hi[16], lo[16];
#pragma unroll
            for (int q = 0; q < 16; q++) {
                __nv_bfloat16 hb = __float2bfloat16_rn(fA[q]);
                __nv_bfloat16 lb = __float2bfloat16_rn(fA[q] - __bfloat162float(hb));
                hi[q] = *(ushort*)&hb; lo[q] = *(ushort*)&lb;
            }
            *(uint4*)(smem_raw + A_BASE(0, 0) + aSt)      = *(uint4*)(hi);
            *(uint4*)(smem_raw + A_BASE(0, 0) + aSt + 16) = *(uint4*)(hi + 8);
            *(uint4*)(smem_raw + A_BASE(1, 0) + aSt)      = *(uint4*)(lo);
            *(uint4*)(smem_raw + A_BASE(1, 0) + aSt + 16) = *(uint4*)(lo + 8);
        }
        CP_WAIT0();
        __syncthreads();
    }
    for (int ch = 0; ch < nch; ch++) {
        int s = ch & 1, ns = s ^ 1;
        bool more = (ch + 1) < nch;
        if (more) {
            const __nv_bfloat16* b2p = Bg + (ch + 1) * KC;
#pragma unroll
            for (int q = 0; q < 4; q++)
                CP_ASYNC16(sb + B_BASE(term, ns) + bSt + q * 16, b2p + q * 8);
            CP_COMMIT();
            if (aAct) {
                const float4* s4 = (const float4*)(Ag + (ch + 1) * KC);
#pragma unroll
                for (int q = 0; q < 4; q++) {
                    float4 v = __ldcg(s4 + q);
                    fA[4 * q] = v.x; fA[4 * q + 1] = v.y; fA[4 * q + 2] = v.z; fA[4 * q + 3] = v.w;
                }
            }
        }
#pragma unroll
        for (int h16 = 0; h16 < 2; h16++) {
            uint32_t kb = (uint32_t)h16 * 32;
            uint32_t bh[8], bl[8];
#pragma unroll
            for (int g2 = 0; g2 < 2; g2++) {
                uint32_t rowb = (uint32_t)((wg_n * 32 + g2 * 16) * PAD) * 2;
                LDSM4(bh[g2 * 4 + 0], bh[g2 * 4 + 1], bh[g2 * 4 + 2], bh[g2 * 4 + 3],
                      sb + B_BASE(0, s) + bLd + rowb + kb);
                LDSM4(bl[g2 * 4 + 0], bl[g2 * 4 + 1], bl[g2 * 4 + 2], bl[g2 * 4 + 3],
                      sb + B_BASE(1, s) + bLd + rowb + kb);
            }
#pragma unroll
            for (int k = 0; k < 2; k++) {
                int mt = 2 * wg_m + k;
                uint32_t ah[4], al[4];
                uint32_t rowa = (uint32_t)(mt * 16 * PAD) * 2;
                LDSM4(ah[0], ah[1], ah[2], ah[3], sb + A_BASE(0, s) + aLd + rowa + kb);
                LDSM4(al[0], al[1], al[2], al[3], sb + A_BASE(1, s) + aLd + rowa + kb);
#pragma unroll
                for (int nt = 0; nt < 4; nt++) {
                    int bi = (nt >> 1) * 4 + (nt & 1) * 2;
                    MMA16816(acc[k][nt], ah, bh[bi], bh[bi + 1]);
                    MMA16816(acc[k][nt], ah, bl[bi], bl[bi + 1]);
                    MMA16816(acc[k][nt], al, bh[bi], bh[bi + 1]);
                }
            }
        }
        if (more) {
            if (aAct) {
                ushort hi[16], lo[16];
#pragma unroll
                for (int q = 0; q < 16; q++) {
                    __nv_bfloat16 hb = __float2bfloat16_rn(fA[q]);
                    __nv_bfloat16 lb = __float2bfloat16_rn(fA[q] - __bfloat162float(hb));
                    hi[q] = *(ushort*)&hb; lo[q] = *(ushort*)&lb;
                }
                *(uint4*)(smem_raw + A_BASE(0, ns) + aSt)      = *(uint4*)(hi);
                *(uint4*)(smem_raw + A_BASE(0, ns) + aSt + 16) = *(uint4*)(hi + 8);
                *(uint4*)(smem_raw + A_BASE(1, ns) + aSt)      = *(uint4*)(lo);
                *(uint4*)(smem_raw + A_BASE(1, ns) + aSt + 16) = *(uint4*)(lo + 8);
            }
            CP_WAIT0();
        }
        __syncthreads();
    }

#pragma unroll
    for (int k = 0; k < 2; k++) {
        int mt = 2 * wg_m + k;
        int r = m0 + mt * 16 + (lane >> 2);
        int r0 = z.rows ? __ldg(z.rows + r) : r;
        int r1 = z.rows ? __ldg(z.rows + r + 8) : (r + 8);
#pragma unroll
        for (int nt = 0; nt < 4; nt++) {
            int c = n0 + wg_n * 32 + nt * 8 + (lane & 3) * 2;
            float b0 = 0.f, b1 = 0.f;
            if (z.bias) { b0 = z.bias[c]; b1 = z.bias[c + 1]; }
            *(float2*)(z.C + (size_t)r0 * p.ldc + c) =
                make_float2(acc[k][nt][0] + b0, acc[k][nt][1] + b1);
            *(float2*)(z.C + (size_t)r1 * p.ldc + c) =
                make_float2(acc[k][nt][2] + b0, acc[k][nt][3] + b1);
        }
    }
}

// ---------------------------------------------------------------------------
// Persistent LSTM scan (R13 + uniform early break)
// ---------------------------------------------------------------------------
__global__ void __launch_bounds__(512) k_lstm_persist() {
    extern __shared__ __align__(16) char smem[];
    uint32_t sb = smem_u32(smem);
    float* buf = d_buf;
    int* meta = (int*)(buf + OFF_META);
    int tid = threadIdx.x, lane = tid & 31, wid = tid >> 5;
    int wg_n = wid & 3, wg_m = wid >> 2;
    int blk = blockIdx.x;
    int r = blk >> 5, nt_ = blk & 31;
    int n0 = nt_ * 64;
    int widx = (r == 0 || r == 2) ? 0 : 1;
    int cls  = (r == 0 || r == 3) ? 0 : 1;
    const int* permc = meta + (cls ? M_PERM1 : M_PERM0);
    const int* slsrt = meta + (cls ? M_SLS1  : M_SLS0);
    const int* mcnt  = meta + (cls ? M_MCNT1 : M_MCNT0);

    {
        const __nv_bfloat16* WhS = (const __nv_bfloat16*)(buf + OFF_WHS);
        int tau = tid >> 8, rem = tid & 255;
        int n = rem >> 2, quar = rem & 3;
        const __nv_bfloat16* src = WhS + (size_t)(widx * 2 + tau) * G4_ * H_
                                   + (size_t)(n0 + n) * H_ + quar * 128;
        uint32_t dst = sb + (uint32_t)tau * 66560u + (uint32_t)n * 1040u + (uint32_t)quar * 256u;
#pragma unroll
        for (int q = 0; q < 16; q++) CP_ASYNC16(dst + q * 16, src + q * 8);
        CP_COMMIT(); CP_WAIT0(); __syncthreads();
    }

    const float* Xg  = buf + OFF_XG + (size_t)r * B_ * T_ * G4_;
    float*       cst = buf + OFF_C + (size_t)r * B_ * H_;
    float*       Yst = buf + OFF_Y + (size_t)r * B_ * T_ * H_;
    float*       hB  = buf + OFF_H;
    __nv_bfloat16* HBb = (__nv_bfloat16*)(buf + OFF_HB);
    unsigned* sync = (unsigned*)(meta + M_SYNC);
    const size_t HBUF = 4ull * B_ * H_;

    uint32_t aLd   = (uint32_t)((lane & 15) * 40 + ((lane >> 4) << 3)) * 2;
    uint32_t bBase = (uint32_t)(wg_n * 16) * 1040u
                   + (uint32_t)(((lane & 7) + ((lane & 16) >> 1)) * 520 + (lane & 8)) * 2;

    for (int t = 0; t < T_; t++) {
        int mc0 = __ldg(meta + M_MCNT0 + t);
        int mc1 = __ldg(meta + M_MCNT1 + t);
        if ((mc0 | mc1) == 0) break;     // uniform across all CTAs
        int mcur  = cls ? mc1 : mc0;
        int mtmax = (mcur + 15) >> 4;
        int mprev = (t >= 2) ? __ldg(mcnt + (t - 2)) : 128;
        int ppi = t & 1, ppo = ppi ^ 1;
        const float* hin  = hB + (size_t)ppi * HBUF + (size_t)r * B_ * H_;
        float*       hout = hB + (size_t)ppo * HBUF + (size_t)r * B_ * H_;
        const __nv_bfloat16* Ain = HBb + (size_t)ppi * 2 * P_HB + (size_t)r * B_ * H_;
        __nv_bfloat16*       ho  = HBb + (size_t)ppo * 2 * P_HB + (size_t)r * B_ * H_;

        float acc[2][2][4] = {};
        if (mtmax > 0) {
            int nrows = mtmax << 4;
            auto issueA = [&](int ch) {
                int slot = ch & 3;
                int tau = tid >> 8, rem = tid & 255;
                int row = rem >> 1, half = rem & 1;
                if (row < nrows) {
                    const __nv_bfloat16* src = Ain + (size_t)tau * P_HB + (size_t)row * H_
                                               + ch * 32 + half * 16;
                    uint32_t dst = sb + 133120u + (uint32_t)slot * 20480u
                                 + (uint32_t)tau * 10240u + (uint32_t)row * 80u + (uint32_t)half * 32u;
                    CP_ASYNC16(dst,      src);
                    CP_ASYNC16(dst + 16, src + 8);
                }
                CP_COMMIT();
            };
            issueA(0); issueA(1); issueA(2);
            for (int ch = 0; ch < 16; ch++) {
                if (ch <= 12) { CP_WAIT2(); }
                else if (ch == 13) { CP_WAIT1(); }
                else { CP_WAIT0(); }
                __syncthreads();
                if (ch + 3 < 16) issueA(ch + 3);
                uint32_t abase = sb + 133120u + (uint32_t)(ch & 3) * 20480u;
#pragma unroll
                for (int h16 = 0; h16 < 2; h16++) {
                    uint32_t kb = (uint32_t)(ch * 32 + h16 * 16) * 2;
                    uint32_t bA[4], bB[4];
                    LDSM4(bA[0], bA[1], bA[2], bA[3], sb + bBase + kb);
                    LDSM4(bB[0], bB[1], bB[2], bB[3], sb + 66560u + bBase + kb);
#pragma unroll
                    for (int k = 0; k < 2; k++) {
                        int mt = 4 * k + wg_m;
                        if (mt < mtmax) {
                            uint32_t ah[4], al[4];
                            uint32_t rowa = (uint32_t)(mt * 16 * 80);
                            LDSM4(ah[0], ah[1], ah[2], ah[3], abase + aLd + rowa + h16 * 32);
                            LDSM4(al[0], al[1], al[2], al[3], abase + 10240u + aLd + rowa + h16 * 32);
                            MMA16816(acc[k][0], ah, bA[0], bA[1]);
                            MMA16816(acc[k][0], ah, bB[0], bB[1]);
                            MMA16816(acc[k][0], al, bA[0], bA[1]);
                            MMA16816(acc[k][1], ah, bA[2], bA[3]);
                            MMA16816(acc[k][1], ah, bB[2], bB[3]);
                            MMA16816(acc[k][1], al, bA[2], bA[3]);
                        }
                    }
                }
            }
        }

#pragma unroll
        for (int k = 0; k < 2; k++) {
            int mt = 4 * k + wg_m;
            if (mt < mtmax) {
                int b = mt * 16 + (lane >> 2);
#pragma unroll
                for (int nt = 0; nt < 2; nt++) {
                    float fo0 = __shfl_xor_sync(0xffffffffu, acc[k][nt][0], 1);
                    float fo1 = __shfl_xor_sync(0xffffffffu, acc[k][nt][1], 1);
                    float fo2 = __shfl_xor_sync(0xffffffffu, acc[k][nt][2], 1);
                    float fo3 = __shfl_xor_sync(0xffffffffu, acc[k][nt][3], 1);
                    if (!(lane & 1)) {
#pragma unroll
                        for (int half = 0; half < 2; half++) {
                            int bb = b + half * 8;
                            float gi = half ? acc[k][nt][2] : acc[k][nt][0];
                            float gj = half ? acc[k][nt][3] : acc[k][nt][1];
                            float gf = half ? fo2 : fo0;
                            float go = half ? fo3 : fo1;
                            int c0 = n0 + wg_n * 16 + nt * 8 + (lane & 3) * 2;
                            int j = c0 >> 2;
                            size_t ci = (size_t)bb * H_ + j;
                            int slv = __ldg(slsrt + bb);
                            float hv;
                            if (t < slv) {
                                int ob = __ldg(permc + bb);
                                float4 x = *(const float4*)(Xg + ((size_t)ob * T_ + t) * G4_ + c0);
                                gi += x.x; gj += x.y; gf += x.z; go += x.w;
                                float cc = cst[ci];
                                float cn = cc * sigf(gf + 1.f) + sigf(gi) * ftanh(gj);
                                hv = ftanh(cn) * sigf(go);
                                cst[ci] = cn;
                                Yst[((size_t)ob * T_ + t) * H_ + j] = hv;
                            } else {
                                hv = __ldcg(hin + ci);
                            }
                            hout[ci] = hv;
                            split_store(hv, ho + ci, ho + P_HB + ci);
                        }
                    }
                }
            }
        }
        {
            int band = mprev - mcur;
            for (int idx = tid; idx < band * 16; idx += 512) {
                int rr = mcur + (idx >> 4);
                int jj = (n0 >> 2) + (idx & 15);
                size_t ci = (size_t)rr * H_ + jj;
                float hv = __ldcg(hin + ci);
                hout[ci] = hv;
                ho[ci]        = Ain[ci];
                ho[P_HB + ci] = Ain[P_HB + ci];
            }
        }
        gbar(sync + 0, sync + 1, (unsigned)(t + 1), 128u);
    }
}

// ---------------------------------------------------------------------------
// Persistent attention scan: phase A pair-parallel (warp halves, named bars).
// ---------------------------------------------------------------------------
__global__ void __launch_bounds__(512) k_att_persist(
    const float* __restrict__ wv,
    const int* __restrict__ s1, const int* __restrict__ s2) {
    extern __shared__ __align__(16) char smem[];
    uint32_t sb = smem_u32(smem);
    float* smf = (float*)(smem + 69632);
    float* buf = d_buf;
    int* meta = (int*)(buf + OFF_META);
    int tid = threadIdx.x, lane = tid & 31, wid = tid >> 5;
    int wg_n = wid & 3, wg_m = wid >> 2;
    int blk = blockIdx.x;

    int ks  = blk & 3;
    int mt_ = (blk >> 2) & 3;
    int nt_ = blk >> 4;
    int m0 = mt_ * 64, n0 = nt_ * 128, kst = ks * 128;

    {
        const __nv_bfloat16* WcS = (const __nv_bfloat16*)(buf + OFF_WCS);
        int tau = tid >> 8, rem = tid & 255;
        int row = rem >> 1, half = rem & 1;
        const __nv_bfloat16* src = WcS + (size_t)tau * 2 * H_ * H_
                                   + (size_t)(n0 + row) * H_ + kst + half * 64;
        uint32_t dst = sb + (uint32_t)tau * 34816u + (uint32_t)row * 272u + (uint32_t)half * 128u;
#pragma unroll
        for (int q = 0; q < 8; q++) CP_ASYNC16(dst + q * 16, src + q * 8);
        CP_COMMIT(); CP_WAIT0(); __syncthreads();
    }

    __nv_bfloat16* RBb = (__nv_bfloat16*)(buf + OFF_RB);
    float* uPt4 = buf + OFF_UPT;
    float* rL   = buf + OFF_RL;
    const float* WyY = buf + OFF_WYY;
    const float* HWy = buf + OFF_HWY;
    const float* Yb  = buf + OFF_Y;
    unsigned* sync = (unsigned*)(meta + M_SYNC);
    const int* mcnt2 = meta + M_MCNT2;

    uint32_t aLd = (uint32_t)((lane & 15) * 40 + ((lane >> 4) << 3)) * 2;
    uint32_t bLd = (uint32_t)(((lane & 7) + ((lane & 16) >> 1)) * 136 + (lane & 8)) * 2;

    float wvr[16];
#pragma unroll
    for (int k = 0; k < 16; k++) wvr[k] = __ldg(wv + lane + 32 * k);

    int spA = blk * 2, spB = blk * 2 + 1;
    int pA = meta[M_PERM2 + spA], pB = meta[M_PERM2 + spB];
    int aA = pA >> 7, bA = pA & 127;
    int aB = pB >> 7, bB = pB & 127;
    int sl2A = aA ? s1[bA] : s2[bA];
    int sl2B = aB ? s1[bB] : s2[bB];
    int slmA = aA ? s2[bA] : s1[bA];
    int slmB = aB ? s2[bB] : s1[bB];

    // per-thread half assignment for phase A
    int half = wid >> 3;          // warps 0-7: pair A, 8-15: pair B
    int hwid = wid & 7;
    int htid = tid & 255;
    int spH  = half ? spB : spA;
    int pH   = half ? pB : pA;
    int aH   = half ? aB : aA;
    int bH   = half ? bB : bA;
    int sl2H = half ? sl2B : sl2A;
    int slmH = half ? slmB : slmA;

    for (int t = 0; t < T_; t++) {
        int mcur2 = __ldg(mcnt2 + t);
        if (mcur2 == 0) break;        // uniform: no pair active at or after t
        int mtloc = 0;
        if (mcur2 > m0) { mtloc = (mcur2 - m0 + 15) >> 4; if (mtloc > 4) mtloc = 4; }

        if (mtloc > 0) {
            int nrows = mtloc << 4;
            auto issueA = [&](int ch) {
                int slot = ch & 3;
                int row = tid >> 1, tau = tid & 1;
                if (tid < 128 && row < nrows) {
                    const __nv_bfloat16* src = RBb + (size_t)tau * P_RB
                                               + (size_t)(m0 + row) * H_ + kst + ch * 32;
                    uint32_t dst = sb + 69632u + (uint32_t)slot * 10240u
                                 + (uint32_t)tau * 5120u + (uint32_t)row * 80u;
                    CP_ASYNC16(dst,      src);
                    CP_ASYNC16(dst + 16, src + 8);
                    CP_ASYNC16(dst + 32, src + 16);
                    CP_ASYNC16(dst + 48, src + 24);
                }
                CP_COMMIT();
            };
            issueA(0); issueA(1); issueA(2);
            float acc[4][4] = {};
            for (int ch = 0; ch < 4; ch++) {
                if (ch <= 1) { CP_WAIT2(); }
                else if (ch == 2) { CP_WAIT1(); }
                else { CP_WAIT0(); }
                __syncthreads();
                if (ch + 3 < 4) issueA(ch + 3);
                uint32_t abase = sb + 69632u + (uint32_t)(ch & 3) * 10240u;
#pragma unroll
                for (int h16 = 0; h16 < 2; h16++) {
                    uint32_t kb = (uint32_t)(ch * 32 + h16 * 16) * 2;
                    uint32_t bh[8], bl[8];
#pragma unroll
                    for (int g2 = 0; g2 < 2; g2++) {
                        uint32_t rowb = (uint32_t)((wg_n * 32 + g2 * 16) * 136) * 2;
                        LDSM4(bh[g2 * 4 + 0], bh[g2 * 4 + 1], bh[g2 * 4 + 2], bh[g2 * 4 + 3],
                              sb + bLd + rowb + kb);
                        LDSM4(bl[g2 * 4 + 0], bl[g2 * 4 + 1], bl[g2 * 4 + 2], bl[g2 * 4 + 3],
                              sb + 34816u + bLd + rowb + kb);
                    }
                    if (wg_m < mtloc) {
                        uint32_t ah[4], al[4];
                        uint32_t rowa = (uint32_t)(wg_m * 16 * 80);
                        LDSM4(ah[0], ah[1], ah[2], ah[3], abase + aLd + rowa + h16 * 32);
                        LDSM4(al[0], al[1], al[2], al[3], abase + 5120u + aLd + rowa + h16 * 32);
#pragma unroll
                        for (int nt = 0; nt < 4; nt++) {
                            int bi = (nt >> 1) * 4 + (nt & 1) * 2;
                            MMA16816(acc[nt], ah, bh[bi], bh[bi + 1]);
                            MMA16816(acc[nt], ah, bl[bi], bl[bi + 1]);
                            MMA16816(acc[nt], al, bh[bi], bh[bi + 1]);
                        }
                    }
                }
            }
            if (wg_m < mtloc) {
                float* Cb = uPt4 + (size_t)ks * 256 * 1024;
                int rr = m0 + wg_m * 16 + (lane >> 2);
#pragma unroll
                for (int nt = 0; nt < 4; nt++) {
                    int c = n0 + wg_n * 32 + nt * 8 + (lane & 3) * 2;
                    *(float2*)(Cb + (size_t)rr * 1024 + c) =
                        make_float2(acc[nt][0], acc[nt][1]);
                    *(float2*)(Cb + (size_t)(rr + 8) * 1024 + c) =
                        make_float2(acc[nt][2], acc[nt][3]);
                }
            }
        }
        gbar(sync + 2, sync + 3, (unsigned)(2 * t + 1), 128u);

        // ---- phase A: both pairs concurrently (warp halves, named barriers) ----
        if (t < sl2H) {
            float* su  = smf + half * 1088;
            float* spt = su + 512;
            float* sc  = su + 1024;
            const float* hb = HWy + (size_t)aH * B_ * T_ * H_ + ((size_t)bH * T_ + t) * H_;
#pragma unroll
            for (int q = 0; q < 2; q++) {
                int h = htid + q * 256;
                float s0 = 0.f, s1v = 0.f;
#pragma unroll
                for (int k = 0; k < 4; k++) {
                    const float* up = uPt4 + ((size_t)k * 256 + spH) * 1024;
                    s0  += __ldcg(up + h);
                    s1v += __ldcg(up + 512 + h);
                }
                su[h]  = s0 + __ldg(hb + h);
                spt[h] = s1v;
            }
            BARH(1 + half);
            const float* WyYb = WyY + (size_t)aH * B_ * T_ * H_ + (size_t)bH * T_ * H_;
#pragma unroll
            for (int q = 0; q < 8; q++) {
                int t2 = hwid * 8 + q;
                if (t2 < slmH) {
                    const float* row = WyYb + (size_t)t2 * H_;
                    float s = 0.f;
#pragma unroll
                    for (int k = 0; k < 16; k++) {
                        int hh = lane + 32 * k;
                        s += tanha(__ldg(row + hh) + su[hh]) * wvr[k];
                    }
                    for (int o = 16; o; o >>= 1) s += __shfl_xor_sync(0xffffffffu, s, o);
                    if (lane == 0) sc[t2] = s;
                } else if (lane == 0) {
                    sc[t2] = -10000.f;
                }
            }
            BARH(1 + half);
            if (hwid == 0) {
                float v1 = sc[lane], v2 = sc[lane + 32];
                float m = fmaxf(v1, v2);
                for (int o = 16; o; o >>= 1) m = fmaxf(m, __shfl_xor_sync(0xffffffffu, m, o));
                float e1 = __expf(v1 - m), e2 = __expf(v2 - m);
                float s = e1 + e2;
                for (int o = 16; o; o >>= 1) s += __shfl_xor_sync(0xffffffffu, s, o);
                float inv = __fdividef(1.f, s);
                sc[lane] = e1 * inv;
                sc[lane + 32] = e2 * inv;
            }
            BARH(1 + half);
            const float* Yp = Yb + (size_t)(aH ? 2 : 0) * B_ * T_ * H_ + (size_t)bH * T_ * H_;
#pragma unroll
            for (int q = 0; q < 2; q++) {
                int h = htid + q * 256;
                float a0 = 0.f, a1 = 0.f, a2 = 0.f, a3 = 0.f;
                int t2 = 0;
                for (; t2 + 4 <= slmH; t2 += 4) {
                    a0 += sc[t2 + 0] * __ldg(Yp + (size_t)(t2 + 0) * H_ + h);
                    a1 += sc[t2 + 1] * __ldg(Yp + (size_t)(t2 + 1) * H_ + h);
                    a2 += sc[t2 + 2] * __ldg(Yp + (size_t)(t2 + 2) * H_ + h);
                    a3 += sc[t2 + 3] * __ldg(Yp + (size_t)(t2 + 3) * H_ + h);
                }
                for (; t2 < slmH; t2++)
                    a0 += sc[t2] * __ldg(Yp + (size_t)t2 * H_ + h);
                float rn = (a0 + a1) + (a2 + a3) + ftanh(spt[h]);
                if (t == sl2H - 1) {
                    rL[(size_t)pH * H_ + h] = rn;
                } else {
                    split_store(rn, RBb + (size_t)spH * H_ + h, RBb + P_RB + (size_t)spH * H_ + h);
                }
            }
        }
        gbar(sync + 2, sync + 3, (unsigned)(2 * t + 2), 128u);
    }
}

// ---------------- final projection ----------------
__global__ void __launch_bounds__(512) k_final(
    const float* __restrict__ rL, const float* __restrict__ hfin,
    const float* __restrict__ Wp, const float* __restrict__ Wx,
    const float* __restrict__ U, const float* __restrict__ bU,
    float* __restrict__ out) {
    int b = blockIdx.x;
    int tid = threadIdx.x;
    const int* meta = (const int*)(d_buf + OFF_META);
    int ip1 = meta[M_IPOS1 + b];
    int ip0 = meta[M_IPOS0 + b];
    __shared__ float s_in[4][512];
    __shared__ float s_sum[512];
    __shared__ float red0[16], red1[16];
    s_in[0][tid] = rL[(size_t)b * H_ + tid];
    s_in[1][tid] = hfin[((size_t)1 * B_ + ip1) * H_ + tid];
    s_in[2][tid] = rL[((size_t)B_ + b) * H_ + tid];
    s_in[3][tid] = hfin[((size_t)3 * B_ + ip0) * H_ + tid];
    __syncthreads();
    float acc0 = 0.f, acc1 = 0.f;
    for (int k = 0; k < H_; k++) {
        float wp = Wp[(size_t)k * H_ + tid];
        float wx = Wx[(size_t)k * H_ + tid];
        acc0 += s_in[0][k] * wp + s_in[1][k] * wx;
        acc1 += s_in[2][k] * wp + s_in[3][k] * wx;
    }
    s_sum[tid] = ftanh(acc0) + ftanh(acc1);
    __syncthreads();
    float p0 = s_sum[tid] * U[(size_t)tid * 2 + 0];
    float p1 = s_sum[tid] * U[(size_t)tid * 2 + 1];
    for (int o = 16; o; o >>= 1) {
        p0 += __shfl_xor_sync(0xffffffffu, p0, o);
        p1 += __shfl_xor_sync(0xffffffffu, p1, o);
    }
    int wp_ = tid >> 5;
    if ((tid & 31) == 0) { red0[wp_] = p0; red1[wp_] = p1; }
    __syncthreads();
    if (tid < 16) {
        p0 = red0[tid]; p1 = red1[tid];
        for (int o = 8; o; o >>= 1) {
            p0 += __shfl_xor_sync(0x0000ffffu, p0, o);
            p1 += __shfl_xor_sync(0x0000ffffu, p1, o);
        }
        if (tid == 0) {
            out[b * 2 + 0] = p0 + bU[0];
            out[b * 2 + 1] = p1 + bU[1];
        }
    }
}

// ---------------- host ----------------
extern "C" void kernel_launch(void* const* d_in, const int* in_sizes, int n_in,
                              void* d_out, int out_size) {
    (void)in_sizes; (void)n_in; (void)out_size;
    const int*   tokens1 = (const int*)d_in[0];
    const int*   tokens2 = (const int*)d_in[1];
    const int*   seqlen1 = (const int*)d_in[2];
    const int*   seqlen2 = (const int*)d_in[3];
    const float* emb = (const float*)d_in[4];
    const float* W1  = (const float*)d_in[5];
    const float* b1  = (const float*)d_in[6];
    const float* W2  = (const float*)d_in[7];
    const float* b2  = (const float*)d_in[8];
    const float* Wy  = (const float*)d_in[9];
    const float* Wh  = (const float*)d_in[10];
    const float* Wr  = (const float*)d_in[11];
    const float* wv  = (const float*)d_in[12];
    const float* Wt  = (const float*)d_in[13];
    const float* Wp  = (const float*)d_in[14];
    const float* Wx  = (const float*)d_in[15];
    const float* U   = (const float*)d_in[16];
    const float* bU  = (const float*)d_in[17];
    float* out = (float*)d_out;

    cudaFuncSetAttribute(mm_gemm, cudaFuncAttributeMaxDynamicSharedMemorySize, SMEM_MM);
    cudaFuncSetAttribute(k_lstm_persist, cudaFuncAttributeMaxDynamicSharedMemorySize, SMEM_LSTM);
    cudaFuncSetAttribute(k_att_persist, cudaFuncAttributeMaxDynamicSharedMemorySize, SMEM_ATT);

    float* buf = nullptr;
    cudaGetSymbolAddress((void**)&buf, d_buf);
    float* e    = buf + OFF_E;
    float* Xg   = buf + OFF_XG;
    float* Yb   = buf + OFF_Y;
    float* hBuf = buf + OFF_H;
    float* WyY  = buf + OFF_WYY;
    float* HWy  = buf + OFF_HWY;
    float* rL   = buf + OFF_RL;
    float* bP   = buf + OFF_BP;
    int*   meta = (int*)(buf + OFF_META);
    __nv_bfloat16* WxS = (__nv_bfloat16*)(buf + OFF_WXS);
    __nv_bfloat16* WyS = (__nv_bfloat16*)(buf + OFF_WYS);
    __nv_bfloat16* WhA = (__nv_bfloat16*)(buf + OFF_WHA);

    k_prep<<<2048, 256>>>(W1, W2, Wy, Wh, Wr, Wt, b1, b2);
    k_gather<<<2048, 256>>>(e, tokens1, tokens2, emb, seqlen1, seqlen2);

    const int iidx[4] = {0, 1, 1, 0}, widx[4] = {0, 1, 0, 1};
    const int xcls[4] = {0, 1, 1, 0};

    // launch #3: X GEMM
    {
        MP p = {};
        for (int r = 0; r < 4; r++) {
            p.z[r].A     = e + (size_t)iidx[r] * B_ * T_ * KPX;
            p.z[r].Bhi   = WxS + (size_t)(widx[r] * 2 + 0) * G4_ * KPX;
            p.z[r].Blo   = WxS + (size_t)(widx[r] * 2 + 1) * G4_ * KPX;
            p.z[r].C     = Xg + (size_t)r * B_ * T_ * G4_;
            p.z[r].bias  = bP + (size_t)widx[r] * G4_;
            p.z[r].rows  = meta + (xcls[r] ? M_ROWL1 : M_ROWL0);
            p.z[r].nactp = meta + M_NACT + xcls[r];
        }
        p.Klen = KPX; p.lda = KPX; p.ldb = KPX; p.ldc = G4_;
        mm_gemm<<<dim3(G4_ / TN, (B_ * T_) / TM, 4), 256, SMEM_MM>>>(p);
    }

    // launch #4 (ncu target): persistent LSTM scan
    k_lstm_persist<<<128, 512, SMEM_LSTM>>>();

    // launch #5: WyY + HWy
    {
        MP p = {};
        const int runs[4] = {0, 2, 1, 3};
        const int qcls[4] = {0, 1, 1, 0};
        for (int q = 0; q < 4; q++) {
            p.z[q].A     = Yb + (size_t)runs[q] * B_ * T_ * H_;
            p.z[q].Bhi   = (q < 2 ? WyS : WhA);
            p.z[q].Blo   = (q < 2 ? WyS : WhA) + (size_t)H_ * H_;
            p.z[q].C     = (q < 2 ? WyY + (size_t)q * B_ * T_ * H_
                                  : HWy + (size_t)(q - 2) * B_ * T_ * H_);
            p.z[q].bias  = nullptr;
            p.z[q].rows  = meta + (qcls[q] ? M_ROWL1 : M_ROWL0);
            p.z[q].nactp = meta + M_NACT + qcls[q];
        }
        p.Klen = H_; p.lda = H_; p.ldb = H_; p.ldc = H_;
        mm_gemm<<<dim3(H_ / TN, (B_ * T_) / TM, 4), 256, SMEM_MM>>>(p);
    }

    // launch #6: persistent attention scan
    k_att_persist<<<128, 512, SMEM_ATT>>>(wv, seqlen1, seqlen2);

    // launch #7
    k_final<<<B_, 512>>>(rL, hBuf, Wp, Wx, U, bU, out);
}